// round 11
// baseline (speedup 1.0000x reference)
#include <cuda_runtime.h>
#include <cstdint>
#include <cstddef>

// Problem constants
#define BB   8
#define TT   1024
#define DD   512
#define EE   1024
#define NTAPE 64
#define CPB  16        // CTAs per cluster
#define RPC  32        // rows / tape-cols per CTA
#define NTHREADS 256
#define NCLU 8         // clusters (1 batch each)

// ---------------- device scratch ----------
__device__ float    g_xz[(size_t)BB * TT * EE];
__device__ float    g_rs[BB * CPB * NTAPE];         // fallback exchange
__device__ float    g_ws[BB * CPB * NTAPE];
__device__ float    g_hnew[BB * DD];
__device__ unsigned g_bar[BB];

__global__ void init_bar_kernel() {
    if (threadIdx.x < BB) g_bar[threadIdx.x] = 0u;
}

// ---------------- projection GEMM ----------
__global__ __launch_bounds__(256) void gemm_xz_kernel(
    const float* __restrict__ X, const float* __restrict__ W)
{
    __shared__ float As[16][68];
    __shared__ float Bs[16][68];
    const int m0 = blockIdx.y * 64;
    const int e0 = blockIdx.x * 64;
    const int tid = threadIdx.x;
    const int tx = tid & 15;
    const int ty = tid >> 4;
    const int lr = tid >> 2;
    const int lc = (tid & 3) * 4;
    float acc[4][4] = {};
    for (int kt = 0; kt < 512; kt += 16) {
        float4 xv = *(const float4*)(X + (size_t)(m0 + lr) * 512 + kt + lc);
        float4 wv = *(const float4*)(W + (size_t)(e0 + lr) * 512 + kt + lc);
        __syncthreads();
        As[lc + 0][lr] = xv.x; As[lc + 1][lr] = xv.y;
        As[lc + 2][lr] = xv.z; As[lc + 3][lr] = xv.w;
        Bs[lc + 0][lr] = wv.x; Bs[lc + 1][lr] = wv.y;
        Bs[lc + 2][lr] = wv.z; Bs[lc + 3][lr] = wv.w;
        __syncthreads();
#pragma unroll
        for (int kk = 0; kk < 16; kk++) {
            float4 a  = *(const float4*)&As[kk][ty * 4];
            float4 bv = *(const float4*)&Bs[kk][tx * 4];
            float av[4] = {a.x, a.y, a.z, a.w};
            float bw[4] = {bv.x, bv.y, bv.z, bv.w};
#pragma unroll
            for (int i = 0; i < 4; i++)
#pragma unroll
                for (int j = 0; j < 4; j++)
                    acc[i][j] += av[i] * bw[j];
        }
    }
#pragma unroll
    for (int i = 0; i < 4; i++) {
        float4 o = make_float4(acc[i][0], acc[i][1], acc[i][2], acc[i][3]);
        *(float4*)(&g_xz[(size_t)(m0 + ty * 4 + i) * EE + e0 + tx * 4]) = o;
    }
}

// ---------------- helpers ------------------------------------------
__device__ __forceinline__ uint32_t smem_u32(const void* p) {
    return (uint32_t)__cvta_generic_to_shared(p);
}
__device__ __forceinline__ uint32_t mapa_u32(uint32_t local_addr, uint32_t rank) {
    uint32_t r;
    asm volatile("mapa.shared::cluster.u32 %0, %1, %2;"
                 : "=r"(r) : "r"(local_addr), "r"(rank));
    return r;
}
#define CLUSTER_SYNC_() do {                                              \
    asm volatile("barrier.cluster.arrive.aligned;" ::: "memory");         \
    asm volatile("barrier.cluster.wait.aligned;"   ::: "memory");         \
} while (0)

__device__ __forceinline__ void push_async64(uint32_t raddr, float lo, float hi,
                                             uint32_t rmbar) {
    unsigned long long v =
        (unsigned long long)__float_as_uint(lo) |
        ((unsigned long long)__float_as_uint(hi) << 32);
    asm volatile(
        "st.async.shared::cluster.mbarrier::complete_tx::bytes.b64 [%0], %1, [%2];"
        :: "r"(raddr), "l"(v), "r"(rmbar) : "memory");
}
__device__ __forceinline__ void mbar_init(uint32_t mbar, uint32_t cnt) {
    asm volatile("mbarrier.init.shared.b64 [%0], %1;" :: "r"(mbar), "r"(cnt) : "memory");
}
__device__ __forceinline__ void mbar_expect_tx(uint32_t mbar, uint32_t bytes) {
    asm volatile("mbarrier.arrive.expect_tx.shared.b64 _, [%0], %1;"
                 :: "r"(mbar), "r"(bytes) : "memory");
}
__device__ __forceinline__ void mbar_wait_cta(uint32_t mbar, uint32_t parity) {
    asm volatile(
        "{\n\t"
        ".reg .pred P1;\n\t"
        "WAIT_LOOP_%=:\n\t"
        "mbarrier.try_wait.parity.acquire.cta.shared::cta.b64 P1, [%0], %1, 0x989680;\n\t"
        "@P1 bra.uni WAIT_DONE_%=;\n\t"
        "bra.uni WAIT_LOOP_%=;\n\t"
        "WAIT_DONE_%=:\n\t"
        "}"
        :: "r"(mbar), "r"(parity) : "memory");
}

__device__ __forceinline__ void fma2(unsigned long long& d,
                                     unsigned long long a,
                                     unsigned long long b) {
    asm("fma.rn.f32x2 %0, %1, %2, %0;" : "+l"(d) : "l"(a), "l"(b));
}
union UF2 { unsigned long long u; float2 f; };

__device__ __forceinline__ unsigned ld_acq_u32(const unsigned* p) {
    unsigned v;
    asm volatile("ld.global.acquire.gpu.u32 %0, [%1];" : "=r"(v) : "l"(p));
    return v;
}
__device__ __forceinline__ void batch_barrier(int b, unsigned target) {
    __syncthreads();
    if (threadIdx.x == 0) {
        __threadfence();
        atomicAdd(&g_bar[b], 1u);
        while (ld_acq_u32(&g_bar[b]) < target) { }
    }
    __syncthreads();
}

// (fallback-only) conflict-free smem matvec
__device__ __forceinline__ void matvec32(const float* __restrict__ sW,
                                         const float* __restrict__ vec,
                                         float* __restrict__ dest)
{
    const int lane = threadIdx.x & 31;
    const int warp = threadIdx.x >> 5;
    float4 v0 = *(const float4*)(vec + 0   + lane * 4);
    float4 v1 = *(const float4*)(vec + 128 + lane * 4);
    float4 v2 = *(const float4*)(vec + 256 + lane * 4);
    float4 v3 = *(const float4*)(vec + 384 + lane * 4);
#pragma unroll
    for (int rr = 0; rr < 4; rr++) {
        int r = warp * 4 + rr;
        const float* w = sW + r * 512;
        float4 w0 = *(const float4*)(w + 0   + lane * 4);
        float4 w1 = *(const float4*)(w + 128 + lane * 4);
        float4 w2 = *(const float4*)(w + 256 + lane * 4);
        float4 w3 = *(const float4*)(w + 384 + lane * 4);
        float s = w0.x * v0.x + w0.y * v0.y + w0.z * v0.z + w0.w * v0.w
                + w1.x * v1.x + w1.y * v1.y + w1.z * v1.z + w1.w * v1.w
                + w2.x * v2.x + w2.y * v2.y + w2.z * v2.z + w2.w * v2.w
                + w3.x * v3.x + w3.y * v3.y + w3.z * v3.z + w3.w * v3.w;
#pragma unroll
        for (int off = 16; off >= 1; off >>= 1)
            s += __shfl_down_sync(0xffffffffu, s, off);
        if (lane == 0) dest[r] = s;
    }
}

// owner-warp sum: inbox layout [cta][nl] (16x4); reduce 16, broadcast 4 scores
__device__ __forceinline__ void owner_reduce_bcast(
    const float* __restrict__ inbox, int lane, int c,
    const uint32_t* __restrict__ pbv, uint32_t off_dst, uint32_t off_mb)
{
    float s = inbox[lane] + inbox[lane + 32];
    s += __shfl_xor_sync(0xffffffffu, s, 4);
    s += __shfl_xor_sync(0xffffffffu, s, 8);
    s += __shfl_xor_sync(0xffffffffu, s, 16);
    float shi = __shfl_down_sync(0xffffffffu, s, 1);
    if (lane == 0 || lane == 2) {
        uint32_t doff = off_dst + (uint32_t)(c * 4 + lane) * 4;
#pragma unroll
        for (int r = 0; r < CPB; r++)
            push_async64(pbv[r] + doff, s, shi, pbv[r] + off_mb);
    }
}

// ---------------- single-batch cluster scan: owner-reduce, no S6 -----------
struct __align__(16) CS5 {
    float tape[NTAPE * 33];
    float hnew[512];              // doubles as h_work
    float rso[64];                // owner inbox [cta][nl]
    float rsf[64];                // finished read scores
    float wso[64];
    float wsf[64];
    float acc[RPC];
    float wv[RPC];
    float bh[RPC], gz[RPC], gr[RPC], gh[RPC], bg[RPC];
    unsigned long long mb_rso, mb_rsf, mb_hn, mb_wso, mb_wsf;
};

#define SOFF(f) ((uint32_t)offsetof(CS5, f))
#define RSO_BYTES 256
#define RSF_BYTES 256
#define WSO_BYTES 256
#define WSF_BYTES 256
#define HN_BYTES  (CPB * RPC * 4)   // 2048

__global__ __launch_bounds__(NTHREADS, 1) void scan5_kernel(
    const float* __restrict__ tape_init,
    const float* __restrict__ hwork_init,
    const float* __restrict__ W_h,
    const float* __restrict__ b_h,
    const float* __restrict__ W_write,
    const float* __restrict__ gzv,
    const float* __restrict__ grv,
    const float* __restrict__ ghv,
    const float* __restrict__ bgv,
    float* __restrict__ out)
{
    extern __shared__ char raw[];
    CS5& S = *(CS5*)raw;

    const int t    = threadIdx.x;
    const int lane = t & 31;
    const int cw   = t >> 5;
    const int u    = blockIdx.x >> 4;     // cluster = batch index
    const int c    = blockIdx.x & 15;     // cluster rank
    const int d0   = c * RPC;
    const float scale = 0.044194173824159216f;  // 1/sqrt(512)

    const bool isctrl      = (cw == 0);
    const bool is_rs_owner = (cw == 1);
    const bool is_ws_owner = (cw == 2);
    const int  rowbase     = cw * 8;      // D-phase rows (aligned with A reads)

    // ---- weights into registers ----
    unsigned long long wh[4][8], ww[4][8];
#pragma unroll
    for (int i = 0; i < 4; i++) {
        const size_t rowoff = (size_t)(d0 + cw * 4 + i) * 512;
#pragma unroll
        for (int ch = 0; ch < 4; ch++) {
            ulonglong2 a = *(const ulonglong2*)(W_h     + rowoff + ch * 128 + lane * 4);
            ulonglong2 b = *(const ulonglong2*)(W_write + rowoff + ch * 128 + lane * 4);
            wh[i][ch * 2] = a.x; wh[i][ch * 2 + 1] = a.y;
            ww[i][ch * 2] = b.x; ww[i][ch * 2 + 1] = b.y;
        }
    }

    // ---- one-time smem loads ----
    for (int i = t; i < NTAPE * RPC; i += NTHREADS) {
        int n = i >> 5, dl = i & 31;
        S.tape[n * 33 + dl] = tape_init[(size_t)(u * NTAPE + n) * DD + d0 + dl];
    }
    for (int i = t; i < 512; i += NTHREADS)
        S.hnew[i] = hwork_init[u * 512 + i];
    if (t < RPC) {
        S.bh[t] = b_h[d0 + t];  S.gz[t] = gzv[d0 + t];
        S.gr[t] = grv[d0 + t];  S.gh[t] = ghv[d0 + t];
        S.bg[t] = bgv[d0 + t];
    }

    const uint32_t sbase = smem_u32(&S);
    uint32_t pb[CPB];
#pragma unroll
    for (int r = 0; r < CPB; r++) pb[r] = mapa_u32(sbase, r);

    if (t == 0) {
        mbar_init(sbase + SOFF(mb_rso), 1);
        mbar_init(sbase + SOFF(mb_rsf), 1);
        mbar_init(sbase + SOFF(mb_hn),  1);
        mbar_init(sbase + SOFF(mb_wso), 1);
        mbar_init(sbase + SOFF(mb_wsf), 1);
        mbar_expect_tx(sbase + SOFF(mb_rso), RSO_BYTES);
        mbar_expect_tx(sbase + SOFF(mb_rsf), RSF_BYTES);
        mbar_expect_tx(sbase + SOFF(mb_hn),  HN_BYTES);
        mbar_expect_tx(sbase + SOFF(mb_wso), WSO_BYTES);
        mbar_expect_tx(sbase + SOFF(mb_wsf), WSF_BYTES);
    }
    __syncthreads();

    // ---- pre-loop: acc = Wh @ h_init ----
    {
        unsigned long long v[8];
#pragma unroll
        for (int ch = 0; ch < 4; ch++) {
            ulonglong2 tv = *(const ulonglong2*)(&S.hnew[ch * 128 + lane * 4]);
            v[ch * 2] = tv.x; v[ch * 2 + 1] = tv.y;
        }
        unsigned long long a2[4] = {0ull, 0ull, 0ull, 0ull};
#pragma unroll
        for (int i = 0; i < 4; i++)
#pragma unroll
            for (int p = 0; p < 8; p++) fma2(a2[i], wh[i][p], v[p]);
        float sa[4];
#pragma unroll
        for (int i = 0; i < 4; i++) { UF2 x; x.u = a2[i]; sa[i] = x.f.x + x.f.y; }
#pragma unroll
        for (int off = 16; off >= 1; off >>= 1) {
#pragma unroll
            for (int i = 0; i < 4; i++)
                sa[i] += __shfl_xor_sync(0xffffffffu, sa[i], off);
        }
        if (lane == 0)
            *(float4*)&S.acc[cw * 4] = make_float4(sa[0], sa[1], sa[2], sa[3]);
    }
    __syncthreads();
    CLUSTER_SYNC_();

    const int n4 = t >> 2, q4 = t & 3;

    // ---- xz prefetch (ctrl warp, step 0) ----
    float xp = 0.f, zt = 0.f;
    if (isctrl) {
        size_t row = (size_t)(u * TT) * EE;
        xp = __ldcs(&g_xz[row + d0 + lane]);
        zt = __ldcs(&g_xz[row + 512 + d0 + lane]);
    }

    for (int step = 0; step < TT; step++) {
        const uint32_t par = step & 1u;

        // ---- Phase A: read-score partial for row n4 -> push pair to OWNER ----
        {
            float s = 0.f;
#pragma unroll
            for (int k = 0; k < 8; k++) {
                int dl = q4 * 8 + k;
                s += S.hnew[d0 + dl] * S.tape[n4 * 33 + dl];
            }
            s += __shfl_down_sync(0xffffffffu, s, 2);
            s += __shfl_down_sync(0xffffffffu, s, 1);
            float shi = __shfl_down_sync(0xffffffffu, s, 4);   // row n4+1
            if ((t & 7) == 0) {
                int o  = n4 >> 2;
                int nl = n4 & 3;
                uint32_t doff = SOFF(rso) + (uint32_t)(c * 4 + nl) * 4;
                push_async64(pb[o] + doff, s, shi, pb[o] + SOFF(mb_rso));
            }
        }

        // ---- rs OWNER (warp 1): reduce 16 partials, broadcast scores ----
        if (is_rs_owner) {
            mbar_wait_cta(sbase + SOFF(mb_rso), par);
            if (lane == 0) mbar_expect_tx(sbase + SOFF(mb_rso), RSO_BYTES);
            owner_reduce_bcast(S.rso, lane, c, pb, SOFF(rsf), SOFF(mb_rsf));
        }

        // ---- Phase B (ctrl warp): wait scores, softmax, read_val, h ----
        if (isctrl) {
            mbar_wait_cta(sbase + SOFF(mb_rsf), par);
            if (lane == 0) mbar_expect_tx(sbase + SOFF(mb_rsf), RSF_BYTES);
            float a0 = S.rsf[lane] * scale;
            float a1 = S.rsf[lane + 32] * scale;
            float m = fmaxf(a0, a1);
#pragma unroll
            for (int off = 16; off >= 1; off >>= 1)
                m = fmaxf(m, __shfl_xor_sync(0xffffffffu, m, off));
            float e0 = __expf(a0 - m), e1 = __expf(a1 - m);
            float ss = e0 + e1;
#pragma unroll
            for (int off = 16; off >= 1; off >>= 1)
                ss += __shfl_xor_sync(0xffffffffu, ss, off);
            float inv = 1.f / ss;
            e0 *= inv; e1 *= inv;
            float rv0 = 0.f, rv1 = 0.f, rv2 = 0.f, rv3 = 0.f;
#pragma unroll
            for (int k = 0; k < 8; k++) {
                rv0 += __shfl_sync(0xffffffffu, e0, 4 * k + 0) * S.tape[(4 * k + 0) * 33 + lane];
                rv1 += __shfl_sync(0xffffffffu, e0, 4 * k + 1) * S.tape[(4 * k + 1) * 33 + lane];
                rv2 += __shfl_sync(0xffffffffu, e0, 4 * k + 2) * S.tape[(4 * k + 2) * 33 + lane];
                rv3 += __shfl_sync(0xffffffffu, e0, 4 * k + 3) * S.tape[(4 * k + 3) * 33 + lane];
            }
#pragma unroll
            for (int k = 0; k < 8; k++) {
                rv0 += __shfl_sync(0xffffffffu, e1, 4 * k + 0) * S.tape[(32 + 4 * k + 0) * 33 + lane];
                rv1 += __shfl_sync(0xffffffffu, e1, 4 * k + 1) * S.tape[(32 + 4 * k + 1) * 33 + lane];
                rv2 += __shfl_sync(0xffffffffu, e1, 4 * k + 2) * S.tape[(32 + 4 * k + 2) * 33 + lane];
                rv3 += __shfl_sync(0xffffffffu, e1, 4 * k + 3) * S.tape[(32 + 4 * k + 3) * 33 + lane];
            }
            float rv = (rv0 + rv1) + (rv2 + rv3);
            float pre = xp + S.acc[lane] + rv + S.bh[lane];
            float ex2 = __expf(2.f * pre);
            float hn  = 1.f - 2.f / (ex2 + 1.f);
            float hnhi = __shfl_down_sync(0xffffffffu, hn, 1);
            if ((lane & 1) == 0) {
                uint32_t doff = SOFF(hnew) + (uint32_t)(d0 + lane) * 4;
#pragma unroll
                for (int r = 0; r < CPB; r++)
                    push_async64(pb[r] + doff, hn, hnhi, pb[r] + SOFF(mb_hn));
            }
            float gi = zt * S.gz[lane] + rv * S.gr[lane] + hn * S.gh[lane] + S.bg[lane];
            gi = fminf(fmaxf(gi, -20.f), 20.f);
            float sig = 1.f / (1.f + __expf(-gi));
            out[(size_t)(u * TT + step) * DD + d0 + lane] = hn * gi * sig;
            int sn = (step + 1 < TT) ? step + 1 : step;
            size_t nrow = (size_t)(u * TT + sn) * EE;
            xp = __ldcs(&g_xz[nrow + d0 + lane]);
            zt = __ldcs(&g_xz[nrow + 512 + d0 + lane]);
        }

        // ---- Phase C: wait h, dual register matvec ----
        mbar_wait_cta(sbase + SOFF(mb_hn), par);
        if (t == 0) mbar_expect_tx(sbase + SOFF(mb_hn), HN_BYTES);
        {
            unsigned long long v[8];
#pragma unroll
            for (int ch = 0; ch < 4; ch++) {
                ulonglong2 tv = *(const ulonglong2*)(&S.hnew[ch * 128 + lane * 4]);
                v[ch * 2] = tv.x; v[ch * 2 + 1] = tv.y;
            }
            unsigned long long a2[4] = {0ull, 0ull, 0ull, 0ull};
            unsigned long long b2[4] = {0ull, 0ull, 0ull, 0ull};
#pragma unroll
            for (int i = 0; i < 4; i++)
#pragma unroll
                for (int p = 0; p < 8; p++) {
                    fma2(a2[i], wh[i][p], v[p]);
                    fma2(b2[i], ww[i][p], v[p]);
                }
            float sa[4], sb[4];
#pragma unroll
            for (int i = 0; i < 4; i++) {
                UF2 x; x.u = a2[i]; sa[i] = x.f.x + x.f.y;
                UF2 y; y.u = b2[i]; sb[i] = y.f.x + y.f.y;
            }
#pragma unroll
            for (int off = 16; off >= 1; off >>= 1) {
#pragma unroll
                for (int i = 0; i < 4; i++) {
                    sa[i] += __shfl_xor_sync(0xffffffffu, sa[i], off);
                    sb[i] += __shfl_xor_sync(0xffffffffu, sb[i], off);
                }
            }
            if (lane == 0) {
                *(float4*)&S.acc[cw * 4] = make_float4(sa[0], sa[1], sa[2], sa[3]);
                *(float4*)&S.wv[cw * 4]  = make_float4(sb[0], sb[1], sb[2], sb[3]);
            }
        }
        __syncthreads();   // S3: acc/wv exchange (only block barrier left)

        // ---- write-score partial -> push pair to OWNER ----
        {
            float s = 0.f;
#pragma unroll
            for (int k = 0; k < 8; k++) {
                int dl = q4 * 8 + k;
                s += S.wv[dl] * S.tape[n4 * 33 + dl];
            }
            s += __shfl_down_sync(0xffffffffu, s, 2);
            s += __shfl_down_sync(0xffffffffu, s, 1);
            float shi = __shfl_down_sync(0xffffffffu, s, 4);
            if ((t & 7) == 0) {
                int o  = n4 >> 2;
                int nl = n4 & 3;
                uint32_t doff = SOFF(wso) + (uint32_t)(c * 4 + nl) * 4;
                push_async64(pb[o] + doff, s, shi, pb[o] + SOFF(mb_wso));
            }
        }

        // ---- ws OWNER (warp 2): reduce, broadcast ----
        if (is_ws_owner) {
            mbar_wait_cta(sbase + SOFF(mb_wso), par);
            if (lane == 0) mbar_expect_tx(sbase + SOFF(mb_wso), WSO_BYTES);
            owner_reduce_bcast(S.wso, lane, c, pb, SOFF(wsf), SOFF(mb_wsf));
        }

        // ---- Phase D: per-warp softmax + OWN-row tape update (no S6) ----
        {
            mbar_wait_cta(sbase + SOFF(mb_wsf), par);
            if (t == 0) mbar_expect_tx(sbase + SOFF(mb_wsf), WSF_BYTES);
            float a0 = S.wsf[lane] * scale;
            float a1 = S.wsf[lane + 32] * scale;
            float m = fmaxf(a0, a1);
#pragma unroll
            for (int off = 16; off >= 1; off >>= 1)
                m = fmaxf(m, __shfl_xor_sync(0xffffffffu, m, off));
            float e0 = __expf(a0 - m), e1 = __expf(a1 - m);
            float ss = e0 + e1;
#pragma unroll
            for (int off = 16; off >= 1; off >>= 1)
                ss += __shfl_xor_sync(0xffffffffu, ss, off);
            float inv = 1.f / ss;
            float eh = (cw < 4) ? e0 * inv : e1 * inv;   // rows rowbase..+8
            float wvl = S.wv[lane];
#pragma unroll
            for (int r = 0; r < 8; r++) {
                int n = rowbase + r;
                float a = __shfl_sync(0xffffffffu, eh, n & 31);
                float tp = S.tape[n * 33 + lane];
                S.tape[n * 33 + lane] = tp - tp * a + wvl * a;
            }
        }
        // No S6: next-step A reads only this warp's rows (program order);
        // all cross-warp consumers are ordered by the rso->rsf->hn chain.
    }

    // ---- final tape output: each warp stores its own rows ----
#pragma unroll
    for (int r = 0; r < 8; r++) {
        int n = rowbase + r;
        out[(size_t)BB * TT * DD + (size_t)(u * NTAPE + n) * DD + d0 + lane] =
            S.tape[n * 33 + lane];
    }
    CLUSTER_SYNC_();
}

// ---------------- fallback scan kernel (global-memory barriers) -----------
struct ScanSmem {
    float Wh[RPC * 512];
    float Ww[RPC * 512];
    float tape[NTAPE * 33];
    float hwork[512];
    float hnew[512];
    float acc[RPC];
    float wv[RPC];
    float rv[RPC];
    float attn[NTAPE];
    float score[NTAPE];
    float bh[RPC], gz[RPC], gr[RPC], gh[RPC], bg[RPC];
};

__device__ __forceinline__ void softmax64f(const float* __restrict__ score,
                                           float* __restrict__ attn, int t)
{
    if (t < 32) {
        float a = score[t], b = score[t + 32];
        float m = fmaxf(a, b);
#pragma unroll
        for (int off = 16; off >= 1; off >>= 1)
            m = fmaxf(m, __shfl_xor_sync(0xffffffffu, m, off));
        float e0 = __expf(a - m), e1 = __expf(b - m);
        float ss = e0 + e1;
#pragma unroll
        for (int off = 16; off >= 1; off >>= 1)
            ss += __shfl_xor_sync(0xffffffffu, ss, off);
        float inv = 1.f / ss;
        attn[t] = e0 * inv;
        attn[t + 32] = e1 * inv;
    }
}

__global__ __launch_bounds__(NTHREADS, 1) void scan_kernel(
    const float* __restrict__ tape_init,
    const float* __restrict__ hwork_init,
    const float* __restrict__ W_h,
    const float* __restrict__ b_h,
    const float* __restrict__ W_write,
    const float* __restrict__ gzv,
    const float* __restrict__ grv,
    const float* __restrict__ ghv,
    const float* __restrict__ bgv,
    float* __restrict__ out)
{
    extern __shared__ char raw[];
    ScanSmem& S = *(ScanSmem*)raw;

    const int t  = threadIdx.x;
    const int b  = blockIdx.x / CPB;
    const int c  = blockIdx.x % CPB;
    const int d0 = c * RPC;
    const float scale = 0.044194173824159216f;

    for (int i = t; i < RPC * 512; i += NTHREADS) {
        S.Wh[i] = W_h[(size_t)d0 * 512 + i];
        S.Ww[i] = W_write[(size_t)d0 * 512 + i];
    }
    for (int i = t; i < NTAPE * RPC; i += NTHREADS) {
        int n = i >> 5, dl = i & 31;
        S.tape[n * 33 + dl] = tape_init[(size_t)(b * NTAPE + n) * DD + d0 + dl];
    }
    for (int i = t; i < 512; i += NTHREADS)
        S.hwork[i] = hwork_init[b * 512 + i];
    if (t < RPC) {
        S.bh[t] = b_h[d0 + t];  S.gz[t] = gzv[d0 + t];
        S.gr[t] = grv[d0 + t];  S.gh[t] = ghv[d0 + t];
        S.bg[t] = bgv[d0 + t];
    }
    __syncthreads();

    unsigned bc = 0;
    const int n4 = t >> 2, q4 = t & 3;
    const int dl8 = t >> 3, q8 = t & 7;

    for (int step = 0; step < TT; step++) {
        {
            float s = 0.f;
#pragma unroll
            for (int k = 0; k < 8; k++) {
                int dl = q4 * 8 + k;
                s += S.hwork[d0 + dl] * S.tape[n4 * 33 + dl];
            }
            s += __shfl_down_sync(0xffffffffu, s, 2);
            s += __shfl_down_sync(0xffffffffu, s, 1);
            if (q4 == 0) g_rs[(b * CPB + c) * NTAPE + n4] = s;
        }
        matvec32(S.Wh, S.hwork, S.acc);
        batch_barrier(b, (++bc) * CPB);

        if (t < NTAPE) {
            float s = 0.f;
#pragma unroll
            for (int cc = 0; cc < CPB; cc++)
                s += __ldcg(&g_rs[(b * CPB + cc) * NTAPE + t]);
            S.score[t] = s * scale;
        }
        __syncthreads();
        softmax64f(S.score, S.attn, t);
        __syncthreads();
        {
            float s = 0.f;
#pragma unroll
            for (int k = 0; k < 8; k++) {
                int n = q8 * 8 + k;
                s += S.attn[n] * S.tape[n * 33 + dl8];
            }
            s += __shfl_down_sync(0xffffffffu, s, 4);
            s += __shfl_down_sync(0xffffffffu, s, 2);
            s += __shfl_down_sync(0xffffffffu, s, 1);
            if (q8 == 0) S.rv[dl8] = s;
        }
        __syncthreads();
        if (t < RPC) {
            size_t row = (size_t)(b * TT + step) * EE;
            float xp = g_xz[row + d0 + t];
            float zt = g_xz[row + 512 + d0 + t];
            float hn = tanhf(xp + S.acc[t] + S.rv[t] + S.bh[t]);
            g_hnew[b * 512 + d0 + t] = hn;
            float gi = zt * S.gz[t] + S.rv[t] * S.gr[t] + hn * S.gh[t] + S.bg[t];
            gi = fminf(fmaxf(gi, -20.f), 20.f);
            float sig = 1.f / (1.f + __expf(-gi));
            out[(size_t)(b * TT + step) * DD + d0 + t] = hn * gi * sig;
        }
        batch_barrier(b, (++bc) * CPB);

        S.hnew[t]       = __ldcg(&g_hnew[b * 512 + t]);
        S.hnew[t + 256] = __ldcg(&g_hnew[b * 512 + t + 256]);
        __syncthreads();
        matvec32(S.Ww, S.hnew, S.wv);
        __syncthreads();
        {
            float s = 0.f;
#pragma unroll
            for (int k = 0; k < 8; k++) {
                int dl = q4 * 8 + k;
                s += S.wv[dl] * S.tape[n4 * 33 + dl];
            }
            s += __shfl_down_sync(0xffffffffu, s, 2);
            s += __shfl_down_sync(0xffffffffu, s, 1);
            if (q4 == 0) g_ws[(b * CPB + c) * NTAPE + n4] = s;
        }
        batch_barrier(b, (++bc) * CPB);

        if (t < NTAPE) {
            float s = 0.f;
#pragma unroll
            for (int cc = 0; cc < CPB; cc++)
                s += __ldcg(&g_ws[(b * CPB + cc) * NTAPE + t]);
            S.score[t] = s * scale;
        }
        __syncthreads();
        softmax64f(S.score, S.attn, t);
        __syncthreads();
        for (int e = t; e < NTAPE * RPC; e += NTHREADS) {
            int n = e >> 5, dl = e & 31;
            float a  = S.attn[n];
            float tp = S.tape[n * 33 + dl];
            S.tape[n * 33 + dl] = tp - tp * a + S.wv[dl] * a;
        }
        S.hwork[t]       = S.hnew[t];
        S.hwork[t + 256] = S.hnew[t + 256];
        __syncthreads();
    }

    for (int e = t; e < NTAPE * RPC; e += NTHREADS) {
        int n = e >> 5, dl = e & 31;
        out[(size_t)BB * TT * DD + (size_t)(b * NTAPE + n) * DD + d0 + dl] =
            S.tape[n * 33 + dl];
    }
}

// ---------------- launch ---------------------------------------------------
extern "C" void kernel_launch(void* const* d_in, const int* in_sizes, int n_in,
                              void* d_out, int out_size)
{
    const float* x         = (const float*)d_in[0];
    const float* tape_init = (const float*)d_in[1];
    const float* hwork     = (const float*)d_in[2];
    const float* W_h       = (const float*)d_in[3];
    const float* W_xz      = (const float*)d_in[4];
    const float* b_h       = (const float*)d_in[5];
    const float* W_write   = (const float*)d_in[6];
    const float* g_z       = (const float*)d_in[7];
    const float* g_r       = (const float*)d_in[8];
    const float* g_h       = (const float*)d_in[9];
    const float* b_gate    = (const float*)d_in[10];
    float* out = (float*)d_out;

    gemm_xz_kernel<<<dim3(EE / 64, (BB * TT) / 64), 256>>>(x, W_xz);

    // ---- primary: single-batch owner-reduce cluster scan ----
    cudaFuncSetAttribute(scan5_kernel,
                         cudaFuncAttributeMaxDynamicSharedMemorySize,
                         (int)sizeof(CS5));
    cudaError_t aerr = cudaFuncSetAttribute(
        scan5_kernel, cudaFuncAttributeNonPortableClusterSizeAllowed, 1);

    cudaLaunchConfig_t cfg = {};
    cfg.gridDim  = dim3(NCLU * CPB, 1, 1);
    cfg.blockDim = dim3(NTHREADS, 1, 1);
    cfg.dynamicSmemBytes = sizeof(CS5);
    cfg.stream = 0;

    int maxClu = 0;
    cudaError_t qerr = cudaOccupancyMaxPotentialClusterSize(
        &maxClu, scan5_kernel, &cfg);

    bool launched = false;
    if (aerr == cudaSuccess && qerr == cudaSuccess && maxClu >= CPB) {
        cudaLaunchAttribute attrs[1];
        attrs[0].id = cudaLaunchAttributeClusterDimension;
        attrs[0].val.clusterDim.x = CPB;
        attrs[0].val.clusterDim.y = 1;
        attrs[0].val.clusterDim.z = 1;
        cfg.attrs = attrs;
        cfg.numAttrs = 1;
        cudaError_t lerr = cudaLaunchKernelEx(&cfg, scan5_kernel,
            tape_init, hwork, W_h, b_h, W_write, g_z, g_r, g_h, b_gate, out);
        launched = (lerr == cudaSuccess);
    }

    // ---- fallback ----
    if (!launched) {
        cudaFuncSetAttribute(scan_kernel,
                             cudaFuncAttributeMaxDynamicSharedMemorySize,
                             (int)sizeof(ScanSmem));
        init_bar_kernel<<<1, 32>>>();
        scan_kernel<<<BB * CPB, NTHREADS, sizeof(ScanSmem)>>>(
            tape_init, hwork, W_h, b_h, W_write, g_z, g_r, g_h, b_gate, out);
    }
}

// round 12
// speedup vs baseline: 1.4652x; 1.4652x over previous
#include <cuda_runtime.h>
#include <cstdint>
#include <cstddef>

// Problem constants
#define BB   8
#define TT   1024
#define DD   512
#define EE   1024
#define NTAPE 64
#define CPB  16        // CTAs per cluster
#define RPC  32        // rows / tape-cols per CTA
#define NTHREADS 256
#define NCLU  4        // clusters (2 batches each)

// ---------------- device scratch ----------
__device__ float    g_xz[(size_t)BB * TT * EE];
__device__ float    g_rs[BB * CPB * NTAPE];         // fallback exchange
__device__ float    g_ws[BB * CPB * NTAPE];
__device__ float    g_hnew[BB * DD];
__device__ unsigned g_bar[BB];

__global__ void init_bar_kernel() {
    if (threadIdx.x < BB) g_bar[threadIdx.x] = 0u;
}

// ---------------- projection GEMM (double-buffered) ----------
__global__ __launch_bounds__(256) void gemm_xz_kernel(
    const float* __restrict__ X, const float* __restrict__ W)
{
    __shared__ float As[2][16][68];
    __shared__ float Bs[2][16][68];
    const int m0 = blockIdx.y * 64;
    const int e0 = blockIdx.x * 64;
    const int tid = threadIdx.x;
    const int tx = tid & 15;
    const int ty = tid >> 4;
    const int lr = tid >> 2;
    const int lc = (tid & 3) * 4;
    float acc[4][4] = {};

    // prime buffer 0
    float4 xv = *(const float4*)(X + (size_t)(m0 + lr) * 512 + lc);
    float4 wv = *(const float4*)(W + (size_t)(e0 + lr) * 512 + lc);
    As[0][lc + 0][lr] = xv.x; As[0][lc + 1][lr] = xv.y;
    As[0][lc + 2][lr] = xv.z; As[0][lc + 3][lr] = xv.w;
    Bs[0][lc + 0][lr] = wv.x; Bs[0][lc + 1][lr] = wv.y;
    Bs[0][lc + 2][lr] = wv.z; Bs[0][lc + 3][lr] = wv.w;
    __syncthreads();

    for (int kt = 0; kt < 32; kt++) {
        const int cur = kt & 1;
        if (kt + 1 < 32) {   // prefetch next chunk into registers
            xv = *(const float4*)(X + (size_t)(m0 + lr) * 512 + (kt + 1) * 16 + lc);
            wv = *(const float4*)(W + (size_t)(e0 + lr) * 512 + (kt + 1) * 16 + lc);
        }
#pragma unroll
        for (int kk = 0; kk < 16; kk++) {
            float4 a  = *(const float4*)&As[cur][kk][ty * 4];
            float4 bv = *(const float4*)&Bs[cur][kk][tx * 4];
            float av[4] = {a.x, a.y, a.z, a.w};
            float bw[4] = {bv.x, bv.y, bv.z, bv.w};
#pragma unroll
            for (int i = 0; i < 4; i++)
#pragma unroll
                for (int j = 0; j < 4; j++)
                    acc[i][j] += av[i] * bw[j];
        }
        if (kt + 1 < 32) {
            const int nxt = cur ^ 1;
            As[nxt][lc + 0][lr] = xv.x; As[nxt][lc + 1][lr] = xv.y;
            As[nxt][lc + 2][lr] = xv.z; As[nxt][lc + 3][lr] = xv.w;
            Bs[nxt][lc + 0][lr] = wv.x; Bs[nxt][lc + 1][lr] = wv.y;
            Bs[nxt][lc + 2][lr] = wv.z; Bs[nxt][lc + 3][lr] = wv.w;
            __syncthreads();
        }
    }
#pragma unroll
    for (int i = 0; i < 4; i++) {
        float4 o = make_float4(acc[i][0], acc[i][1], acc[i][2], acc[i][3]);
        *(float4*)(&g_xz[(size_t)(m0 + ty * 4 + i) * EE + e0 + tx * 4]) = o;
    }
}

// ---------------- helpers ------------------------------------------
__device__ __forceinline__ uint32_t smem_u32(const void* p) {
    return (uint32_t)__cvta_generic_to_shared(p);
}
__device__ __forceinline__ uint32_t mapa_u32(uint32_t local_addr, uint32_t rank) {
    uint32_t r;
    asm volatile("mapa.shared::cluster.u32 %0, %1, %2;"
                 : "=r"(r) : "r"(local_addr), "r"(rank));
    return r;
}
#define CLUSTER_SYNC_() do {                                              \
    asm volatile("barrier.cluster.arrive.aligned;" ::: "memory");         \
    asm volatile("barrier.cluster.wait.aligned;"   ::: "memory");         \
} while (0)

__device__ __forceinline__ void push_async64(uint32_t raddr, float lo, float hi,
                                             uint32_t rmbar) {
    unsigned long long v =
        (unsigned long long)__float_as_uint(lo) |
        ((unsigned long long)__float_as_uint(hi) << 32);
    asm volatile(
        "st.async.shared::cluster.mbarrier::complete_tx::bytes.b64 [%0], %1, [%2];"
        :: "r"(raddr), "l"(v), "r"(rmbar) : "memory");
}
__device__ __forceinline__ void mbar_init(uint32_t mbar, uint32_t cnt) {
    asm volatile("mbarrier.init.shared.b64 [%0], %1;" :: "r"(mbar), "r"(cnt) : "memory");
}
__device__ __forceinline__ void mbar_expect_tx(uint32_t mbar, uint32_t bytes) {
    asm volatile("mbarrier.arrive.expect_tx.shared.b64 _, [%0], %1;"
                 :: "r"(mbar), "r"(bytes) : "memory");
}
__device__ __forceinline__ void mbar_wait_cta(uint32_t mbar, uint32_t parity) {
    asm volatile(
        "{\n\t"
        ".reg .pred P1;\n\t"
        "WAIT_LOOP_%=:\n\t"
        "mbarrier.try_wait.parity.acquire.cta.shared::cta.b64 P1, [%0], %1, 0x989680;\n\t"
        "@P1 bra.uni WAIT_DONE_%=;\n\t"
        "bra.uni WAIT_LOOP_%=;\n\t"
        "WAIT_DONE_%=:\n\t"
        "}"
        :: "r"(mbar), "r"(parity) : "memory");
}

__device__ __forceinline__ void fma2(unsigned long long& d,
                                     unsigned long long a,
                                     unsigned long long b) {
    asm("fma.rn.f32x2 %0, %1, %2, %0;" : "+l"(d) : "l"(a), "l"(b));
}
union UF2 { unsigned long long u; float2 f; };

__device__ __forceinline__ unsigned ld_acq_u32(const unsigned* p) {
    unsigned v;
    asm volatile("ld.global.acquire.gpu.u32 %0, [%1];" : "=r"(v) : "l"(p));
    return v;
}
__device__ __forceinline__ void batch_barrier(int b, unsigned target) {
    __syncthreads();
    if (threadIdx.x == 0) {
        __threadfence();
        atomicAdd(&g_bar[b], 1u);
        while (ld_acq_u32(&g_bar[b]) < target) { }
    }
    __syncthreads();
}

// (fallback-only) conflict-free smem matvec
__device__ __forceinline__ void matvec32(const float* __restrict__ sW,
                                         const float* __restrict__ vec,
                                         float* __restrict__ dest)
{
    const int lane = threadIdx.x & 31;
    const int warp = threadIdx.x >> 5;
    float4 v0 = *(const float4*)(vec + 0   + lane * 4);
    float4 v1 = *(const float4*)(vec + 128 + lane * 4);
    float4 v2 = *(const float4*)(vec + 256 + lane * 4);
    float4 v3 = *(const float4*)(vec + 384 + lane * 4);
#pragma unroll
    for (int rr = 0; rr < 4; rr++) {
        int r = warp * 4 + rr;
        const float* w = sW + r * 512;
        float4 w0 = *(const float4*)(w + 0   + lane * 4);
        float4 w1 = *(const float4*)(w + 128 + lane * 4);
        float4 w2 = *(const float4*)(w + 256 + lane * 4);
        float4 w3 = *(const float4*)(w + 384 + lane * 4);
        float s = w0.x * v0.x + w0.y * v0.y + w0.z * v0.z + w0.w * v0.w
                + w1.x * v1.x + w1.y * v1.y + w1.z * v1.z + w1.w * v1.w
                + w2.x * v2.x + w2.y * v2.y + w2.z * v2.z + w2.w * v2.w
                + w3.x * v3.x + w3.y * v3.y + w3.z * v3.z + w3.w * v3.w;
#pragma unroll
        for (int off = 16; off >= 1; off >>= 1)
            s += __shfl_down_sync(0xffffffffu, s, off);
        if (lane == 0) dest[r] = s;
    }
}

// owner-warp sum: inbox layout [cta][nl] (16x4); reduce 16, broadcast 4 scores
__device__ __forceinline__ void owner_reduce_bcast(
    const float* __restrict__ inbox, int lane, int c,
    const uint32_t* __restrict__ pbv, uint32_t off_dst, uint32_t off_mb)
{
    float s = inbox[lane] + inbox[lane + 32];
    s += __shfl_xor_sync(0xffffffffu, s, 4);
    s += __shfl_xor_sync(0xffffffffu, s, 8);
    s += __shfl_xor_sync(0xffffffffu, s, 16);
    float shi = __shfl_down_sync(0xffffffffu, s, 1);
    if (lane == 0 || lane == 2) {
        uint32_t doff = off_dst + (uint32_t)(c * 4 + lane) * 4;
#pragma unroll
        for (int r = 0; r < CPB; r++)
            push_async64(pbv[r] + doff, s, shi, pbv[r] + off_mb);
    }
}

// ---------------- dual-batch cluster scan: owner-reduce score exchange -----
struct __align__(16) CS {
    float tape[2][NTAPE * 33];
    float hnew[2][512];           // doubles as h_work
    float rso[2][64];             // owner inbox: [cta][nl]
    float rsf[2][64];             // finished read scores (unscaled)
    float wso[2][64];
    float wsf[2][64];
    float acc[2][RPC];
    float wv[2][RPC];
    float bh[RPC], gz[RPC], gr[RPC], gh[RPC], bg[RPC];
    unsigned long long mb_rso[2], mb_rsf[2], mb_hn[2], mb_wso[2], mb_wsf[2];
};

#define RSO_BYTES 256   // 16 src CTAs x 2 b64
#define RSF_BYTES 256   // 16 owners x 2 b64
#define WSO_BYTES 256
#define WSF_BYTES 256
#define HN_BYTES  (CPB * RPC * 4)   // 2048

__global__ __launch_bounds__(NTHREADS, 1) void scan4_kernel(
    const float* __restrict__ tape_init,
    const float* __restrict__ hwork_init,
    const float* __restrict__ W_h,
    const float* __restrict__ b_h,
    const float* __restrict__ W_write,
    const float* __restrict__ gzv,
    const float* __restrict__ grv,
    const float* __restrict__ ghv,
    const float* __restrict__ bgv,
    float* __restrict__ out)
{
    extern __shared__ char raw[];
    CS& S = *(CS*)raw;

    const int t    = threadIdx.x;
    const int lane = t & 31;
    const int cw   = t >> 5;
    const int u    = blockIdx.x >> 4;
    const int c    = blockIdx.x & 15;
    const int d0   = c * RPC;
    const float scale = 0.044194173824159216f;  // 1/sqrt(512)

    const bool isctrl = (cw == 0) || (cw == 5);
    const int  gme    = (cw == 5) ? 1 : 0;
    // owner roles (never the ctrl warps)
    const bool is_rs_owner = (cw == 1) || (cw == 6);
    const int  rs_og       = (cw == 6) ? 1 : 0;
    const bool is_ws_owner = (cw == 2) || (cw == 7);
    const int  ws_og       = (cw == 7) ? 1 : 0;

    // ---- weights into registers ----
    unsigned long long wh[4][8], ww[4][8];
#pragma unroll
    for (int i = 0; i < 4; i++) {
        const size_t rowoff = (size_t)(d0 + cw * 4 + i) * 512;
#pragma unroll
        for (int ch = 0; ch < 4; ch++) {
            ulonglong2 a = *(const ulonglong2*)(W_h     + rowoff + ch * 128 + lane * 4);
            ulonglong2 b = *(const ulonglong2*)(W_write + rowoff + ch * 128 + lane * 4);
            wh[i][ch * 2] = a.x; wh[i][ch * 2 + 1] = a.y;
            ww[i][ch * 2] = b.x; ww[i][ch * 2 + 1] = b.y;
        }
    }

    // ---- one-time smem loads ----
#pragma unroll
    for (int g = 0; g < 2; g++) {
        int bg = 2 * u + g;
        for (int i = t; i < NTAPE * RPC; i += NTHREADS) {
            int n = i >> 5, dl = i & 31;
            S.tape[g][n * 33 + dl] = tape_init[(size_t)(bg * NTAPE + n) * DD + d0 + dl];
        }
        for (int i = t; i < 512; i += NTHREADS)
            S.hnew[g][i] = hwork_init[bg * 512 + i];
    }
    if (t < RPC) {
        S.bh[t] = b_h[d0 + t];  S.gz[t] = gzv[d0 + t];
        S.gr[t] = grv[d0 + t];  S.gh[t] = ghv[d0 + t];
        S.bg[t] = bgv[d0 + t];
    }

    const uint32_t sbase = smem_u32(&S);
    uint32_t pb[CPB];
#pragma unroll
    for (int r = 0; r < CPB; r++) pb[r] = mapa_u32(sbase, r);

    uint32_t mbrso[2], mbrsf[2], mbhn[2], mbwso[2], mbwsf[2];
    uint32_t off_rso[2], off_rsf[2], off_hn[2], off_wso[2], off_wsf[2];
    uint32_t offm_rso[2], offm_rsf[2], offm_hn[2], offm_wso[2], offm_wsf[2];
#pragma unroll
    for (int g = 0; g < 2; g++) {
        mbrso[g] = smem_u32(&S.mb_rso[g]);
        mbrsf[g] = smem_u32(&S.mb_rsf[g]);
        mbhn[g]  = smem_u32(&S.mb_hn[g]);
        mbwso[g] = smem_u32(&S.mb_wso[g]);
        mbwsf[g] = smem_u32(&S.mb_wsf[g]);
        off_rso[g] = smem_u32(&S.rso[g][0]) - sbase;
        off_rsf[g] = smem_u32(&S.rsf[g][0]) - sbase;
        off_hn[g]  = smem_u32(&S.hnew[g][0]) - sbase;
        off_wso[g] = smem_u32(&S.wso[g][0]) - sbase;
        off_wsf[g] = smem_u32(&S.wsf[g][0]) - sbase;
        offm_rso[g] = mbrso[g] - sbase;
        offm_rsf[g] = mbrsf[g] - sbase;
        offm_hn[g]  = mbhn[g]  - sbase;
        offm_wso[g] = mbwso[g] - sbase;
        offm_wsf[g] = mbwsf[g] - sbase;
    }
    if (t == 0) {
#pragma unroll
        for (int g = 0; g < 2; g++) {
            mbar_init(mbrso[g], 1); mbar_init(mbrsf[g], 1); mbar_init(mbhn[g], 1);
            mbar_init(mbwso[g], 1); mbar_init(mbwsf[g], 1);
            mbar_expect_tx(mbrso[g], RSO_BYTES);
            mbar_expect_tx(mbrsf[g], RSF_BYTES);
            mbar_expect_tx(mbhn[g],  HN_BYTES);
            mbar_expect_tx(mbwso[g], WSO_BYTES);
            mbar_expect_tx(mbwsf[g], WSF_BYTES);
        }
    }
    __syncthreads();

    // ---- pre-loop: acc[g] = Wh @ h_init ----
#pragma unroll
    for (int g = 0; g < 2; g++) {
        unsigned long long v[8];
#pragma unroll
        for (int ch = 0; ch < 4; ch++) {
            ulonglong2 tv = *(const ulonglong2*)(&S.hnew[g][ch * 128 + lane * 4]);
            v[ch * 2] = tv.x; v[ch * 2 + 1] = tv.y;
        }
        unsigned long long a2[4] = {0ull, 0ull, 0ull, 0ull};
#pragma unroll
        for (int i = 0; i < 4; i++)
#pragma unroll
            for (int p = 0; p < 8; p++) fma2(a2[i], wh[i][p], v[p]);
        float sa[4];
#pragma unroll
        for (int i = 0; i < 4; i++) { UF2 x; x.u = a2[i]; sa[i] = x.f.x + x.f.y; }
#pragma unroll
        for (int off = 16; off >= 1; off >>= 1) {
#pragma unroll
            for (int i = 0; i < 4; i++)
                sa[i] += __shfl_xor_sync(0xffffffffu, sa[i], off);
        }
        if (lane == 0)
            *(float4*)&S.acc[g][cw * 4] = make_float4(sa[0], sa[1], sa[2], sa[3]);
    }
    __syncthreads();
    CLUSTER_SYNC_();

    const int n4 = t >> 2, q4 = t & 3;
    const int g2    = cw >> 2;
    const int rbase = (cw & 3) * 16;

    // ---- xz prefetch (ctrl warps, step 0) ----
    float xp = 0.f, zt = 0.f;
    if (isctrl) {
        size_t row = (size_t)((2 * u + gme) * TT) * EE;
        xp = __ldcs(&g_xz[row + d0 + lane]);
        zt = __ldcs(&g_xz[row + 512 + d0 + lane]);
    }

    for (int step = 0; step < TT; step++) {
        const uint32_t par = step & 1u;

        // ---- Phase A: read-score partials -> push pair to OWNER only ----
#pragma unroll
        for (int g = 0; g < 2; g++) {
            float s = 0.f;
#pragma unroll
            for (int k = 0; k < 8; k++) {
                int dl = q4 * 8 + k;
                s += S.hnew[g][d0 + dl] * S.tape[g][n4 * 33 + dl];
            }
            s += __shfl_down_sync(0xffffffffu, s, 2);
            s += __shfl_down_sync(0xffffffffu, s, 1);
            float shi = __shfl_down_sync(0xffffffffu, s, 4);   // partial[n4+1]
            if ((t & 7) == 0) {
                int o  = n4 >> 2;        // owner rank
                int nl = n4 & 3;         // 0 or 2
                uint32_t doff = off_rso[g] + (uint32_t)(c * 4 + nl) * 4;
                push_async64(pb[o] + doff, s, shi, pb[o] + offm_rso[g]);
            }
        }

        // ---- rs OWNER (warps 1,6): reduce 16 partials, broadcast scores ----
        if (is_rs_owner) {
            const int g = rs_og;
            mbar_wait_cta(mbrso[g], par);
            if (lane == 0) mbar_expect_tx(mbrso[g], RSO_BYTES);
            owner_reduce_bcast(S.rso[g], lane, c, pb, off_rsf[g], offm_rsf[g]);
        }

        // ---- Phase B (ctrl warps): wait finished scores, softmax, h ----
        if (isctrl) {
            const int g = gme;
            const int bg = 2 * u + g;
            mbar_wait_cta(mbrsf[g], par);
            if (lane == 0) mbar_expect_tx(mbrsf[g], RSF_BYTES);
            float a0 = S.rsf[g][lane] * scale;
            float a1 = S.rsf[g][lane + 32] * scale;
            float m = fmaxf(a0, a1);
#pragma unroll
            for (int off = 16; off >= 1; off >>= 1)
                m = fmaxf(m, __shfl_xor_sync(0xffffffffu, m, off));
            float e0 = __expf(a0 - m), e1 = __expf(a1 - m);
            float ss = e0 + e1;
#pragma unroll
            for (int off = 16; off >= 1; off >>= 1)
                ss += __shfl_xor_sync(0xffffffffu, ss, off);
            float inv = 1.f / ss;
            e0 *= inv; e1 *= inv;
            float rv0 = 0.f, rv1 = 0.f, rv2 = 0.f, rv3 = 0.f;
#pragma unroll
            for (int k = 0; k < 8; k++) {
                rv0 += __shfl_sync(0xffffffffu, e0, 4 * k + 0) * S.tape[g][(4 * k + 0) * 33 + lane];
                rv1 += __shfl_sync(0xffffffffu, e0, 4 * k + 1) * S.tape[g][(4 * k + 1) * 33 + lane];
                rv2 += __shfl_sync(0xffffffffu, e0, 4 * k + 2) * S.tape[g][(4 * k + 2) * 33 + lane];
                rv3 += __shfl_sync(0xffffffffu, e0, 4 * k + 3) * S.tape[g][(4 * k + 3) * 33 + lane];
            }
#pragma unroll
            for (int k = 0; k < 8; k++) {
                rv0 += __shfl_sync(0xffffffffu, e1, 4 * k + 0) * S.tape[g][(32 + 4 * k + 0) * 33 + lane];
                rv1 += __shfl_sync(0xffffffffu, e1, 4 * k + 1) * S.tape[g][(32 + 4 * k + 1) * 33 + lane];
                rv2 += __shfl_sync(0xffffffffu, e1, 4 * k + 2) * S.tape[g][(32 + 4 * k + 2) * 33 + lane];
                rv3 += __shfl_sync(0xffffffffu, e1, 4 * k + 3) * S.tape[g][(32 + 4 * k + 3) * 33 + lane];
            }
            float rv = (rv0 + rv1) + (rv2 + rv3);
            float pre = xp + S.acc[g][lane] + rv + S.bh[lane];
            float ex2 = __expf(2.f * pre);
            float hn  = 1.f - 2.f / (ex2 + 1.f);
            // paired b64 h pushes to ALL ranks — unblocks C
            float hnhi = __shfl_down_sync(0xffffffffu, hn, 1);
            if ((lane & 1) == 0) {
                uint32_t doff = off_hn[g] + (uint32_t)(d0 + lane) * 4;
#pragma unroll
                for (int r = 0; r < CPB; r++)
                    push_async64(pb[r] + doff, hn, hnhi, pb[r] + offm_hn[g]);
            }
            float gi = zt * S.gz[lane] + rv * S.gr[lane] + hn * S.gh[lane] + S.bg[lane];
            gi = fminf(fmaxf(gi, -20.f), 20.f);
            float sig = 1.f / (1.f + __expf(-gi));
            out[(size_t)(bg * TT + step) * DD + d0 + lane] = hn * gi * sig;
            // prefetch next step's xz
            int sn = (step + 1 < TT) ? step + 1 : step;
            size_t nrow = (size_t)(bg * TT + sn) * EE;
            xp = __ldcs(&g_xz[nrow + d0 + lane]);
            zt = __ldcs(&g_xz[nrow + 512 + d0 + lane]);
        }

        // ---- Phase C: staggered waits — matvec(g0) overlaps B(g1) ----
#pragma unroll
        for (int g = 0; g < 2; g++) {
            mbar_wait_cta(mbhn[g], par);
            unsigned long long v[8];
#pragma unroll
            for (int ch = 0; ch < 4; ch++) {
                ulonglong2 tv = *(const ulonglong2*)(&S.hnew[g][ch * 128 + lane * 4]);
                v[ch * 2] = tv.x; v[ch * 2 + 1] = tv.y;
            }
            unsigned long long a2[4] = {0ull, 0ull, 0ull, 0ull};
            unsigned long long b2[4] = {0ull, 0ull, 0ull, 0ull};
#pragma unroll
            for (int i = 0; i < 4; i++)
#pragma unroll
                for (int p = 0; p < 8; p++) {
                    fma2(a2[i], wh[i][p], v[p]);
                    fma2(b2[i], ww[i][p], v[p]);
                }
            float sa[4], sb[4];
#pragma unroll
            for (int i = 0; i < 4; i++) {
                UF2 x; x.u = a2[i]; sa[i] = x.f.x + x.f.y;
                UF2 y; y.u = b2[i]; sb[i] = y.f.x + y.f.y;
            }
#pragma unroll
            for (int off = 16; off >= 1; off >>= 1) {
#pragma unroll
                for (int i = 0; i < 4; i++) {
                    sa[i] += __shfl_xor_sync(0xffffffffu, sa[i], off);
                    sb[i] += __shfl_xor_sync(0xffffffffu, sb[i], off);
                }
            }
            if (lane == 0) {
                *(float4*)&S.acc[g][cw * 4] = make_float4(sa[0], sa[1], sa[2], sa[3]);
                *(float4*)&S.wv[g][cw * 4]  = make_float4(sb[0], sb[1], sb[2], sb[3]);
            }
        }
        if (t == 0) {   // re-arm after BOTH waits have passed
            mbar_expect_tx(mbhn[0], HN_BYTES);
            mbar_expect_tx(mbhn[1], HN_BYTES);
        }
        __syncthreads();   // S3: acc/wv exchange

        // ---- write-score partials -> push pair to OWNER only ----
#pragma unroll
        for (int g = 0; g < 2; g++) {
            float s = 0.f;
#pragma unroll
            for (int k = 0; k < 8; k++) {
                int dl = q4 * 8 + k;
                s += S.wv[g][dl] * S.tape[g][n4 * 33 + dl];
            }
            s += __shfl_down_sync(0xffffffffu, s, 2);
            s += __shfl_down_sync(0xffffffffu, s, 1);
            float shi = __shfl_down_sync(0xffffffffu, s, 4);
            if ((t & 7) == 0) {
                int o  = n4 >> 2;
                int nl = n4 & 3;
                uint32_t doff = off_wso[g] + (uint32_t)(c * 4 + nl) * 4;
                push_async64(pb[o] + doff, s, shi, pb[o] + offm_wso[g]);
            }
        }

        // ---- ws OWNER (warps 2,7): reduce, broadcast ----
        if (is_ws_owner) {
            const int g = ws_og;
            mbar_wait_cta(mbwso[g], par);
            if (lane == 0) mbar_expect_tx(mbwso[g], WSO_BYTES);
            owner_reduce_bcast(S.wso[g], lane, c, pb, off_wsf[g], offm_wsf[g]);
        }

        // ---- Phase D: wait finished write scores, softmax, tape update ----
        {
            mbar_wait_cta(mbwsf[g2], par);
            if (lane == 0 && (cw == 0 || cw == 4))
                mbar_expect_tx(mbwsf[g2], WSF_BYTES);
            float a0 = S.wsf[g2][lane] * scale;
            float a1 = S.wsf[g2][lane + 32] * scale;
            float m = fmaxf(a0, a1);
#pragma unroll
            for (int off = 16; off >= 1; off >>= 1)
                m = fmaxf(m, __shfl_xor_sync(0xffffffffu, m, off));
            float e0 = __expf(a0 - m), e1 = __expf(a1 - m);
            float ss = e0 + e1;
#pragma unroll
            for (int off = 16; off >= 1; off >>= 1)
                ss += __shfl_xor_sync(0xffffffffu, ss, off);
            float inv = 1.f / ss;
            float eh = (rbase < 32) ? e0 * inv : e1 * inv;
            float wvl = S.wv[g2][lane];
#pragma unroll
            for (int r = 0; r < 16; r++) {
                int n = rbase + r;
                float a = __shfl_sync(0xffffffffu, eh, n & 31);
                float tp = S.tape[g2][n * 33 + lane];
                S.tape[g2][n * 33 + lane] = tp - tp * a + wvl * a;
            }
        }
        __syncthreads();   // S6: tape/hnew ordering for next step
    }

    // ---- final tape output ----
#pragma unroll
    for (int g = 0; g < 2; g++) {
        int bg = 2 * u + g;
        for (int e = t; e < NTAPE * RPC; e += NTHREADS) {
            int n = e >> 5, dl = e & 31;
            out[(size_t)BB * TT * DD + (size_t)(bg * NTAPE + n) * DD + d0 + dl] =
                S.tape[g][n * 33 + dl];
        }
    }
    CLUSTER_SYNC_();
}

// ---------------- fallback scan kernel (global-memory barriers) -----------
struct ScanSmem {
    float Wh[RPC * 512];
    float Ww[RPC * 512];
    float tape[NTAPE * 33];
    float hwork[512];
    float hnew[512];
    float acc[RPC];
    float wv[RPC];
    float rv[RPC];
    float attn[NTAPE];
    float score[NTAPE];
    float bh[RPC], gz[RPC], gr[RPC], gh[RPC], bg[RPC];
};

__device__ __forceinline__ void softmax64f(const float* __restrict__ score,
                                           float* __restrict__ attn, int t)
{
    if (t < 32) {
        float a = score[t], b = score[t + 32];
        float m = fmaxf(a, b);
#pragma unroll
        for (int off = 16; off >= 1; off >>= 1)
            m = fmaxf(m, __shfl_xor_sync(0xffffffffu, m, off));
        float e0 = __expf(a - m), e1 = __expf(b - m);
        float ss = e0 + e1;
#pragma unroll
        for (int off = 16; off >= 1; off >>= 1)
            ss += __shfl_xor_sync(0xffffffffu, ss, off);
        float inv = 1.f / ss;
        attn[t] = e0 * inv;
        attn[t + 32] = e1 * inv;
    }
}

__global__ __launch_bounds__(NTHREADS, 1) void scan_kernel(
    const float* __restrict__ tape_init,
    const float* __restrict__ hwork_init,
    const float* __restrict__ W_h,
    const float* __restrict__ b_h,
    const float* __restrict__ W_write,
    const float* __restrict__ gzv,
    const float* __restrict__ grv,
    const float* __restrict__ ghv,
    const float* __restrict__ bgv,
    float* __restrict__ out)
{
    extern __shared__ char raw[];
    ScanSmem& S = *(ScanSmem*)raw;

    const int t  = threadIdx.x;
    const int b  = blockIdx.x / CPB;
    const int c  = blockIdx.x % CPB;
    const int d0 = c * RPC;
    const float scale = 0.044194173824159216f;

    for (int i = t; i < RPC * 512; i += NTHREADS) {
        S.Wh[i] = W_h[(size_t)d0 * 512 + i];
        S.Ww[i] = W_write[(size_t)d0 * 512 + i];
    }
    for (int i = t; i < NTAPE * RPC; i += NTHREADS) {
        int n = i >> 5, dl = i & 31;
        S.tape[n * 33 + dl] = tape_init[(size_t)(b * NTAPE + n) * DD + d0 + dl];
    }
    for (int i = t; i < 512; i += NTHREADS)
        S.hwork[i] = hwork_init[b * 512 + i];
    if (t < RPC) {
        S.bh[t] = b_h[d0 + t];  S.gz[t] = gzv[d0 + t];
        S.gr[t] = grv[d0 + t];  S.gh[t] = ghv[d0 + t];
        S.bg[t] = bgv[d0 + t];
    }
    __syncthreads();

    unsigned bc = 0;
    const int n4 = t >> 2, q4 = t & 3;
    const int dl8 = t >> 3, q8 = t & 7;

    for (int step = 0; step < TT; step++) {
        {
            float s = 0.f;
#pragma unroll
            for (int k = 0; k < 8; k++) {
                int dl = q4 * 8 + k;
                s += S.hwork[d0 + dl] * S.tape[n4 * 33 + dl];
            }
            s += __shfl_down_sync(0xffffffffu, s, 2);
            s += __shfl_down_sync(0xffffffffu, s, 1);
            if (q4 == 0) g_rs[(b * CPB + c) * NTAPE + n4] = s;
        }
        matvec32(S.Wh, S.hwork, S.acc);
        batch_barrier(b, (++bc) * CPB);

        if (t < NTAPE) {
            float s = 0.f;
#pragma unroll
            for (int cc = 0; cc < CPB; cc++)
                s += __ldcg(&g_rs[(b * CPB + cc) * NTAPE + t]);
            S.score[t] = s * scale;
        }
        __syncthreads();
        softmax64f(S.score, S.attn, t);
        __syncthreads();
        {
            float s = 0.f;
#pragma unroll
            for (int k = 0; k < 8; k++) {
                int n = q8 * 8 + k;
                s += S.attn[n] * S.tape[n * 33 + dl8];
            }
            s += __shfl_down_sync(0xffffffffu, s, 4);
            s += __shfl_down_sync(0xffffffffu, s, 2);
            s += __shfl_down_sync(0xffffffffu, s, 1);
            if (q8 == 0) S.rv[dl8] = s;
        }
        __syncthreads();
        if (t < RPC) {
            size_t row = (size_t)(b * TT + step) * EE;
            float xp = g_xz[row + d0 + t];
            float zt = g_xz[row + 512 + d0 + t];
            float hn = tanhf(xp + S.acc[t] + S.rv[t] + S.bh[t]);
            g_hnew[b * 512 + d0 + t] = hn;
            float gi = zt * S.gz[t] + S.rv[t] * S.gr[t] + hn * S.gh[t] + S.bg[t];
            gi = fminf(fmaxf(gi, -20.f), 20.f);
            float sig = 1.f / (1.f + __expf(-gi));
            out[(size_t)(b * TT + step) * DD + d0 + t] = hn * gi * sig;
        }
        batch_barrier(b, (++bc) * CPB);

        S.hnew[t]       = __ldcg(&g_hnew[b * 512 + t]);
        S.hnew[t + 256] = __ldcg(&g_hnew[b * 512 + t + 256]);
        __syncthreads();
        matvec32(S.Ww, S.hnew, S.wv);
        __syncthreads();
        {
            float s = 0.f;
#pragma unroll
            for (int k = 0; k < 8; k++) {
                int dl = q4 * 8 + k;
                s += S.wv[dl] * S.tape[n4 * 33 + dl];
            }
            s += __shfl_down_sync(0xffffffffu, s, 2);
            s += __shfl_down_sync(0xffffffffu, s, 1);
            if (q4 == 0) g_ws[(b * CPB + c) * NTAPE + n4] = s;
        }
        batch_barrier(b, (++bc) * CPB);

        if (t < NTAPE) {
            float s = 0.f;
#pragma unroll
            for (int cc = 0; cc < CPB; cc++)
                s += __ldcg(&g_ws[(b * CPB + cc) * NTAPE + t]);
            S.score[t] = s * scale;
        }
        __syncthreads();
        softmax64f(S.score, S.attn, t);
        __syncthreads();
        for (int e = t; e < NTAPE * RPC; e += NTHREADS) {
            int n = e >> 5, dl = e & 31;
            float a  = S.attn[n];
            float tp = S.tape[n * 33 + dl];
            S.tape[n * 33 + dl] = tp - tp * a + S.wv[dl] * a;
        }
        S.hwork[t]       = S.hnew[t];
        S.hwork[t + 256] = S.hnew[t + 256];
        __syncthreads();
    }

    for (int e = t; e < NTAPE * RPC; e += NTHREADS) {
        int n = e >> 5, dl = e & 31;
        out[(size_t)BB * TT * DD + (size_t)(b * NTAPE + n) * DD + d0 + dl] =
            S.tape[n * 33 + dl];
    }
}

// ---------------- launch ---------------------------------------------------
extern "C" void kernel_launch(void* const* d_in, const int* in_sizes, int n_in,
                              void* d_out, int out_size)
{
    const float* x         = (const float*)d_in[0];
    const float* tape_init = (const float*)d_in[1];
    const float* hwork     = (const float*)d_in[2];
    const float* W_h       = (const float*)d_in[3];
    const float* W_xz      = (const float*)d_in[4];
    const float* b_h       = (const float*)d_in[5];
    const float* W_write   = (const float*)d_in[6];
    const float* g_z       = (const float*)d_in[7];
    const float* g_r       = (const float*)d_in[8];
    const float* g_h       = (const float*)d_in[9];
    const float* b_gate    = (const float*)d_in[10];
    float* out = (float*)d_out;

    gemm_xz_kernel<<<dim3(EE / 64, (BB * TT) / 64), 256>>>(x, W_xz);

    // ---- primary: owner-reduce dual-batch cluster scan ----
    cudaFuncSetAttribute(scan4_kernel,
                         cudaFuncAttributeMaxDynamicSharedMemorySize,
                         (int)sizeof(CS));
    cudaError_t aerr = cudaFuncSetAttribute(
        scan4_kernel, cudaFuncAttributeNonPortableClusterSizeAllowed, 1);

    cudaLaunchConfig_t cfg = {};
    cfg.gridDim  = dim3(NCLU * CPB, 1, 1);
    cfg.blockDim = dim3(NTHREADS, 1, 1);
    cfg.dynamicSmemBytes = sizeof(CS);
    cfg.stream = 0;

    int maxClu = 0;
    cudaError_t qerr = cudaOccupancyMaxPotentialClusterSize(
        &maxClu, scan4_kernel, &cfg);

    bool launched = false;
    if (aerr == cudaSuccess && qerr == cudaSuccess && maxClu >= CPB) {
        cudaLaunchAttribute attrs[1];
        attrs[0].id = cudaLaunchAttributeClusterDimension;
        attrs[0].val.clusterDim.x = CPB;
        attrs[0].val.clusterDim.y = 1;
        attrs[0].val.clusterDim.z = 1;
        cfg.attrs = attrs;
        cfg.numAttrs = 1;
        cudaError_t lerr = cudaLaunchKernelEx(&cfg, scan4_kernel,
            tape_init, hwork, W_h, b_h, W_write, g_z, g_r, g_h, b_gate, out);
        launched = (lerr == cudaSuccess);
    }

    // ---- fallback ----
    if (!launched) {
        cudaFuncSetAttribute(scan_kernel,
                             cudaFuncAttributeMaxDynamicSharedMemorySize,
                             (int)sizeof(ScanSmem));
        init_bar_kernel<<<1, 32>>>();
        scan_kernel<<<BB * CPB, NTHREADS, sizeof(ScanSmem)>>>(
            tape_init, hwork, W_h, b_h, W_write, g_z, g_r, g_h, b_gate, out);
    }
}

// round 13
// speedup vs baseline: 1.5587x; 1.0638x over previous
#include <cuda_runtime.h>
#include <cstdint>
#include <cstddef>

// Problem constants
#define BB   8
#define TT   1024
#define DD   512
#define EE   1024
#define NTAPE 64
#define CPB  16        // CTAs per cluster
#define RPC  32        // rows / tape-cols per CTA
#define NTHREADS 256
#define NCLU  4        // clusters (2 batches each)

// ---------------- device scratch ----------
__device__ float    g_xz[(size_t)BB * TT * EE];
__device__ float    g_rs[BB * CPB * NTAPE];         // fallback exchange
__device__ float    g_ws[BB * CPB * NTAPE];
__device__ float    g_hnew[BB * DD];
__device__ unsigned g_bar[BB];

__global__ void init_bar_kernel() {
    if (threadIdx.x < BB) g_bar[threadIdx.x] = 0u;
}

// ---------------- projection GEMM (double-buffered) ----------
__global__ __launch_bounds__(256) void gemm_xz_kernel(
    const float* __restrict__ X, const float* __restrict__ W)
{
    __shared__ float As[2][16][68];
    __shared__ float Bs[2][16][68];
    const int m0 = blockIdx.y * 64;
    const int e0 = blockIdx.x * 64;
    const int tid = threadIdx.x;
    const int tx = tid & 15;
    const int ty = tid >> 4;
    const int lr = tid >> 2;
    const int lc = (tid & 3) * 4;
    float acc[4][4] = {};

    float4 xv = *(const float4*)(X + (size_t)(m0 + lr) * 512 + lc);
    float4 wv = *(const float4*)(W + (size_t)(e0 + lr) * 512 + lc);
    As[0][lc + 0][lr] = xv.x; As[0][lc + 1][lr] = xv.y;
    As[0][lc + 2][lr] = xv.z; As[0][lc + 3][lr] = xv.w;
    Bs[0][lc + 0][lr] = wv.x; Bs[0][lc + 1][lr] = wv.y;
    Bs[0][lc + 2][lr] = wv.z; Bs[0][lc + 3][lr] = wv.w;
    __syncthreads();

    for (int kt = 0; kt < 32; kt++) {
        const int cur = kt & 1;
        if (kt + 1 < 32) {
            xv = *(const float4*)(X + (size_t)(m0 + lr) * 512 + (kt + 1) * 16 + lc);
            wv = *(const float4*)(W + (size_t)(e0 + lr) * 512 + (kt + 1) * 16 + lc);
        }
#pragma unroll
        for (int kk = 0; kk < 16; kk++) {
            float4 a  = *(const float4*)&As[cur][kk][ty * 4];
            float4 bv = *(const float4*)&Bs[cur][kk][tx * 4];
            float av[4] = {a.x, a.y, a.z, a.w};
            float bw[4] = {bv.x, bv.y, bv.z, bv.w};
#pragma unroll
            for (int i = 0; i < 4; i++)
#pragma unroll
                for (int j = 0; j < 4; j++)
                    acc[i][j] += av[i] * bw[j];
        }
        if (kt + 1 < 32) {
            const int nxt = cur ^ 1;
            As[nxt][lc + 0][lr] = xv.x; As[nxt][lc + 1][lr] = xv.y;
            As[nxt][lc + 2][lr] = xv.z; As[nxt][lc + 3][lr] = xv.w;
            Bs[nxt][lc + 0][lr] = wv.x; Bs[nxt][lc + 1][lr] = wv.y;
            Bs[nxt][lc + 2][lr] = wv.z; Bs[nxt][lc + 3][lr] = wv.w;
            __syncthreads();
        }
    }
#pragma unroll
    for (int i = 0; i < 4; i++) {
        float4 o = make_float4(acc[i][0], acc[i][1], acc[i][2], acc[i][3]);
        *(float4*)(&g_xz[(size_t)(m0 + ty * 4 + i) * EE + e0 + tx * 4]) = o;
    }
}

// ---------------- helpers ------------------------------------------
__device__ __forceinline__ uint32_t smem_u32(const void* p) {
    return (uint32_t)__cvta_generic_to_shared(p);
}
__device__ __forceinline__ uint32_t mapa_u32(uint32_t local_addr, uint32_t rank) {
    uint32_t r;
    asm volatile("mapa.shared::cluster.u32 %0, %1, %2;"
                 : "=r"(r) : "r"(local_addr), "r"(rank));
    return r;
}
#define CLUSTER_SYNC_() do {                                              \
    asm volatile("barrier.cluster.arrive.aligned;" ::: "memory");         \
    asm volatile("barrier.cluster.wait.aligned;"   ::: "memory");         \
} while (0)

__device__ __forceinline__ void push_async64(uint32_t raddr, float lo, float hi,
                                             uint32_t rmbar) {
    unsigned long long v =
        (unsigned long long)__float_as_uint(lo) |
        ((unsigned long long)__float_as_uint(hi) << 32);
    asm volatile(
        "st.async.shared::cluster.mbarrier::complete_tx::bytes.b64 [%0], %1, [%2];"
        :: "r"(raddr), "l"(v), "r"(rmbar) : "memory");
}
__device__ __forceinline__ void mbar_init(uint32_t mbar, uint32_t cnt) {
    asm volatile("mbarrier.init.shared.b64 [%0], %1;" :: "r"(mbar), "r"(cnt) : "memory");
}
__device__ __forceinline__ void mbar_expect_tx(uint32_t mbar, uint32_t bytes) {
    asm volatile("mbarrier.arrive.expect_tx.shared.b64 _, [%0], %1;"
                 :: "r"(mbar), "r"(bytes) : "memory");
}
__device__ __forceinline__ void mbar_wait_cta(uint32_t mbar, uint32_t parity) {
    asm volatile(
        "{\n\t"
        ".reg .pred P1;\n\t"
        "WAIT_LOOP_%=:\n\t"
        "mbarrier.try_wait.parity.acquire.cta.shared::cta.b64 P1, [%0], %1, 0x989680;\n\t"
        "@P1 bra.uni WAIT_DONE_%=;\n\t"
        "bra.uni WAIT_LOOP_%=;\n\t"
        "WAIT_DONE_%=:\n\t"
        "}"
        :: "r"(mbar), "r"(parity) : "memory");
}

__device__ __forceinline__ void fma2(unsigned long long& d,
                                     unsigned long long a,
                                     unsigned long long b) {
    asm("fma.rn.f32x2 %0, %1, %2, %0;" : "+l"(d) : "l"(a), "l"(b));
}
union UF2 { unsigned long long u; float2 f; };

__device__ __forceinline__ unsigned ld_acq_u32(const unsigned* p) {
    unsigned v;
    asm volatile("ld.global.acquire.gpu.u32 %0, [%1];" : "=r"(v) : "l"(p));
    return v;
}
__device__ __forceinline__ void batch_barrier(int b, unsigned target) {
    __syncthreads();
    if (threadIdx.x == 0) {
        __threadfence();
        atomicAdd(&g_bar[b], 1u);
        while (ld_acq_u32(&g_bar[b]) < target) { }
    }
    __syncthreads();
}

// (fallback-only) conflict-free smem matvec
__device__ __forceinline__ void matvec32(const float* __restrict__ sW,
                                         const float* __restrict__ vec,
                                         float* __restrict__ dest)
{
    const int lane = threadIdx.x & 31;
    const int warp = threadIdx.x >> 5;
    float4 v0 = *(const float4*)(vec + 0   + lane * 4);
    float4 v1 = *(const float4*)(vec + 128 + lane * 4);
    float4 v2 = *(const float4*)(vec + 256 + lane * 4);
    float4 v3 = *(const float4*)(vec + 384 + lane * 4);
#pragma unroll
    for (int rr = 0; rr < 4; rr++) {
        int r = warp * 4 + rr;
        const float* w = sW + r * 512;
        float4 w0 = *(const float4*)(w + 0   + lane * 4);
        float4 w1 = *(const float4*)(w + 128 + lane * 4);
        float4 w2 = *(const float4*)(w + 256 + lane * 4);
        float4 w3 = *(const float4*)(w + 384 + lane * 4);
        float s = w0.x * v0.x + w0.y * v0.y + w0.z * v0.z + w0.w * v0.w
                + w1.x * v1.x + w1.y * v1.y + w1.z * v1.z + w1.w * v1.w
                + w2.x * v2.x + w2.y * v2.y + w2.z * v2.z + w2.w * v2.w
                + w3.x * v3.x + w3.y * v3.y + w3.z * v3.z + w3.w * v3.w;
#pragma unroll
        for (int off = 16; off >= 1; off >>= 1)
            s += __shfl_down_sync(0xffffffffu, s, off);
        if (lane == 0) dest[r] = s;
    }
}

// owner-warp sum: inbox layout [cta][nl] (16x4); reduce 16, broadcast 4 scores
__device__ __forceinline__ void owner_reduce_bcast(
    const float* __restrict__ inbox, int lane, int c,
    const uint32_t* __restrict__ pbv, uint32_t off_dst, uint32_t off_mb)
{
    float s = inbox[lane] + inbox[lane + 32];
    s += __shfl_xor_sync(0xffffffffu, s, 4);
    s += __shfl_xor_sync(0xffffffffu, s, 8);
    s += __shfl_xor_sync(0xffffffffu, s, 16);
    float shi = __shfl_down_sync(0xffffffffu, s, 1);
    if (lane == 0 || lane == 2) {
        uint32_t doff = off_dst + (uint32_t)(c * 4 + lane) * 4;
#pragma unroll
        for (int r = 0; r < CPB; r++)
            push_async64(pbv[r] + doff, s, shi, pbv[r] + off_mb);
    }
}

// ---------------- dual-batch cluster scan: owner-reduce score exchange -----
struct __align__(16) CS {
    float tape[2][NTAPE * 33];
    float hnew[2][512];           // doubles as h_work
    float rso[2][64];             // owner inbox: [cta][nl]
    float rsf[2][64];             // finished read scores (unscaled)
    float wso[2][64];
    float wsf[2][64];
    float attn[2][64];            // ctrl-warp normalized read attn (B-local)
    float acc[2][RPC];
    float wv[2][RPC];
    float bh[RPC], gz[RPC], gr[RPC], gh[RPC], bg[RPC];
    unsigned long long mb_rso[2], mb_rsf[2], mb_hn[2], mb_wso[2], mb_wsf[2];
};

#define RSO_BYTES 256   // 16 src CTAs x 2 b64
#define RSF_BYTES 256   // 16 owners x 2 b64
#define WSO_BYTES 256
#define WSF_BYTES 256
#define HN_BYTES  (CPB * RPC * 4)   // 2048

__global__ __launch_bounds__(NTHREADS, 1) void scan4_kernel(
    const float* __restrict__ tape_init,
    const float* __restrict__ hwork_init,
    const float* __restrict__ W_h,
    const float* __restrict__ b_h,
    const float* __restrict__ W_write,
    const float* __restrict__ gzv,
    const float* __restrict__ grv,
    const float* __restrict__ ghv,
    const float* __restrict__ bgv,
    float* __restrict__ out)
{
    extern __shared__ char raw[];
    CS& S = *(CS*)raw;

    const int t    = threadIdx.x;
    const int lane = t & 31;
    const int cw   = t >> 5;
    const int u    = blockIdx.x >> 4;
    const int c    = blockIdx.x & 15;
    const int d0   = c * RPC;
    const float scale = 0.044194173824159216f;  // 1/sqrt(512)

    const bool isctrl = (cw == 0) || (cw == 5);
    const int  gme    = (cw == 5) ? 1 : 0;
    const bool is_rs_owner = (cw == 1) || (cw == 6);
    const int  rs_og       = (cw == 6) ? 1 : 0;
    const bool is_ws_owner = (cw == 2) || (cw == 7);
    const int  ws_og       = (cw == 7) ? 1 : 0;

    // ---- weights into registers ----
    unsigned long long wh[4][8], ww[4][8];
#pragma unroll
    for (int i = 0; i < 4; i++) {
        const size_t rowoff = (size_t)(d0 + cw * 4 + i) * 512;
#pragma unroll
        for (int ch = 0; ch < 4; ch++) {
            ulonglong2 a = *(const ulonglong2*)(W_h     + rowoff + ch * 128 + lane * 4);
            ulonglong2 b = *(const ulonglong2*)(W_write + rowoff + ch * 128 + lane * 4);
            wh[i][ch * 2] = a.x; wh[i][ch * 2 + 1] = a.y;
            ww[i][ch * 2] = b.x; ww[i][ch * 2 + 1] = b.y;
        }
    }

    // ---- one-time smem loads ----
#pragma unroll
    for (int g = 0; g < 2; g++) {
        int bg = 2 * u + g;
        for (int i = t; i < NTAPE * RPC; i += NTHREADS) {
            int n = i >> 5, dl = i & 31;
            S.tape[g][n * 33 + dl] = tape_init[(size_t)(bg * NTAPE + n) * DD + d0 + dl];
        }
        for (int i = t; i < 512; i += NTHREADS)
            S.hnew[g][i] = hwork_init[bg * 512 + i];
    }
    if (t < RPC) {
        S.bh[t] = b_h[d0 + t];  S.gz[t] = gzv[d0 + t];
        S.gr[t] = grv[d0 + t];  S.gh[t] = ghv[d0 + t];
        S.bg[t] = bgv[d0 + t];
    }

    const uint32_t sbase = smem_u32(&S);
    uint32_t pb[CPB];
#pragma unroll
    for (int r = 0; r < CPB; r++) pb[r] = mapa_u32(sbase, r);

    uint32_t mbrso[2], mbrsf[2], mbhn[2], mbwso[2], mbwsf[2];
    uint32_t off_rso[2], off_rsf[2], off_hn[2], off_wso[2], off_wsf[2];
    uint32_t offm_rso[2], offm_rsf[2], offm_hn[2], offm_wso[2], offm_wsf[2];
#pragma unroll
    for (int g = 0; g < 2; g++) {
        mbrso[g] = smem_u32(&S.mb_rso[g]);
        mbrsf[g] = smem_u32(&S.mb_rsf[g]);
        mbhn[g]  = smem_u32(&S.mb_hn[g]);
        mbwso[g] = smem_u32(&S.mb_wso[g]);
        mbwsf[g] = smem_u32(&S.mb_wsf[g]);
        off_rso[g] = smem_u32(&S.rso[g][0]) - sbase;
        off_rsf[g] = smem_u32(&S.rsf[g][0]) - sbase;
        off_hn[g]  = smem_u32(&S.hnew[g][0]) - sbase;
        off_wso[g] = smem_u32(&S.wso[g][0]) - sbase;
        off_wsf[g] = smem_u32(&S.wsf[g][0]) - sbase;
        offm_rso[g] = mbrso[g] - sbase;
        offm_rsf[g] = mbrsf[g] - sbase;
        offm_hn[g]  = mbhn[g]  - sbase;
        offm_wso[g] = mbwso[g] - sbase;
        offm_wsf[g] = mbwsf[g] - sbase;
    }
    if (t == 0) {
#pragma unroll
        for (int g = 0; g < 2; g++) {
            mbar_init(mbrso[g], 1); mbar_init(mbrsf[g], 1); mbar_init(mbhn[g], 1);
            mbar_init(mbwso[g], 1); mbar_init(mbwsf[g], 1);
            mbar_expect_tx(mbrso[g], RSO_BYTES);
            mbar_expect_tx(mbrsf[g], RSF_BYTES);
            mbar_expect_tx(mbhn[g],  HN_BYTES);
            mbar_expect_tx(mbwso[g], WSO_BYTES);
            mbar_expect_tx(mbwsf[g], WSF_BYTES);
        }
    }
    __syncthreads();

    // ---- pre-loop: acc[g] = Wh @ h_init ----
#pragma unroll
    for (int g = 0; g < 2; g++) {
        unsigned long long v[8];
#pragma unroll
        for (int ch = 0; ch < 4; ch++) {
            ulonglong2 tv = *(const ulonglong2*)(&S.hnew[g][ch * 128 + lane * 4]);
            v[ch * 2] = tv.x; v[ch * 2 + 1] = tv.y;
        }
        unsigned long long a2[4] = {0ull, 0ull, 0ull, 0ull};
#pragma unroll
        for (int i = 0; i < 4; i++)
#pragma unroll
            for (int p = 0; p < 8; p++) fma2(a2[i], wh[i][p], v[p]);
        float sa[4];
#pragma unroll
        for (int i = 0; i < 4; i++) { UF2 x; x.u = a2[i]; sa[i] = x.f.x + x.f.y; }
#pragma unroll
        for (int off = 16; off >= 1; off >>= 1) {
#pragma unroll
            for (int i = 0; i < 4; i++)
                sa[i] += __shfl_xor_sync(0xffffffffu, sa[i], off);
        }
        if (lane == 0)
            *(float4*)&S.acc[g][cw * 4] = make_float4(sa[0], sa[1], sa[2], sa[3]);
    }
    __syncthreads();
    CLUSTER_SYNC_();

    const int n4 = t >> 2, q4 = t & 3;
    const int g2    = cw >> 2;
    const int rbase = (cw & 3) * 16;

    // ---- xz prefetch (ctrl warps, step 0) ----
    float xp = 0.f, zt = 0.f;
    if (isctrl) {
        size_t row = (size_t)((2 * u + gme) * TT) * EE;
        xp = __ldcs(&g_xz[row + d0 + lane]);
        zt = __ldcs(&g_xz[row + 512 + d0 + lane]);
    }

    for (int step = 0; step < TT; step++) {
        const uint32_t par = step & 1u;

        // ---- Phase A: read-score partials -> push pair to OWNER only ----
#pragma unroll
        for (int g = 0; g < 2; g++) {
            float s = 0.f;
#pragma unroll
            for (int k = 0; k < 8; k++) {
                int dl = q4 * 8 + k;
                s += S.hnew[g][d0 + dl] * S.tape[g][n4 * 33 + dl];
            }
            s += __shfl_down_sync(0xffffffffu, s, 2);
            s += __shfl_down_sync(0xffffffffu, s, 1);
            float shi = __shfl_down_sync(0xffffffffu, s, 4);   // partial[n4+1]
            if ((t & 7) == 0) {
                int o  = n4 >> 2;
                int nl = n4 & 3;
                uint32_t doff = off_rso[g] + (uint32_t)(c * 4 + nl) * 4;
                push_async64(pb[o] + doff, s, shi, pb[o] + offm_rso[g]);
            }
        }

        // ---- rs OWNER (warps 1,6): reduce 16 partials, broadcast scores ----
        if (is_rs_owner) {
            const int g = rs_og;
            mbar_wait_cta(mbrso[g], par);
            if (lane == 0) mbar_expect_tx(mbrso[g], RSO_BYTES);
            owner_reduce_bcast(S.rso[g], lane, c, pb, off_rsf[g], offm_rsf[g]);
        }

        // ---- Phase B (ctrl warps): wait finished scores, softmax, h ----
        if (isctrl) {
            const int g = gme;
            const int bg = 2 * u + g;
            mbar_wait_cta(mbrsf[g], par);
            if (lane == 0) mbar_expect_tx(mbrsf[g], RSF_BYTES);
            float a0 = S.rsf[g][lane] * scale;
            float a1 = S.rsf[g][lane + 32] * scale;
            float m = fmaxf(a0, a1);
#pragma unroll
            for (int off = 16; off >= 1; off >>= 1)
                m = fmaxf(m, __shfl_xor_sync(0xffffffffu, m, off));
            float e0 = __expf(a0 - m), e1 = __expf(a1 - m);
            float ss = e0 + e1;
#pragma unroll
            for (int off = 16; off >= 1; off >>= 1)
                ss += __shfl_xor_sync(0xffffffffu, ss, off);
            float inv = 1.f / ss;
            e0 *= inv; e1 *= inv;
            // stage attn in smem, read back with broadcast LDS.128 (4 attn/ld)
            S.attn[g][lane]      = e0;
            S.attn[g][lane + 32] = e1;
            __syncwarp();
            float rv0 = 0.f, rv1 = 0.f, rv2 = 0.f, rv3 = 0.f;
#pragma unroll
            for (int k = 0; k < 16; k++) {
                float4 a4 = *(const float4*)&S.attn[g][k * 4];
                rv0 += a4.x * S.tape[g][(4 * k + 0) * 33 + lane];
                rv1 += a4.y * S.tape[g][(4 * k + 1) * 33 + lane];
                rv2 += a4.z * S.tape[g][(4 * k + 2) * 33 + lane];
                rv3 += a4.w * S.tape[g][(4 * k + 3) * 33 + lane];
            }
            float rv = (rv0 + rv1) + (rv2 + rv3);
            float pre = xp + S.acc[g][lane] + rv + S.bh[lane];
            float ex2 = __expf(2.f * pre);
            float hn  = 1.f - 2.f / (ex2 + 1.f);
            // paired b64 h pushes to ALL ranks — unblocks C
            float hnhi = __shfl_down_sync(0xffffffffu, hn, 1);
            if ((lane & 1) == 0) {
                uint32_t doff = off_hn[g] + (uint32_t)(d0 + lane) * 4;
#pragma unroll
                for (int r = 0; r < CPB; r++)
                    push_async64(pb[r] + doff, hn, hnhi, pb[r] + offm_hn[g]);
            }
            float gi = zt * S.gz[lane] + rv * S.gr[lane] + hn * S.gh[lane] + S.bg[lane];
            gi = fminf(fmaxf(gi, -20.f), 20.f);
            float sig = 1.f / (1.f + __expf(-gi));
            out[(size_t)(bg * TT + step) * DD + d0 + lane] = hn * gi * sig;
            // prefetch next step's xz
            int sn = (step + 1 < TT) ? step + 1 : step;
            size_t nrow = (size_t)(bg * TT + sn) * EE;
            xp = __ldcs(&g_xz[nrow + d0 + lane]);
            zt = __ldcs(&g_xz[nrow + 512 + d0 + lane]);
        }

        // ---- Phase C: all warps wait h (joint), dual register matvec ----
        mbar_wait_cta(mbhn[0], par);
        mbar_wait_cta(mbhn[1], par);
        if (t == 0) {
            mbar_expect_tx(mbhn[0], HN_BYTES);
            mbar_expect_tx(mbhn[1], HN_BYTES);
        }
#pragma unroll
        for (int g = 0; g < 2; g++) {
            unsigned long long v[8];
#pragma unroll
            for (int ch = 0; ch < 4; ch++) {
                ulonglong2 tv = *(const ulonglong2*)(&S.hnew[g][ch * 128 + lane * 4]);
                v[ch * 2] = tv.x; v[ch * 2 + 1] = tv.y;
            }
            unsigned long long a2[4] = {0ull, 0ull, 0ull, 0ull};
            unsigned long long b2[4] = {0ull, 0ull, 0ull, 0ull};
#pragma unroll
            for (int i = 0; i < 4; i++)
#pragma unroll
                for (int p = 0; p < 8; p++) {
                    fma2(a2[i], wh[i][p], v[p]);
                    fma2(b2[i], ww[i][p], v[p]);
                }
            float sa[4], sb[4];
#pragma unroll
            for (int i = 0; i < 4; i++) {
                UF2 x; x.u = a2[i]; sa[i] = x.f.x + x.f.y;
                UF2 y; y.u = b2[i]; sb[i] = y.f.x + y.f.y;
            }
#pragma unroll
            for (int off = 16; off >= 1; off >>= 1) {
#pragma unroll
                for (int i = 0; i < 4; i++) {
                    sa[i] += __shfl_xor_sync(0xffffffffu, sa[i], off);
                    sb[i] += __shfl_xor_sync(0xffffffffu, sb[i], off);
                }
            }
            if (lane == 0) {
                *(float4*)&S.acc[g][cw * 4] = make_float4(sa[0], sa[1], sa[2], sa[3]);
                *(float4*)&S.wv[g][cw * 4]  = make_float4(sb[0], sb[1], sb[2], sb[3]);
            }
        }
        __syncthreads();   // S3: acc/wv exchange

        // ---- write-score partials -> push pair to OWNER only ----
#pragma unroll
        for (int g = 0; g < 2; g++) {
            float s = 0.f;
#pragma unroll
            for (int k = 0; k < 8; k++) {
                int dl = q4 * 8 + k;
                s += S.wv[g][dl] * S.tape[g][n4 * 33 + dl];
            }
            s += __shfl_down_sync(0xffffffffu, s, 2);
            s += __shfl_down_sync(0xffffffffu, s, 1);
            float shi = __shfl_down_sync(0xffffffffu, s, 4);
            if ((t & 7) == 0) {
                int o  = n4 >> 2;
                int nl = n4 & 3;
                uint32_t doff = off_wso[g] + (uint32_t)(c * 4 + nl) * 4;
                push_async64(pb[o] + doff, s, shi, pb[o] + offm_wso[g]);
            }
        }

        // ---- ws OWNER (warps 2,7): reduce, broadcast ----
        if (is_ws_owner) {
            const int g = ws_og;
            mbar_wait_cta(mbwso[g], par);
            if (lane == 0) mbar_expect_tx(mbwso[g], WSO_BYTES);
            owner_reduce_bcast(S.wso[g], lane, c, pb, off_wsf[g], offm_wsf[g]);
        }

        // ---- Phase D: wait finished write scores, softmax, tape update ----
        {
            mbar_wait_cta(mbwsf[g2], par);
            if (lane == 0 && (cw == 0 || cw == 4))
                mbar_expect_tx(mbwsf[g2], WSF_BYTES);
            float a0 = S.wsf[g2][lane] * scale;
            float a1 = S.wsf[g2][lane + 32] * scale;
            float m = fmaxf(a0, a1);
#pragma unroll
            for (int off = 16; off >= 1; off >>= 1)
                m = fmaxf(m, __shfl_xor_sync(0xffffffffu, m, off));
            float e0 = __expf(a0 - m), e1 = __expf(a1 - m);
            float ss = e0 + e1;
#pragma unroll
            for (int off = 16; off >= 1; off >>= 1)
                ss += __shfl_xor_sync(0xffffffffu, ss, off);
            float inv = 1.f / ss;
            float eh = (rbase < 32) ? e0 * inv : e1 * inv;
            float wvl = S.wv[g2][lane];
#pragma unroll
            for (int r = 0; r < 16; r++) {
                int n = rbase + r;
                float a = __shfl_sync(0xffffffffu, eh, n & 31);
                float tp = S.tape[g2][n * 33 + lane];
                S.tape[g2][n * 33 + lane] = tp - tp * a + wvl * a;
            }
        }
        __syncthreads();   // S6: tape/hnew ordering for next step
    }

    // ---- final tape output ----
#pragma unroll
    for (int g = 0; g < 2; g++) {
        int bg = 2 * u + g;
        for (int e = t; e < NTAPE * RPC; e += NTHREADS) {
            int n = e >> 5, dl = e & 31;
            out[(size_t)BB * TT * DD + (size_t)(bg * NTAPE + n) * DD + d0 + dl] =
                S.tape[g][n * 33 + dl];
        }
    }
    CLUSTER_SYNC_();
}

// ---------------- fallback scan kernel (global-memory barriers) -----------
struct ScanSmem {
    float Wh[RPC * 512];
    float Ww[RPC * 512];
    float tape[NTAPE * 33];
    float hwork[512];
    float hnew[512];
    float acc[RPC];
    float wv[RPC];
    float rv[RPC];
    float attn[NTAPE];
    float score[NTAPE];
    float bh[RPC], gz[RPC], gr[RPC], gh[RPC], bg[RPC];
};

__device__ __forceinline__ void softmax64f(const float* __restrict__ score,
                                           float* __restrict__ attn, int t)
{
    if (t < 32) {
        float a = score[t], b = score[t + 32];
        float m = fmaxf(a, b);
#pragma unroll
        for (int off = 16; off >= 1; off >>= 1)
            m = fmaxf(m, __shfl_xor_sync(0xffffffffu, m, off));
        float e0 = __expf(a - m), e1 = __expf(b - m);
        float ss = e0 + e1;
#pragma unroll
        for (int off = 16; off >= 1; off >>= 1)
            ss += __shfl_xor_sync(0xffffffffu, ss, off);
        float inv = 1.f / ss;
        attn[t] = e0 * inv;
        attn[t + 32] = e1 * inv;
    }
}

__global__ __launch_bounds__(NTHREADS, 1) void scan_kernel(
    const float* __restrict__ tape_init,
    const float* __restrict__ hwork_init,
    const float* __restrict__ W_h,
    const float* __restrict__ b_h,
    const float* __restrict__ W_write,
    const float* __restrict__ gzv,
    const float* __restrict__ grv,
    const float* __restrict__ ghv,
    const float* __restrict__ bgv,
    float* __restrict__ out)
{
    extern __shared__ char raw[];
    ScanSmem& S = *(ScanSmem*)raw;

    const int t  = threadIdx.x;
    const int b  = blockIdx.x / CPB;
    const int c  = blockIdx.x % CPB;
    const int d0 = c * RPC;
    const float scale = 0.044194173824159216f;

    for (int i = t; i < RPC * 512; i += NTHREADS) {
        S.Wh[i] = W_h[(size_t)d0 * 512 + i];
        S.Ww[i] = W_write[(size_t)d0 * 512 + i];
    }
    for (int i = t; i < NTAPE * RPC; i += NTHREADS) {
        int n = i >> 5, dl = i & 31;
        S.tape[n * 33 + dl] = tape_init[(size_t)(b * NTAPE + n) * DD + d0 + dl];
    }
    for (int i = t; i < 512; i += NTHREADS)
        S.hwork[i] = hwork_init[b * 512 + i];
    if (t < RPC) {
        S.bh[t] = b_h[d0 + t];  S.gz[t] = gzv[d0 + t];
        S.gr[t] = grv[d0 + t];  S.gh[t] = ghv[d0 + t];
        S.bg[t] = bgv[d0 + t];
    }
    __syncthreads();

    unsigned bc = 0;
    const int n4 = t >> 2, q4 = t & 3;
    const int dl8 = t >> 3, q8 = t & 7;

    for (int step = 0; step < TT; step++) {
        {
            float s = 0.f;
#pragma unroll
            for (int k = 0; k < 8; k++) {
                int dl = q4 * 8 + k;
                s += S.hwork[d0 + dl] * S.tape[n4 * 33 + dl];
            }
            s += __shfl_down_sync(0xffffffffu, s, 2);
            s += __shfl_down_sync(0xffffffffu, s, 1);
            if (q4 == 0) g_rs[(b * CPB + c) * NTAPE + n4] = s;
        }
        matvec32(S.Wh, S.hwork, S.acc);
        batch_barrier(b, (++bc) * CPB);

        if (t < NTAPE) {
            float s = 0.f;
#pragma unroll
            for (int cc = 0; cc < CPB; cc++)
                s += __ldcg(&g_rs[(b * CPB + cc) * NTAPE + t]);
            S.score[t] = s * scale;
        }
        __syncthreads();
        softmax64f(S.score, S.attn, t);
        __syncthreads();
        {
            float s = 0.f;
#pragma unroll
            for (int k = 0; k < 8; k++) {
                int n = q8 * 8 + k;
                s += S.attn[n] * S.tape[n * 33 + dl8];
            }
            s += __shfl_down_sync(0xffffffffu, s, 4);
            s += __shfl_down_sync(0xffffffffu, s, 2);
            s += __shfl_down_sync(0xffffffffu, s, 1);
            if (q8 == 0) S.rv[dl8] = s;
        }
        __syncthreads();
        if (t < RPC) {
            size_t row = (size_t)(b * TT + step) * EE;
            float xp = g_xz[row + d0 + t];
            float zt = g_xz[row + 512 + d0 + t];
            float hn = tanhf(xp + S.acc[t] + S.rv[t] + S.bh[t]);
            g_hnew[b * 512 + d0 + t] = hn;
            float gi = zt * S.gz[t] + S.rv[t] * S.gr[t] + hn * S.gh[t] + S.bg[t];
            gi = fminf(fmaxf(gi, -20.f), 20.f);
            float sig = 1.f / (1.f + __expf(-gi));
            out[(size_t)(b * TT + step) * DD + d0 + t] = hn * gi * sig;
        }
        batch_barrier(b, (++bc) * CPB);

        S.hnew[t]       = __ldcg(&g_hnew[b * 512 + t]);
        S.hnew[t + 256] = __ldcg(&g_hnew[b * 512 + t + 256]);
        __syncthreads();
        matvec32(S.Ww, S.hnew, S.wv);
        __syncthreads();
        {
            float s = 0.f;
#pragma unroll
            for (int k = 0; k < 8; k++) {
                int dl = q4 * 8 + k;
                s += S.wv[dl] * S.tape[n4 * 33 + dl];
            }
            s += __shfl_down_sync(0xffffffffu, s, 2);
            s += __shfl_down_sync(0xffffffffu, s, 1);
            if (q4 == 0) g_ws[(b * CPB + c) * NTAPE + n4] = s;
        }
        batch_barrier(b, (++bc) * CPB);

        if (t < NTAPE) {
            float s = 0.f;
#pragma unroll
            for (int cc = 0; cc < CPB; cc++)
                s += __ldcg(&g_ws[(b * CPB + cc) * NTAPE + t]);
            S.score[t] = s * scale;
        }
        __syncthreads();
        softmax64f(S.score, S.attn, t);
        __syncthreads();
        for (int e = t; e < NTAPE * RPC; e += NTHREADS) {
            int n = e >> 5, dl = e & 31;
            float a  = S.attn[n];
            float tp = S.tape[n * 33 + dl];
            S.tape[n * 33 + dl] = tp - tp * a + S.wv[dl] * a;
        }
        S.hwork[t]       = S.hnew[t];
        S.hwork[t + 256] = S.hnew[t + 256];
        __syncthreads();
    }

    for (int e = t; e < NTAPE * RPC; e += NTHREADS) {
        int n = e >> 5, dl = e & 31;
        out[(size_t)BB * TT * DD + (size_t)(b * NTAPE + n) * DD + d0 + dl] =
            S.tape[n * 33 + dl];
    }
}

// ---------------- launch ---------------------------------------------------
extern "C" void kernel_launch(void* const* d_in, const int* in_sizes, int n_in,
                              void* d_out, int out_size)
{
    const float* x         = (const float*)d_in[0];
    const float* tape_init = (const float*)d_in[1];
    const float* hwork     = (const float*)d_in[2];
    const float* W_h       = (const float*)d_in[3];
    const float* W_xz      = (const float*)d_in[4];
    const float* b_h       = (const float*)d_in[5];
    const float* W_write   = (const float*)d_in[6];
    const float* g_z       = (const float*)d_in[7];
    const float* g_r       = (const float*)d_in[8];
    const float* g_h       = (const float*)d_in[9];
    const float* b_gate    = (const float*)d_in[10];
    float* out = (float*)d_out;

    gemm_xz_kernel<<<dim3(EE / 64, (BB * TT) / 64), 256>>>(x, W_xz);

    // ---- primary: owner-reduce dual-batch cluster scan ----
    cudaFuncSetAttribute(scan4_kernel,
                         cudaFuncAttributeMaxDynamicSharedMemorySize,
                         (int)sizeof(CS));
    cudaError_t aerr = cudaFuncSetAttribute(
        scan4_kernel, cudaFuncAttributeNonPortableClusterSizeAllowed, 1);

    cudaLaunchConfig_t cfg = {};
    cfg.gridDim  = dim3(NCLU * CPB, 1, 1);
    cfg.blockDim = dim3(NTHREADS, 1, 1);
    cfg.dynamicSmemBytes = sizeof(CS);
    cfg.stream = 0;

    int maxClu = 0;
    cudaError_t qerr = cudaOccupancyMaxPotentialClusterSize(
        &maxClu, scan4_kernel, &cfg);

    bool launched = false;
    if (aerr == cudaSuccess && qerr == cudaSuccess && maxClu >= CPB) {
        cudaLaunchAttribute attrs[1];
        attrs[0].id = cudaLaunchAttributeClusterDimension;
        attrs[0].val.clusterDim.x = CPB;
        attrs[0].val.clusterDim.y = 1;
        attrs[0].val.clusterDim.z = 1;
        cfg.attrs = attrs;
        cfg.numAttrs = 1;
        cudaError_t lerr = cudaLaunchKernelEx(&cfg, scan4_kernel,
            tape_init, hwork, W_h, b_h, W_write, g_z, g_r, g_h, b_gate, out);
        launched = (lerr == cudaSuccess);
    }

    // ---- fallback ----
    if (!launched) {
        cudaFuncSetAttribute(scan_kernel,
                             cudaFuncAttributeMaxDynamicSharedMemorySize,
                             (int)sizeof(ScanSmem));
        init_bar_kernel<<<1, 32>>>();
        scan_kernel<<<BB * CPB, NTHREADS, sizeof(ScanSmem)>>>(
            tape_init, hwork, W_h, b_h, W_write, g_z, g_r, g_h, b_gate, out);
    }
}

// round 14
// speedup vs baseline: 1.6449x; 1.0553x over previous
#include <cuda_runtime.h>
#include <cstdint>
#include <cstddef>

// Problem constants
#define BB   8
#define TT   1024
#define DD   512
#define EE   1024
#define NTAPE 64
#define CPB  16        // CTAs per cluster
#define RPC  32        // rows / tape-cols per CTA
#define NTHREADS 256
#define NCLU  4        // clusters (2 batches each)

// ---------------- device scratch ----------
__device__ float    g_xz[(size_t)BB * TT * EE];
__device__ float    g_rs[BB * CPB * NTAPE];         // fallback exchange
__device__ float    g_ws[BB * CPB * NTAPE];
__device__ float    g_hnew[BB * DD];
__device__ unsigned g_bar[BB];

__global__ void init_bar_kernel() {
    if (threadIdx.x < BB) g_bar[threadIdx.x] = 0u;
}

// ---------------- projection GEMM (double-buffered) ----------
__global__ __launch_bounds__(256) void gemm_xz_kernel(
    const float* __restrict__ X, const float* __restrict__ W)
{
    __shared__ float As[2][16][68];
    __shared__ float Bs[2][16][68];
    const int m0 = blockIdx.y * 64;
    const int e0 = blockIdx.x * 64;
    const int tid = threadIdx.x;
    const int tx = tid & 15;
    const int ty = tid >> 4;
    const int lr = tid >> 2;
    const int lc = (tid & 3) * 4;
    float acc[4][4] = {};

    float4 xv = *(const float4*)(X + (size_t)(m0 + lr) * 512 + lc);
    float4 wv = *(const float4*)(W + (size_t)(e0 + lr) * 512 + lc);
    As[0][lc + 0][lr] = xv.x; As[0][lc + 1][lr] = xv.y;
    As[0][lc + 2][lr] = xv.z; As[0][lc + 3][lr] = xv.w;
    Bs[0][lc + 0][lr] = wv.x; Bs[0][lc + 1][lr] = wv.y;
    Bs[0][lc + 2][lr] = wv.z; Bs[0][lc + 3][lr] = wv.w;
    __syncthreads();

    for (int kt = 0; kt < 32; kt++) {
        const int cur = kt & 1;
        if (kt + 1 < 32) {
            xv = *(const float4*)(X + (size_t)(m0 + lr) * 512 + (kt + 1) * 16 + lc);
            wv = *(const float4*)(W + (size_t)(e0 + lr) * 512 + (kt + 1) * 16 + lc);
        }
#pragma unroll
        for (int kk = 0; kk < 16; kk++) {
            float4 a  = *(const float4*)&As[cur][kk][ty * 4];
            float4 bv = *(const float4*)&Bs[cur][kk][tx * 4];
            float av[4] = {a.x, a.y, a.z, a.w};
            float bw[4] = {bv.x, bv.y, bv.z, bv.w};
#pragma unroll
            for (int i = 0; i < 4; i++)
#pragma unroll
                for (int j = 0; j < 4; j++)
                    acc[i][j] += av[i] * bw[j];
        }
        if (kt + 1 < 32) {
            const int nxt = cur ^ 1;
            As[nxt][lc + 0][lr] = xv.x; As[nxt][lc + 1][lr] = xv.y;
            As[nxt][lc + 2][lr] = xv.z; As[nxt][lc + 3][lr] = xv.w;
            Bs[nxt][lc + 0][lr] = wv.x; Bs[nxt][lc + 1][lr] = wv.y;
            Bs[nxt][lc + 2][lr] = wv.z; Bs[nxt][lc + 3][lr] = wv.w;
            __syncthreads();
        }
    }
#pragma unroll
    for (int i = 0; i < 4; i++) {
        float4 o = make_float4(acc[i][0], acc[i][1], acc[i][2], acc[i][3]);
        *(float4*)(&g_xz[(size_t)(m0 + ty * 4 + i) * EE + e0 + tx * 4]) = o;
    }
}

// ---------------- helpers ------------------------------------------
__device__ __forceinline__ uint32_t smem_u32(const void* p) {
    return (uint32_t)__cvta_generic_to_shared(p);
}
__device__ __forceinline__ uint32_t mapa_u32(uint32_t local_addr, uint32_t rank) {
    uint32_t r;
    asm volatile("mapa.shared::cluster.u32 %0, %1, %2;"
                 : "=r"(r) : "r"(local_addr), "r"(rank));
    return r;
}
#define CLUSTER_SYNC_() do {                                              \
    asm volatile("barrier.cluster.arrive.aligned;" ::: "memory");         \
    asm volatile("barrier.cluster.wait.aligned;"   ::: "memory");         \
} while (0)

__device__ __forceinline__ void push_async32(uint32_t raddr, float v, uint32_t rmbar) {
    asm volatile(
        "st.async.shared::cluster.mbarrier::complete_tx::bytes.b32 [%0], %1, [%2];"
        :: "r"(raddr), "r"(__float_as_uint(v)), "r"(rmbar) : "memory");
}
__device__ __forceinline__ void push_async64(uint32_t raddr, float lo, float hi,
                                             uint32_t rmbar) {
    unsigned long long v =
        (unsigned long long)__float_as_uint(lo) |
        ((unsigned long long)__float_as_uint(hi) << 32);
    asm volatile(
        "st.async.shared::cluster.mbarrier::complete_tx::bytes.b64 [%0], %1, [%2];"
        :: "r"(raddr), "l"(v), "r"(rmbar) : "memory");
}
__device__ __forceinline__ void mbar_init(uint32_t mbar, uint32_t cnt) {
    asm volatile("mbarrier.init.shared.b64 [%0], %1;" :: "r"(mbar), "r"(cnt) : "memory");
}
__device__ __forceinline__ void mbar_expect_tx(uint32_t mbar, uint32_t bytes) {
    asm volatile("mbarrier.arrive.expect_tx.shared.b64 _, [%0], %1;"
                 :: "r"(mbar), "r"(bytes) : "memory");
}
__device__ __forceinline__ void mbar_wait_cta(uint32_t mbar, uint32_t parity) {
    asm volatile(
        "{\n\t"
        ".reg .pred P1;\n\t"
        "WAIT_LOOP_%=:\n\t"
        "mbarrier.try_wait.parity.acquire.cta.shared::cta.b64 P1, [%0], %1, 0x989680;\n\t"
        "@P1 bra.uni WAIT_DONE_%=;\n\t"
        "bra.uni WAIT_LOOP_%=;\n\t"
        "WAIT_DONE_%=:\n\t"
        "}"
        :: "r"(mbar), "r"(parity) : "memory");
}

__device__ __forceinline__ void fma2(unsigned long long& d,
                                     unsigned long long a,
                                     unsigned long long b) {
    asm("fma.rn.f32x2 %0, %1, %2, %0;" : "+l"(d) : "l"(a), "l"(b));
}
union UF2 { unsigned long long u; float2 f; };

__device__ __forceinline__ unsigned ld_acq_u32(const unsigned* p) {
    unsigned v;
    asm volatile("ld.global.acquire.gpu.u32 %0, [%1];" : "=r"(v) : "l"(p));
    return v;
}
__device__ __forceinline__ void batch_barrier(int b, unsigned target) {
    __syncthreads();
    if (threadIdx.x == 0) {
        __threadfence();
        atomicAdd(&g_bar[b], 1u);
        while (ld_acq_u32(&g_bar[b]) < target) { }
    }
    __syncthreads();
}

// (fallback-only) conflict-free smem matvec
__device__ __forceinline__ void matvec32(const float* __restrict__ sW,
                                         const float* __restrict__ vec,
                                         float* __restrict__ dest)
{
    const int lane = threadIdx.x & 31;
    const int warp = threadIdx.x >> 5;
    float4 v0 = *(const float4*)(vec + 0   + lane * 4);
    float4 v1 = *(const float4*)(vec + 128 + lane * 4);
    float4 v2 = *(const float4*)(vec + 256 + lane * 4);
    float4 v3 = *(const float4*)(vec + 384 + lane * 4);
#pragma unroll
    for (int rr = 0; rr < 4; rr++) {
        int r = warp * 4 + rr;
        const float* w = sW + r * 512;
        float4 w0 = *(const float4*)(w + 0   + lane * 4);
        float4 w1 = *(const float4*)(w + 128 + lane * 4);
        float4 w2 = *(const float4*)(w + 256 + lane * 4);
        float4 w3 = *(const float4*)(w + 384 + lane * 4);
        float s = w0.x * v0.x + w0.y * v0.y + w0.z * v0.z + w0.w * v0.w
                + w1.x * v1.x + w1.y * v1.y + w1.z * v1.z + w1.w * v1.w
                + w2.x * v2.x + w2.y * v2.y + w2.z * v2.z + w2.w * v2.w
                + w3.x * v3.x + w3.y * v3.y + w3.z * v3.z + w3.w * v3.w;
#pragma unroll
        for (int off = 16; off >= 1; off >>= 1)
            s += __shfl_down_sync(0xffffffffu, s, off);
        if (lane == 0) dest[r] = s;
    }
}

// ---------------- blended owner-reduce dual-batch cluster scan --------------
// inbox layout per batch: cin[cta][0..3]=p, [4..7]=ws, [8]=q, [9]=pad (stride 10)
struct __align__(16) CS {
    float tape[2][2][NTAPE * 33];   // [buffer][batch]
    float hnew[2][512];
    float cin[2][CPB * 10];         // combined inbox
    float rsf[2][64];               // finished P
    float wsf[2][64];               // finished WS
    float qf[2][2];                 // finished Q (+pad)
    float attn[2][64];              // B staging (blend coeffs)
    float acc[2][RPC];
    float wv[2][RPC];
    float bh[RPC], gz[RPC], gr[RPC], gh[RPC], bg[RPC];
    unsigned long long mb_cin[2], mb_cf[2], mb_hn[2];
};

#define CF_BYTES  (15 * 32 + 40)       // 520: 16 owners' P+WS pairs, rank0 adds Q
#define HN_BYTES  (CPB * RPC * 4)      // 2048

__global__ __launch_bounds__(NTHREADS, 1) void scan6_kernel(
    const float* __restrict__ tape_init,
    const float* __restrict__ hwork_init,
    const float* __restrict__ W_h,
    const float* __restrict__ b_h,
    const float* __restrict__ W_write,
    const float* __restrict__ gzv,
    const float* __restrict__ grv,
    const float* __restrict__ ghv,
    const float* __restrict__ bgv,
    float* __restrict__ out)
{
    extern __shared__ char raw[];
    CS& S = *(CS*)raw;

    const int t    = threadIdx.x;
    const int lane = t & 31;
    const int cw   = t >> 5;
    const int u    = blockIdx.x >> 4;
    const int c    = blockIdx.x & 15;
    const int d0   = c * RPC;
    const float scale = 0.044194173824159216f;  // 1/sqrt(512)

    const bool isctrl = (cw == 0) || (cw == 5);
    const int  gme    = (cw == 5) ? 1 : 0;
    const bool isowner = (cw == 1) || (cw == 6);
    const int  og      = (cw == 6) ? 1 : 0;
    // D-warp assignment (non-ctrl): materialize tape into double buffer
    int dg = -1, dr0 = 0, dr1 = 0;
    if      (cw == 1) { dg = 0; dr0 = 0;  dr1 = 22; }
    else if (cw == 2) { dg = 0; dr0 = 22; dr1 = 43; }
    else if (cw == 3) { dg = 0; dr0 = 43; dr1 = 64; }
    else if (cw == 4) { dg = 1; dr0 = 0;  dr1 = 22; }
    else if (cw == 6) { dg = 1; dr0 = 22; dr1 = 43; }
    else if (cw == 7) { dg = 1; dr0 = 43; dr1 = 64; }
    // epilogue row ownership
    const int g2    = cw >> 2;
    const int rbase = (cw & 3) * 16;
    const uint32_t CIN_BYTES = (c == 0) ? (CPB * 32 + CPB * 4) : (CPB * 32);

    // ---- weights into registers ----
    unsigned long long wh[4][8], ww[4][8];
#pragma unroll
    for (int i = 0; i < 4; i++) {
        const size_t rowoff = (size_t)(d0 + cw * 4 + i) * 512;
#pragma unroll
        for (int ch = 0; ch < 4; ch++) {
            ulonglong2 a = *(const ulonglong2*)(W_h     + rowoff + ch * 128 + lane * 4);
            ulonglong2 b = *(const ulonglong2*)(W_write + rowoff + ch * 128 + lane * 4);
            wh[i][ch * 2] = a.x; wh[i][ch * 2 + 1] = a.y;
            ww[i][ch * 2] = b.x; ww[i][ch * 2 + 1] = b.y;
        }
    }

    // ---- one-time smem loads ----
#pragma unroll
    for (int g = 0; g < 2; g++) {
        int bg = 2 * u + g;
        for (int i = t; i < NTAPE * RPC; i += NTHREADS) {
            int n = i >> 5, dl = i & 31;
            S.tape[0][g][n * 33 + dl] =
                tape_init[(size_t)(bg * NTAPE + n) * DD + d0 + dl];
        }
        for (int i = t; i < 512; i += NTHREADS)
            S.hnew[g][i] = hwork_init[bg * 512 + i];
    }
    if (t < RPC) {
        S.bh[t] = b_h[d0 + t];  S.gz[t] = gzv[d0 + t];
        S.gr[t] = grv[d0 + t];  S.gh[t] = ghv[d0 + t];
        S.bg[t] = bgv[d0 + t];
        S.wv[0][t] = 0.f;  S.wv[1][t] = 0.f;
    }

    const uint32_t sbase = smem_u32(&S);
    uint32_t pb[CPB];
#pragma unroll
    for (int r = 0; r < CPB; r++) pb[r] = mapa_u32(sbase, r);

    uint32_t mbcin[2], mbcf[2], mbhn[2];
    uint32_t off_cin[2], off_rsf[2], off_wsf[2], off_qf[2], off_hn[2];
    uint32_t offm_cin[2], offm_cf[2], offm_hn[2];
#pragma unroll
    for (int g = 0; g < 2; g++) {
        mbcin[g] = smem_u32(&S.mb_cin[g]);
        mbcf[g]  = smem_u32(&S.mb_cf[g]);
        mbhn[g]  = smem_u32(&S.mb_hn[g]);
        off_cin[g] = smem_u32(&S.cin[g][0]) - sbase;
        off_rsf[g] = smem_u32(&S.rsf[g][0]) - sbase;
        off_wsf[g] = smem_u32(&S.wsf[g][0]) - sbase;
        off_qf[g]  = smem_u32(&S.qf[g][0])  - sbase;
        off_hn[g]  = smem_u32(&S.hnew[g][0]) - sbase;
        offm_cin[g] = mbcin[g] - sbase;
        offm_cf[g]  = mbcf[g]  - sbase;
        offm_hn[g]  = mbhn[g]  - sbase;
    }
    if (t == 0) {
#pragma unroll
        for (int g = 0; g < 2; g++) {
            mbar_init(mbcin[g], 1); mbar_init(mbcf[g], 1); mbar_init(mbhn[g], 1);
            mbar_expect_tx(mbcin[g], CIN_BYTES);
            mbar_expect_tx(mbcf[g],  CF_BYTES);
            mbar_expect_tx(mbhn[g],  HN_BYTES);
        }
    }
    __syncthreads();

    // ---- pre-loop: acc[g] = Wh @ h_init ----
#pragma unroll
    for (int g = 0; g < 2; g++) {
        unsigned long long v[8];
#pragma unroll
        for (int ch = 0; ch < 4; ch++) {
            ulonglong2 tv = *(const ulonglong2*)(&S.hnew[g][ch * 128 + lane * 4]);
            v[ch * 2] = tv.x; v[ch * 2 + 1] = tv.y;
        }
        unsigned long long a2[4] = {0ull, 0ull, 0ull, 0ull};
#pragma unroll
        for (int i = 0; i < 4; i++)
#pragma unroll
            for (int p = 0; p < 8; p++) fma2(a2[i], wh[i][p], v[p]);
        float sa[4];
#pragma unroll
        for (int i = 0; i < 4; i++) { UF2 x; x.u = a2[i]; sa[i] = x.f.x + x.f.y; }
#pragma unroll
        for (int off = 16; off >= 1; off >>= 1) {
#pragma unroll
            for (int i = 0; i < 4; i++)
                sa[i] += __shfl_xor_sync(0xffffffffu, sa[i], off);
        }
        if (lane == 0)
            *(float4*)&S.acc[g][cw * 4] = make_float4(sa[0], sa[1], sa[2], sa[3]);
    }
    __syncthreads();
    CLUSTER_SYNC_();

    const int n4 = t >> 2, q4 = t & 3;

    // ---- bootstrap: push p0 = h_init·tape_0, ws=0, q=0 (inbox completion 0) ----
#pragma unroll
    for (int g = 0; g < 2; g++) {
        float sp = 0.f;
#pragma unroll
        for (int kk = 0; kk < 8; kk++) {
            int dl = q4 * 8 + kk;
            sp += S.hnew[g][d0 + dl] * S.tape[0][g][n4 * 33 + dl];
        }
        sp += __shfl_down_sync(0xffffffffu, sp, 2);
        sp += __shfl_down_sync(0xffffffffu, sp, 1);
        float sphi = __shfl_down_sync(0xffffffffu, sp, 4);
        if ((t & 7) == 0) {
            int o  = n4 >> 2;
            int nl = n4 & 3;
            uint32_t dop = off_cin[g] + (uint32_t)(c * 10 + nl) * 4;
            uint32_t dow = off_cin[g] + (uint32_t)(c * 10 + 4 + nl) * 4;
            push_async64(pb[o] + dop, sp, sphi, pb[o] + offm_cin[g]);
            push_async64(pb[o] + dow, 0.f, 0.f, pb[o] + offm_cin[g]);
        }
    }
    if (isctrl && lane == 0) {
        uint32_t doff = off_cin[gme] + (uint32_t)(c * 10 + 8) * 4;
        push_async32(pb[0] + doff, 0.f, pb[0] + offm_cin[gme]);
    }

    // ---- xz prefetch (ctrl warps, step 0) ----
    float xp = 0.f, zt = 0.f;
    if (isctrl) {
        size_t row = (size_t)((2 * u + gme) * TT) * EE;
        xp = __ldcs(&g_xz[row + d0 + lane]);
        zt = __ldcs(&g_xz[row + 512 + d0 + lane]);
    }

    for (int k = 0; k < TT; k++) {
        const uint32_t par = (uint32_t)(k & 1);

        // ---- OWNER (warps 1,6): reduce combined inbox, broadcast CF ----
        if (isowner) {
            const int g = og;
            mbar_wait_cta(mbcin[g], par);
            if (lane == 0) mbar_expect_tx(mbcin[g], CIN_BYTES);
            const float* cin = &S.cin[g][0];
            const int ctaL = lane >> 2, nl = lane & 3;
            float p = cin[ctaL * 10 + nl]      + cin[(ctaL + 8) * 10 + nl];
            float w = cin[ctaL * 10 + 4 + nl]  + cin[(ctaL + 8) * 10 + 4 + nl];
            p += __shfl_xor_sync(0xffffffffu, p, 4);
            p += __shfl_xor_sync(0xffffffffu, p, 8);
            p += __shfl_xor_sync(0xffffffffu, p, 16);
            w += __shfl_xor_sync(0xffffffffu, w, 4);
            w += __shfl_xor_sync(0xffffffffu, w, 8);
            w += __shfl_xor_sync(0xffffffffu, w, 16);
            float phi = __shfl_down_sync(0xffffffffu, p, 1);
            float whi = __shfl_down_sync(0xffffffffu, w, 1);
            float qv = (lane < CPB) ? cin[lane * 10 + 8] : 0.f;
#pragma unroll
            for (int off = 16; off >= 1; off >>= 1)
                qv += __shfl_xor_sync(0xffffffffu, qv, off);
            if (lane == 0 || lane == 2) {
                uint32_t dop = off_rsf[g] + (uint32_t)(c * 4 + lane) * 4;
                uint32_t dow = off_wsf[g] + (uint32_t)(c * 4 + lane) * 4;
#pragma unroll
                for (int r = 0; r < CPB; r++) {
                    push_async64(pb[r] + dop, p, phi, pb[r] + offm_cf[g]);
                    push_async64(pb[r] + dow, w, whi, pb[r] + offm_cf[g]);
                }
            }
            if (c == 0 && lane == 0) {
#pragma unroll
                for (int r = 0; r < CPB; r++)
                    push_async64(pb[r] + off_qf[g], qv, 0.f, pb[r] + offm_cf[g]);
            }
        }

        // ---- B (ctrl warps): one CF wait -> blend -> h_k ----
        if (isctrl) {
            const int g = gme;
            const int bg = 2 * u + g;
            mbar_wait_cta(mbcf[g], par);
            if (lane == 0) mbar_expect_tx(mbcf[g], CF_BYTES);
            float wa0 = 0.f, wa1 = 0.f;
            if (k > 0) {
                float b0 = S.wsf[g][lane] * scale;
                float b1 = S.wsf[g][lane + 32] * scale;
                float mw = fmaxf(b0, b1);
#pragma unroll
                for (int off = 16; off >= 1; off >>= 1)
                    mw = fmaxf(mw, __shfl_xor_sync(0xffffffffu, mw, off));
                float f0 = __expf(b0 - mw), f1 = __expf(b1 - mw);
                float fs = f0 + f1;
#pragma unroll
                for (int off = 16; off >= 1; off >>= 1)
                    fs += __shfl_xor_sync(0xffffffffu, fs, off);
                float finv = 1.f / fs;
                wa0 = f0 * finv; wa1 = f1 * finv;
            }
            float Q  = S.qf[g][0];
            float p0 = S.rsf[g][lane];
            float p1 = S.rsf[g][lane + 32];
            float s0 = (p0 + (Q - p0) * wa0) * scale;
            float s1 = (p1 + (Q - p1) * wa1) * scale;
            float m = fmaxf(s0, s1);
#pragma unroll
            for (int off = 16; off >= 1; off >>= 1)
                m = fmaxf(m, __shfl_xor_sync(0xffffffffu, m, off));
            float e0 = __expf(s0 - m), e1 = __expf(s1 - m);
            float ss = e0 + e1;
#pragma unroll
            for (int off = 16; off >= 1; off >>= 1)
                ss += __shfl_xor_sync(0xffffffffu, ss, off);
            float inv = 1.f / ss;
            float r0 = e0 * inv, r1 = e1 * inv;
            float c0 = r0 * (1.f - wa0), c1 = r1 * (1.f - wa1);
            float sg = r0 * wa0 + r1 * wa1;
#pragma unroll
            for (int off = 16; off >= 1; off >>= 1)
                sg += __shfl_xor_sync(0xffffffffu, sg, off);
            // stage blend coeffs, read_val via broadcast LDS.128
            S.attn[g][lane]      = c0;
            S.attn[g][lane + 32] = c1;
            __syncwarp();
            const int bp = (k == 0) ? 0 : ((k - 1) & 1);
            const float* tpb = &S.tape[bp][g][0];
            float rv0 = 0.f, rv1 = 0.f, rv2 = 0.f, rv3 = 0.f;
#pragma unroll
            for (int kk = 0; kk < 16; kk++) {
                float4 a4 = *(const float4*)&S.attn[g][kk * 4];
                rv0 += a4.x * tpb[(4 * kk + 0) * 33 + lane];
                rv1 += a4.y * tpb[(4 * kk + 1) * 33 + lane];
                rv2 += a4.z * tpb[(4 * kk + 2) * 33 + lane];
                rv3 += a4.w * tpb[(4 * kk + 3) * 33 + lane];
            }
            float rv = (rv0 + rv1) + (rv2 + rv3) + sg * S.wv[g][lane];
            float pre = xp + S.acc[g][lane] + rv + S.bh[lane];
            float ex2 = __expf(2.f * pre);
            float hn  = 1.f - 2.f / (ex2 + 1.f);
            float hnhi = __shfl_down_sync(0xffffffffu, hn, 1);
            if ((lane & 1) == 0) {
                uint32_t doff = off_hn[g] + (uint32_t)(d0 + lane) * 4;
#pragma unroll
                for (int r = 0; r < CPB; r++)
                    push_async64(pb[r] + doff, hn, hnhi, pb[r] + offm_hn[g]);
            }
            float gi = zt * S.gz[lane] + rv * S.gr[lane] + hn * S.gh[lane] + S.bg[lane];
            gi = fminf(fmaxf(gi, -20.f), 20.f);
            float sig = 1.f / (1.f + __expf(-gi));
            out[(size_t)(bg * TT + k) * DD + d0 + lane] = hn * gi * sig;
            int sn = (k + 1 < TT) ? k + 1 : k;
            size_t nrow = (size_t)(bg * TT + sn) * EE;
            xp = __ldcs(&g_xz[nrow + d0 + lane]);
            zt = __ldcs(&g_xz[nrow + 512 + d0 + lane]);
        }

        // ---- D (non-ctrl warps, k>0): materialize tape from CF's WS ----
        if (dg >= 0 && k > 0) {
            mbar_wait_cta(mbcf[dg], par);
            float b0 = S.wsf[dg][lane] * scale;
            float b1 = S.wsf[dg][lane + 32] * scale;
            float mw = fmaxf(b0, b1);
#pragma unroll
            for (int off = 16; off >= 1; off >>= 1)
                mw = fmaxf(mw, __shfl_xor_sync(0xffffffffu, mw, off));
            float f0 = __expf(b0 - mw), f1 = __expf(b1 - mw);
            float fs = f0 + f1;
#pragma unroll
            for (int off = 16; off >= 1; off >>= 1)
                fs += __shfl_xor_sync(0xffffffffu, fs, off);
            float finv = 1.f / fs;
            f0 *= finv; f1 *= finv;
            const float wvl = S.wv[dg][lane];
            const float* tsrc = &S.tape[(k - 1) & 1][dg][0];
            float* tdst = &S.tape[k & 1][dg][0];
            for (int n = dr0; n < dr1; n++) {
                float vsel = (n < 32) ? f0 : f1;
                float a = __shfl_sync(0xffffffffu, vsel, n & 31);
                float told = tsrc[n * 33 + lane];
                tdst[n * 33 + lane] = told - told * a + wvl * a;
            }
        }

        // ---- C: join, matvec, combined partial pushes ----
        mbar_wait_cta(mbhn[0], par);
        mbar_wait_cta(mbhn[1], par);
        __syncthreads();   // Sa: D tape writes + B/D reads settled
        if (t == 0) {
            mbar_expect_tx(mbhn[0], HN_BYTES);
            mbar_expect_tx(mbhn[1], HN_BYTES);
        }
#pragma unroll
        for (int g = 0; g < 2; g++) {
            unsigned long long v[8];
#pragma unroll
            for (int ch = 0; ch < 4; ch++) {
                ulonglong2 tv = *(const ulonglong2*)(&S.hnew[g][ch * 128 + lane * 4]);
                v[ch * 2] = tv.x; v[ch * 2 + 1] = tv.y;
            }
            unsigned long long a2[4] = {0ull, 0ull, 0ull, 0ull};
            unsigned long long b2[4] = {0ull, 0ull, 0ull, 0ull};
#pragma unroll
            for (int i = 0; i < 4; i++)
#pragma unroll
                for (int p = 0; p < 8; p++) {
                    fma2(a2[i], wh[i][p], v[p]);
                    fma2(b2[i], ww[i][p], v[p]);
                }
            float sa[4], sb[4];
#pragma unroll
            for (int i = 0; i < 4; i++) {
                UF2 x; x.u = a2[i]; sa[i] = x.f.x + x.f.y;
                UF2 y; y.u = b2[i]; sb[i] = y.f.x + y.f.y;
            }
#pragma unroll
            for (int off = 16; off >= 1; off >>= 1) {
#pragma unroll
                for (int i = 0; i < 4; i++) {
                    sa[i] += __shfl_xor_sync(0xffffffffu, sa[i], off);
                    sb[i] += __shfl_xor_sync(0xffffffffu, sb[i], off);
                }
            }
            if (lane == 0) {
                *(float4*)&S.acc[g][cw * 4] = make_float4(sa[0], sa[1], sa[2], sa[3]);
                *(float4*)&S.wv[g][cw * 4]  = make_float4(sb[0], sb[1], sb[2], sb[3]);
            }
        }
        __syncthreads();   // S3: acc/wv available

        // fused p (h·tape) and ws (wv·tape) partials against buffer k&1
        const int bc2 = k & 1;
#pragma unroll
        for (int g = 0; g < 2; g++) {
            float sp = 0.f, sw = 0.f;
#pragma unroll
            for (int kk = 0; kk < 8; kk++) {
                int dl = q4 * 8 + kk;
                float tp = S.tape[bc2][g][n4 * 33 + dl];
                sp += S.hnew[g][d0 + dl] * tp;
                sw += S.wv[g][dl] * tp;
            }
            sp += __shfl_down_sync(0xffffffffu, sp, 2);
            sp += __shfl_down_sync(0xffffffffu, sp, 1);
            sw += __shfl_down_sync(0xffffffffu, sw, 2);
            sw += __shfl_down_sync(0xffffffffu, sw, 1);
            float sphi = __shfl_down_sync(0xffffffffu, sp, 4);
            float swhi = __shfl_down_sync(0xffffffffu, sw, 4);
            if ((t & 7) == 0) {
                int o  = n4 >> 2;
                int nl = n4 & 3;
                uint32_t dop = off_cin[g] + (uint32_t)(c * 10 + nl) * 4;
                uint32_t dow = off_cin[g] + (uint32_t)(c * 10 + 4 + nl) * 4;
                push_async64(pb[o] + dop, sp, sphi, pb[o] + offm_cin[g]);
                push_async64(pb[o] + dow, sw, swhi, pb[o] + offm_cin[g]);
            }
        }
        // q = h·wv partial (warp0 -> g0, warp5 -> g1), pushed to rank0
        if (isctrl) {
            const int g = gme;
            float qp = S.hnew[g][d0 + lane] * S.wv[g][lane];
#pragma unroll
            for (int off = 16; off >= 1; off >>= 1)
                qp += __shfl_xor_sync(0xffffffffu, qp, off);
            if (lane == 0) {
                uint32_t doff = off_cin[g] + (uint32_t)(c * 10 + 8) * 4;
                push_async32(pb[0] + doff, qp, pb[0] + offm_cin[g]);
            }
        }
    }

    // ---- post-loop: owners process final inbox (completion TT, parity 0) ----
    if (isowner) {
        const int g = og;
        mbar_wait_cta(mbcin[g], 0u);
        const float* cin = &S.cin[g][0];
        const int ctaL = lane >> 2, nl = lane & 3;
        float w = cin[ctaL * 10 + 4 + nl] + cin[(ctaL + 8) * 10 + 4 + nl];
        w += __shfl_xor_sync(0xffffffffu, w, 4);
        w += __shfl_xor_sync(0xffffffffu, w, 8);
        w += __shfl_xor_sync(0xffffffffu, w, 16);
        float whi = __shfl_down_sync(0xffffffffu, w, 1);
        if (lane == 0 || lane == 2) {
            uint32_t dow = off_wsf[g] + (uint32_t)(c * 4 + lane) * 4;
            uint32_t dop = off_rsf[g] + (uint32_t)(c * 4 + lane) * 4;
#pragma unroll
            for (int r = 0; r < CPB; r++) {
                push_async64(pb[r] + dow, w, whi, pb[r] + offm_cf[g]);
                push_async64(pb[r] + dop, 0.f, 0.f, pb[r] + offm_cf[g]);  // byte filler
            }
        }
        if (c == 0 && lane == 0) {
#pragma unroll
            for (int r = 0; r < CPB; r++)
                push_async64(pb[r] + off_qf[g], 0.f, 0.f, pb[r] + offm_cf[g]);
        }
    }

    // ---- epilogue: final write-update blended straight to out (parity 0) ----
    {
        mbar_wait_cta(mbcf[g2], 0u);
        float b0 = S.wsf[g2][lane] * scale;
        float b1 = S.wsf[g2][lane + 32] * scale;
        float mw = fmaxf(b0, b1);
#pragma unroll
        for (int off = 16; off >= 1; off >>= 1)
            mw = fmaxf(mw, __shfl_xor_sync(0xffffffffu, mw, off));
        float f0 = __expf(b0 - mw), f1 = __expf(b1 - mw);
        float fs = f0 + f1;
#pragma unroll
        for (int off = 16; off >= 1; off >>= 1)
            fs += __shfl_xor_sync(0xffffffffu, fs, off);
        float finv = 1.f / fs;
        f0 *= finv; f1 *= finv;
        const float wvl = S.wv[g2][lane];
        const float* tsrc = &S.tape[(TT - 1) & 1][g2][0];
        const int bg2 = 2 * u + g2;
#pragma unroll
        for (int r = 0; r < 16; r++) {
            int n = rbase + r;
            float vsel = (n < 32) ? f0 : f1;
            float a = __shfl_sync(0xffffffffu, vsel, n & 31);
            float told = tsrc[n * 33 + lane];
            out[(size_t)BB * TT * DD + (size_t)(bg2 * NTAPE + n) * DD + d0 + lane] =
                told - told * a + wvl * a;
        }
    }
    CLUSTER_SYNC_();
}

// ---------------- fallback scan kernel (global-memory barriers) -----------
struct ScanSmem {
    float Wh[RPC * 512];
    float Ww[RPC * 512];
    float tape[NTAPE * 33];
    float hwork[512];
    float hnew[512];
    float acc[RPC];
    float wv[RPC];
    float rv[RPC];
    float attn[NTAPE];
    float score[NTAPE];
    float bh[RPC], gz[RPC], gr[RPC], gh[RPC], bg[RPC];
};

__device__ __forceinline__ void softmax64f(const float* __restrict__ score,
                                           float* __restrict__ attn, int t)
{
    if (t < 32) {
        float a = score[t], b = score[t + 32];
        float m = fmaxf(a, b);
#pragma unroll
        for (int off = 16; off >= 1; off >>= 1)
            m = fmaxf(m, __shfl_xor_sync(0xffffffffu, m, off));
        float e0 = __expf(a - m), e1 = __expf(b - m);
        float ss = e0 + e1;
#pragma unroll
        for (int off = 16; off >= 1; off >>= 1)
            ss += __shfl_xor_sync(0xffffffffu, ss, off);
        float inv = 1.f / ss;
        attn[t] = e0 * inv;
        attn[t + 32] = e1 * inv;
    }
}

__global__ __launch_bounds__(NTHREADS, 1) void scan_kernel(
    const float* __restrict__ tape_init,
    const float* __restrict__ hwork_init,
    const float* __restrict__ W_h,
    const float* __restrict__ b_h,
    const float* __restrict__ W_write,
    const float* __restrict__ gzv,
    const float* __restrict__ grv,
    const float* __restrict__ ghv,
    const float* __restrict__ bgv,
    float* __restrict__ out)
{
    extern __shared__ char raw[];
    ScanSmem& S = *(ScanSmem*)raw;

    const int t  = threadIdx.x;
    const int b  = blockIdx.x / CPB;
    const int c  = blockIdx.x % CPB;
    const int d0 = c * RPC;
    const float scale = 0.044194173824159216f;

    for (int i = t; i < RPC * 512; i += NTHREADS) {
        S.Wh[i] = W_h[(size_t)d0 * 512 + i];
        S.Ww[i] = W_write[(size_t)d0 * 512 + i];
    }
    for (int i = t; i < NTAPE * RPC; i += NTHREADS) {
        int n = i >> 5, dl = i & 31;
        S.tape[n * 33 + dl] = tape_init[(size_t)(b * NTAPE + n) * DD + d0 + dl];
    }
    for (int i = t; i < 512; i += NTHREADS)
        S.hwork[i] = hwork_init[b * 512 + i];
    if (t < RPC) {
        S.bh[t] = b_h[d0 + t];  S.gz[t] = gzv[d0 + t];
        S.gr[t] = grv[d0 + t];  S.gh[t] = ghv[d0 + t];
        S.bg[t] = bgv[d0 + t];
    }
    __syncthreads();

    unsigned bc = 0;
    const int n4 = t >> 2, q4 = t & 3;
    const int dl8 = t >> 3, q8 = t & 7;

    for (int step = 0; step < TT; step++) {
        {
            float s = 0.f;
#pragma unroll
            for (int k = 0; k < 8; k++) {
                int dl = q4 * 8 + k;
                s += S.hwork[d0 + dl] * S.tape[n4 * 33 + dl];
            }
            s += __shfl_down_sync(0xffffffffu, s, 2);
            s += __shfl_down_sync(0xffffffffu, s, 1);
            if (q4 == 0) g_rs[(b * CPB + c) * NTAPE + n4] = s;
        }
        matvec32(S.Wh, S.hwork, S.acc);
        batch_barrier(b, (++bc) * CPB);

        if (t < NTAPE) {
            float s = 0.f;
#pragma unroll
            for (int cc = 0; cc < CPB; cc++)
                s += __ldcg(&g_rs[(b * CPB + cc) * NTAPE + t]);
            S.score[t] = s * scale;
        }
        __syncthreads();
        softmax64f(S.score, S.attn, t);
        __syncthreads();
        {
            float s = 0.f;
#pragma unroll
            for (int k = 0; k < 8; k++) {
                int n = q8 * 8 + k;
                s += S.attn[n] * S.tape[n * 33 + dl8];
            }
            s += __shfl_down_sync(0xffffffffu, s, 4);
            s += __shfl_down_sync(0xffffffffu, s, 2);
            s += __shfl_down_sync(0xffffffffu, s, 1);
            if (q8 == 0) S.rv[dl8] = s;
        }
        __syncthreads();
        if (t < RPC) {
            size_t row = (size_t)(b * TT + step) * EE;
            float xp = g_xz[row + d0 + t];
            float zt = g_xz[row + 512 + d0 + t];
            float hn = tanhf(xp + S.acc[t] + S.rv[t] + S.bh[t]);
            g_hnew[b * 512 + d0 + t] = hn;
            float gi = zt * S.gz[t] + S.rv[t] * S.gr[t] + hn * S.gh[t] + S.bg[t];
            gi = fminf(fmaxf(gi, -20.f), 20.f);
            float sig = 1.f / (1.f + __expf(-gi));
            out[(size_t)(b * TT + step) * DD + d0 + t] = hn * gi * sig;
        }
        batch_barrier(b, (++bc) * CPB);

        S.hnew[t]       = __ldcg(&g_hnew[b * 512 + t]);
        S.hnew[t + 256] = __ldcg(&g_hnew[b * 512 + t + 256]);
        __syncthreads();
        matvec32(S.Ww, S.hnew, S.wv);
        __syncthreads();
        {
            float s = 0.f;
#pragma unroll
            for (int k = 0; k < 8; k++) {
                int dl = q4 * 8 + k;
                s += S.wv[dl] * S.tape[n4 * 33 + dl];
            }
            s += __shfl_down_sync(0xffffffffu, s, 2);
            s += __shfl_down_sync(0xffffffffu, s, 1);
            if (q4 == 0) g_ws[(b * CPB + c) * NTAPE + n4] = s;
        }
        batch_barrier(b, (++bc) * CPB);

        if (t < NTAPE) {
            float s = 0.f;
#pragma unroll
            for (int cc = 0; cc < CPB; cc++)
                s += __ldcg(&g_ws[(b * CPB + cc) * NTAPE + t]);
            S.score[t] = s * scale;
        }
        __syncthreads();
        softmax64f(S.score, S.attn, t);
        __syncthreads();
        for (int e = t; e < NTAPE * RPC; e += NTHREADS) {
            int n = e >> 5, dl = e & 31;
            float a  = S.attn[n];
            float tp = S.tape[n * 33 + dl];
            S.tape[n * 33 + dl] = tp - tp * a + S.wv[dl] * a;
        }
        S.hwork[t]       = S.hnew[t];
        S.hwork[t + 256] = S.hnew[t + 256];
        __syncthreads();
    }

    for (int e = t; e < NTAPE * RPC; e += NTHREADS) {
        int n = e >> 5, dl = e & 31;
        out[(size_t)BB * TT * DD + (size_t)(b * NTAPE + n) * DD + d0 + dl] =
            S.tape[n * 33 + dl];
    }
}

// ---------------- launch ---------------------------------------------------
extern "C" void kernel_launch(void* const* d_in, const int* in_sizes, int n_in,
                              void* d_out, int out_size)
{
    const float* x         = (const float*)d_in[0];
    const float* tape_init = (const float*)d_in[1];
    const float* hwork     = (const float*)d_in[2];
    const float* W_h       = (const float*)d_in[3];
    const float* W_xz      = (const float*)d_in[4];
    const float* b_h       = (const float*)d_in[5];
    const float* W_write   = (const float*)d_in[6];
    const float* g_z       = (const float*)d_in[7];
    const float* g_r       = (const float*)d_in[8];
    const float* g_h       = (const float*)d_in[9];
    const float* b_gate    = (const float*)d_in[10];
    float* out = (float*)d_out;

    gemm_xz_kernel<<<dim3(EE / 64, (BB * TT) / 64), 256>>>(x, W_xz);

    // ---- primary: blended owner-reduce dual-batch cluster scan ----
    cudaFuncSetAttribute(scan6_kernel,
                         cudaFuncAttributeMaxDynamicSharedMemorySize,
                         (int)sizeof(CS));
    cudaError_t aerr = cudaFuncSetAttribute(
        scan6_kernel, cudaFuncAttributeNonPortableClusterSizeAllowed, 1);

    cudaLaunchConfig_t cfg = {};
    cfg.gridDim  = dim3(NCLU * CPB, 1, 1);
    cfg.blockDim = dim3(NTHREADS, 1, 1);
    cfg.dynamicSmemBytes = sizeof(CS);
    cfg.stream = 0;

    int maxClu = 0;
    cudaError_t qerr = cudaOccupancyMaxPotentialClusterSize(
        &maxClu, scan6_kernel, &cfg);

    bool launched = false;
    if (aerr == cudaSuccess && qerr == cudaSuccess && maxClu >= CPB) {
        cudaLaunchAttribute attrs[1];
        attrs[0].id = cudaLaunchAttributeClusterDimension;
        attrs[0].val.clusterDim.x = CPB;
        attrs[0].val.clusterDim.y = 1;
        attrs[0].val.clusterDim.z = 1;
        cfg.attrs = attrs;
        cfg.numAttrs = 1;
        cudaError_t lerr = cudaLaunchKernelEx(&cfg, scan6_kernel,
            tape_init, hwork, W_h, b_h, W_write, g_z, g_r, g_h, b_gate, out);
        launched = (lerr == cudaSuccess);
    }

    // ---- fallback ----
    if (!launched) {
        cudaFuncSetAttribute(scan_kernel,
                             cudaFuncAttributeMaxDynamicSharedMemorySize,
                             (int)sizeof(ScanSmem));
        init_bar_kernel<<<1, 32>>>();
        scan_kernel<<<BB * CPB, NTHREADS, sizeof(ScanSmem)>>>(
            tape_init, hwork, W_h, b_h, W_write, g_z, g_r, g_h, b_gate, out);
    }
}

// round 16
// speedup vs baseline: 1.7296x; 1.0515x over previous
#include <cuda_runtime.h>
#include <cstdint>
#include <cstddef>

// Problem constants
#define BB   8
#define TT   1024
#define DD   512
#define EE   1024
#define NTAPE 64
#define CPB  16        // CTAs per cluster
#define RPC  32        // rows / tape-cols per CTA
#define NTHREADS 256
#define NCLU  4        // clusters (2 batches each)

// ---------------- device scratch ----------
__device__ float    g_xz[(size_t)BB * TT * EE];
__device__ float    g_rs[BB * CPB * NTAPE];         // fallback exchange
__device__ float    g_ws[BB * CPB * NTAPE];
__device__ float    g_hnew[BB * DD];
__device__ unsigned g_bar[BB];

__global__ void init_bar_kernel() {
    if (threadIdx.x < BB) g_bar[threadIdx.x] = 0u;
}

// ---------------- projection GEMM (double-buffered) ----------
__global__ __launch_bounds__(256) void gemm_xz_kernel(
    const float* __restrict__ X, const float* __restrict__ W)
{
    __shared__ float As[2][16][68];
    __shared__ float Bs[2][16][68];
    const int m0 = blockIdx.y * 64;
    const int e0 = blockIdx.x * 64;
    const int tid = threadIdx.x;
    const int tx = tid & 15;
    const int ty = tid >> 4;
    const int lr = tid >> 2;
    const int lc = (tid & 3) * 4;
    float acc[4][4] = {};

    float4 xv = *(const float4*)(X + (size_t)(m0 + lr) * 512 + lc);
    float4 wv = *(const float4*)(W + (size_t)(e0 + lr) * 512 + lc);
    As[0][lc + 0][lr] = xv.x; As[0][lc + 1][lr] = xv.y;
    As[0][lc + 2][lr] = xv.z; As[0][lc + 3][lr] = xv.w;
    Bs[0][lc + 0][lr] = wv.x; Bs[0][lc + 1][lr] = wv.y;
    Bs[0][lc + 2][lr] = wv.z; Bs[0][lc + 3][lr] = wv.w;
    __syncthreads();

    for (int kt = 0; kt < 32; kt++) {
        const int cur = kt & 1;
        if (kt + 1 < 32) {
            xv = *(const float4*)(X + (size_t)(m0 + lr) * 512 + (kt + 1) * 16 + lc);
            wv = *(const float4*)(W + (size_t)(e0 + lr) * 512 + (kt + 1) * 16 + lc);
        }
#pragma unroll
        for (int kk = 0; kk < 16; kk++) {
            float4 a  = *(const float4*)&As[cur][kk][ty * 4];
            float4 bv = *(const float4*)&Bs[cur][kk][tx * 4];
            float av[4] = {a.x, a.y, a.z, a.w};
            float bw[4] = {bv.x, bv.y, bv.z, bv.w};
#pragma unroll
            for (int i = 0; i < 4; i++)
#pragma unroll
                for (int j = 0; j < 4; j++)
                    acc[i][j] += av[i] * bw[j];
        }
        if (kt + 1 < 32) {
            const int nxt = cur ^ 1;
            As[nxt][lc + 0][lr] = xv.x; As[nxt][lc + 1][lr] = xv.y;
            As[nxt][lc + 2][lr] = xv.z; As[nxt][lc + 3][lr] = xv.w;
            Bs[nxt][lc + 0][lr] = wv.x; Bs[nxt][lc + 1][lr] = wv.y;
            Bs[nxt][lc + 2][lr] = wv.z; Bs[nxt][lc + 3][lr] = wv.w;
            __syncthreads();
        }
    }
#pragma unroll
    for (int i = 0; i < 4; i++) {
        float4 o = make_float4(acc[i][0], acc[i][1], acc[i][2], acc[i][3]);
        *(float4*)(&g_xz[(size_t)(m0 + ty * 4 + i) * EE + e0 + tx * 4]) = o;
    }
}

// ---------------- helpers ------------------------------------------
__device__ __forceinline__ uint32_t smem_u32(const void* p) {
    return (uint32_t)__cvta_generic_to_shared(p);
}
__device__ __forceinline__ uint32_t mapa_u32(uint32_t local_addr, uint32_t rank) {
    uint32_t r;
    asm volatile("mapa.shared::cluster.u32 %0, %1, %2;"
                 : "=r"(r) : "r"(local_addr), "r"(rank));
    return r;
}
#define CLUSTER_SYNC_() do {                                              \
    asm volatile("barrier.cluster.arrive.aligned;" ::: "memory");         \
    asm volatile("barrier.cluster.wait.aligned;"   ::: "memory");         \
} while (0)

__device__ __forceinline__ void push_async32(uint32_t raddr, float v, uint32_t rmbar) {
    asm volatile(
        "st.async.shared::cluster.mbarrier::complete_tx::bytes.b32 [%0], %1, [%2];"
        :: "r"(raddr), "r"(__float_as_uint(v)), "r"(rmbar) : "memory");
}
__device__ __forceinline__ void push_async64(uint32_t raddr, float lo, float hi,
                                             uint32_t rmbar) {
    unsigned long long v =
        (unsigned long long)__float_as_uint(lo) |
        ((unsigned long long)__float_as_uint(hi) << 32);
    asm volatile(
        "st.async.shared::cluster.mbarrier::complete_tx::bytes.b64 [%0], %1, [%2];"
        :: "r"(raddr), "l"(v), "r"(rmbar) : "memory");
}
__device__ __forceinline__ void mbar_init(uint32_t mbar, uint32_t cnt) {
    asm volatile("mbarrier.init.shared.b64 [%0], %1;" :: "r"(mbar), "r"(cnt) : "memory");
}
__device__ __forceinline__ void mbar_expect_tx(uint32_t mbar, uint32_t bytes) {
    asm volatile("mbarrier.arrive.expect_tx.shared.b64 _, [%0], %1;"
                 :: "r"(mbar), "r"(bytes) : "memory");
}
__device__ __forceinline__ void mbar_wait_cta(uint32_t mbar, uint32_t parity) {
    asm volatile(
        "{\n\t"
        ".reg .pred P1;\n\t"
        "WAIT_LOOP_%=:\n\t"
        "mbarrier.try_wait.parity.acquire.cta.shared::cta.b64 P1, [%0], %1, 0x989680;\n\t"
        "@P1 bra.uni WAIT_DONE_%=;\n\t"
        "bra.uni WAIT_LOOP_%=;\n\t"
        "WAIT_DONE_%=:\n\t"
        "}"
        :: "r"(mbar), "r"(parity) : "memory");
}

__device__ __forceinline__ void fma2(unsigned long long& d,
                                     unsigned long long a,
                                     unsigned long long b) {
    asm("fma.rn.f32x2 %0, %1, %2, %0;" : "+l"(d) : "l"(a), "l"(b));
}
union UF2 { unsigned long long u; float2 f; };

__device__ __forceinline__ unsigned ld_acq_u32(const unsigned* p) {
    unsigned v;
    asm volatile("ld.global.acquire.gpu.u32 %0, [%1];" : "=r"(v) : "l"(p));
    return v;
}
__device__ __forceinline__ void batch_barrier(int b, unsigned target) {
    __syncthreads();
    if (threadIdx.x == 0) {
        __threadfence();
        atomicAdd(&g_bar[b], 1u);
        while (ld_acq_u32(&g_bar[b]) < target) { }
    }
    __syncthreads();
}

// (fallback-only) conflict-free smem matvec
__device__ __forceinline__ void matvec32(const float* __restrict__ sW,
                                         const float* __restrict__ vec,
                                         float* __restrict__ dest)
{
    const int lane = threadIdx.x & 31;
    const int warp = threadIdx.x >> 5;
    float4 v0 = *(const float4*)(vec + 0   + lane * 4);
    float4 v1 = *(const float4*)(vec + 128 + lane * 4);
    float4 v2 = *(const float4*)(vec + 256 + lane * 4);
    float4 v3 = *(const float4*)(vec + 384 + lane * 4);
#pragma unroll
    for (int rr = 0; rr < 4; rr++) {
        int r = warp * 4 + rr;
        const float* w = sW + r * 512;
        float4 w0 = *(const float4*)(w + 0   + lane * 4);
        float4 w1 = *(const float4*)(w + 128 + lane * 4);
        float4 w2 = *(const float4*)(w + 256 + lane * 4);
        float4 w3 = *(const float4*)(w + 384 + lane * 4);
        float s = w0.x * v0.x + w0.y * v0.y + w0.z * v0.z + w0.w * v0.w
                + w1.x * v1.x + w1.y * v1.y + w1.z * v1.z + w1.w * v1.w
                + w2.x * v2.x + w2.y * v2.y + w2.z * v2.z + w2.w * v2.w
                + w3.x * v3.x + w3.y * v3.y + w3.z * v3.z + w3.w * v3.w;
#pragma unroll
        for (int off = 16; off >= 1; off >>= 1)
            s += __shfl_down_sync(0xffffffffu, s, off);
        if (lane == 0) dest[r] = s;
    }
}

// warp-wide sum via 5-stage butterfly (all lanes get result)
__device__ __forceinline__ float warp_sum(float v) {
#pragma unroll
    for (int off = 16; off >= 1; off >>= 1)
        v += __shfl_xor_sync(0xffffffffu, v, off);
    return v;
}

// ---------------- blended owner-reduce dual-batch cluster scan --------------
// inbox layout per batch: cin[cta][0..3]=p, [4..7]=ws, [8]=q, [9]=pad (stride 10)
struct __align__(16) CS {
    float tape[2][2][NTAPE * 33];   // [buffer][batch]
    float hnew[2][512];
    float cin[2][CPB * 10];         // combined inbox
    float rsf[2][64];               // finished P
    float wsf[2][64];               // finished WS
    float qf[2][2];                 // finished Q (+pad)
    float attn[2][64];              // B staging (blend coeffs)
    float acc[2][RPC];
    float wv[2][RPC];
    float bh[RPC], gz[RPC], gr[RPC], gh[RPC], bg[RPC];
    unsigned long long mb_cin[2], mb_cf[2], mb_hn[2];
};

#define CF_BYTES  (15 * 32 + 40)       // 520: 16 owners' P+WS pairs, rank0 adds Q
#define HN_BYTES  (CPB * RPC * 4)      // 2048

__global__ __launch_bounds__(NTHREADS, 1) void scan8_kernel(
    const float* __restrict__ tape_init,
    const float* __restrict__ hwork_init,
    const float* __restrict__ W_h,
    const float* __restrict__ b_h,
    const float* __restrict__ W_write,
    const float* __restrict__ gzv,
    const float* __restrict__ grv,
    const float* __restrict__ ghv,
    const float* __restrict__ bgv,
    float* __restrict__ out)
{
    extern __shared__ char raw[];
    CS& S = *(CS*)raw;

    const int t    = threadIdx.x;
    const int lane = t & 31;
    const int cw   = t >> 5;
    const int u    = blockIdx.x >> 4;
    const int c    = blockIdx.x & 15;
    const int d0   = c * RPC;
    const float scale = 0.044194173824159216f;  // 1/sqrt(512)

    const bool isctrl = (cw == 0) || (cw == 5);
    const int  gme    = (cw == 5) ? 1 : 0;
    const bool isowner = (cw == 1) || (cw == 6);
    const int  og      = (cw == 6) ? 1 : 0;
    // D-warp assignment (non-ctrl): materialize tape into double buffer
    int dg = -1, dr0 = 0, dr1 = 0;
    if      (cw == 1) { dg = 0; dr0 = 0;  dr1 = 22; }
    else if (cw == 2) { dg = 0; dr0 = 22; dr1 = 43; }
    else if (cw == 3) { dg = 0; dr0 = 43; dr1 = 64; }
    else if (cw == 4) { dg = 1; dr0 = 0;  dr1 = 22; }
    else if (cw == 6) { dg = 1; dr0 = 22; dr1 = 43; }
    else if (cw == 7) { dg = 1; dr0 = 43; dr1 = 64; }
    // epilogue row ownership
    const int g2    = cw >> 2;
    const int rbase = (cw & 3) * 16;
    const uint32_t CIN_BYTES = (c == 0) ? (CPB * 32 + CPB * 4) : (CPB * 32);

    // ---- weights into registers ----
    unsigned long long wh[4][8], ww[4][8];
#pragma unroll
    for (int i = 0; i < 4; i++) {
        const size_t rowoff = (size_t)(d0 + cw * 4 + i) * 512;
#pragma unroll
        for (int ch = 0; ch < 4; ch++) {
            ulonglong2 a = *(const ulonglong2*)(W_h     + rowoff + ch * 128 + lane * 4);
            ulonglong2 b = *(const ulonglong2*)(W_write + rowoff + ch * 128 + lane * 4);
            wh[i][ch * 2] = a.x; wh[i][ch * 2 + 1] = a.y;
            ww[i][ch * 2] = b.x; ww[i][ch * 2 + 1] = b.y;
        }
    }

    // ---- one-time smem loads ----
#pragma unroll
    for (int g = 0; g < 2; g++) {
        int bg = 2 * u + g;
        for (int i = t; i < NTAPE * RPC; i += NTHREADS) {
            int n = i >> 5, dl = i & 31;
            S.tape[0][g][n * 33 + dl] =
                tape_init[(size_t)(bg * NTAPE + n) * DD + d0 + dl];
        }
        for (int i = t; i < 512; i += NTHREADS)
            S.hnew[g][i] = hwork_init[bg * 512 + i];
    }
    if (t < RPC) {
        S.bh[t] = b_h[d0 + t];  S.gz[t] = gzv[d0 + t];
        S.gr[t] = grv[d0 + t];  S.gh[t] = ghv[d0 + t];
        S.bg[t] = bgv[d0 + t];
        S.wv[0][t] = 0.f;  S.wv[1][t] = 0.f;
    }

    const uint32_t sbase = smem_u32(&S);
    uint32_t pb[CPB];
#pragma unroll
    for (int r = 0; r < CPB; r++) pb[r] = mapa_u32(sbase, r);

    uint32_t mbcin[2], mbcf[2], mbhn[2];
    uint32_t off_cin[2], off_rsf[2], off_wsf[2], off_qf[2], off_hn[2];
    uint32_t offm_cin[2], offm_cf[2], offm_hn[2];
#pragma unroll
    for (int g = 0; g < 2; g++) {
        mbcin[g] = smem_u32(&S.mb_cin[g]);
        mbcf[g]  = smem_u32(&S.mb_cf[g]);
        mbhn[g]  = smem_u32(&S.mb_hn[g]);
        off_cin[g] = smem_u32(&S.cin[g][0]) - sbase;
        off_rsf[g] = smem_u32(&S.rsf[g][0]) - sbase;
        off_wsf[g] = smem_u32(&S.wsf[g][0]) - sbase;
        off_qf[g]  = smem_u32(&S.qf[g][0])  - sbase;
        off_hn[g]  = smem_u32(&S.hnew[g][0]) - sbase;
        offm_cin[g] = mbcin[g] - sbase;
        offm_cf[g]  = mbcf[g]  - sbase;
        offm_hn[g]  = mbhn[g]  - sbase;
    }
    if (t == 0) {
#pragma unroll
        for (int g = 0; g < 2; g++) {
            mbar_init(mbcin[g], 1); mbar_init(mbcf[g], 1); mbar_init(mbhn[g], 1);
            mbar_expect_tx(mbcin[g], CIN_BYTES);
            mbar_expect_tx(mbcf[g],  CF_BYTES);
            mbar_expect_tx(mbhn[g],  HN_BYTES);
        }
    }
    __syncthreads();

    // ---- pre-loop: acc[g] = Wh @ h_init ----
#pragma unroll
    for (int g = 0; g < 2; g++) {
        unsigned long long v[8];
#pragma unroll
        for (int ch = 0; ch < 4; ch++) {
            ulonglong2 tv = *(const ulonglong2*)(&S.hnew[g][ch * 128 + lane * 4]);
            v[ch * 2] = tv.x; v[ch * 2 + 1] = tv.y;
        }
        unsigned long long a2[4] = {0ull, 0ull, 0ull, 0ull};
#pragma unroll
        for (int i = 0; i < 4; i++)
#pragma unroll
            for (int p = 0; p < 8; p++) fma2(a2[i], wh[i][p], v[p]);
        float sa[4];
#pragma unroll
        for (int i = 0; i < 4; i++) {
            UF2 x; x.u = a2[i];
            sa[i] = warp_sum(x.f.x + x.f.y);
        }
        if (lane == 0)
            *(float4*)&S.acc[g][cw * 4] = make_float4(sa[0], sa[1], sa[2], sa[3]);
    }
    __syncthreads();
    CLUSTER_SYNC_();

    const int n4 = t >> 2, q4 = t & 3;

    // ---- bootstrap: push p0 = h_init·tape_0, ws=0, q=0 (inbox completion 0) ----
#pragma unroll
    for (int g = 0; g < 2; g++) {
        float sp = 0.f;
#pragma unroll
        for (int kk = 0; kk < 8; kk++) {
            int dl = q4 * 8 + kk;
            sp += S.hnew[g][d0 + dl] * S.tape[0][g][n4 * 33 + dl];
        }
        sp += __shfl_down_sync(0xffffffffu, sp, 2);
        sp += __shfl_down_sync(0xffffffffu, sp, 1);
        float sphi = __shfl_down_sync(0xffffffffu, sp, 4);
        if ((t & 7) == 0) {
            int o  = n4 >> 2;
            int nl = n4 & 3;
            uint32_t dop = off_cin[g] + (uint32_t)(c * 10 + nl) * 4;
            uint32_t dow = off_cin[g] + (uint32_t)(c * 10 + 4 + nl) * 4;
            push_async64(pb[o] + dop, sp, sphi, pb[o] + offm_cin[g]);
            push_async64(pb[o] + dow, 0.f, 0.f, pb[o] + offm_cin[g]);
        }
    }
    if (isctrl && lane == 0) {
        uint32_t doff = off_cin[gme] + (uint32_t)(c * 10 + 8) * 4;
        push_async32(pb[0] + doff, 0.f, pb[0] + offm_cin[gme]);
    }

    // ---- xz prefetch (ctrl warps, step 0) ----
    float xp = 0.f, zt = 0.f;
    if (isctrl) {
        size_t row = (size_t)((2 * u + gme) * TT) * EE;
        xp = __ldcs(&g_xz[row + d0 + lane]);
        zt = __ldcs(&g_xz[row + 512 + d0 + lane]);
    }

    for (int k = 0; k < TT; k++) {
        const uint32_t par = (uint32_t)(k & 1);

        // ---- OWNER (warps 1,6): reduce combined inbox, broadcast CF ----
        if (isowner) {
            const int g = og;
            mbar_wait_cta(mbcin[g], par);
            if (lane == 0) mbar_expect_tx(mbcin[g], CIN_BYTES);
            const float* cin = &S.cin[g][0];
            const int ctaL = lane >> 2, nl = lane & 3;
            float p = cin[ctaL * 10 + nl]      + cin[(ctaL + 8) * 10 + nl];
            float w = cin[ctaL * 10 + 4 + nl]  + cin[(ctaL + 8) * 10 + 4 + nl];
            p += __shfl_xor_sync(0xffffffffu, p, 4);
            p += __shfl_xor_sync(0xffffffffu, p, 8);
            p += __shfl_xor_sync(0xffffffffu, p, 16);
            w += __shfl_xor_sync(0xffffffffu, w, 4);
            w += __shfl_xor_sync(0xffffffffu, w, 8);
            w += __shfl_xor_sync(0xffffffffu, w, 16);
            float phi = __shfl_down_sync(0xffffffffu, p, 1);
            float whi = __shfl_down_sync(0xffffffffu, w, 1);
            float qv = warp_sum((lane < CPB) ? cin[lane * 10 + 8] : 0.f);
            if (lane == 0 || lane == 2) {
                uint32_t dop = off_rsf[g] + (uint32_t)(c * 4 + lane) * 4;
                uint32_t dow = off_wsf[g] + (uint32_t)(c * 4 + lane) * 4;
#pragma unroll
                for (int r = 0; r < CPB; r++) {
                    push_async64(pb[r] + dop, p, phi, pb[r] + offm_cf[g]);
                    push_async64(pb[r] + dow, w, whi, pb[r] + offm_cf[g]);
                }
            }
            if (c == 0 && lane == 0) {
#pragma unroll
                for (int r = 0; r < CPB; r++)
                    push_async64(pb[r] + off_qf[g], qv, 0.f, pb[r] + offm_cf[g]);
            }
        }

        // ---- B (ctrl warps): one CF wait -> blend -> h_k (max-free softmax) ----
        if (isctrl) {
            const int g = gme;
            const int bg = 2 * u + g;
            mbar_wait_cta(mbcf[g], par);
            if (lane == 0) mbar_expect_tx(mbcf[g], CF_BYTES);
            float wa0 = 0.f, wa1 = 0.f;
            if (k > 0) {
                float b0 = S.wsf[g][lane] * scale;
                float b1 = S.wsf[g][lane + 32] * scale;
                float f0 = __expf(b0), f1 = __expf(b1);
                float fs = warp_sum(f0 + f1);
                float finv = 1.f / fs;
                wa0 = f0 * finv; wa1 = f1 * finv;
            }
            float Q  = S.qf[g][0];
            float p0 = S.rsf[g][lane];
            float p1 = S.rsf[g][lane + 32];
            float s0 = (p0 + (Q - p0) * wa0) * scale;
            float s1 = (p1 + (Q - p1) * wa1) * scale;
            float e0 = __expf(s0), e1 = __expf(s1);
            float ss = warp_sum(e0 + e1);
            float inv = 1.f / ss;
            float r0 = e0 * inv, r1 = e1 * inv;
            float c0 = r0 * (1.f - wa0), c1 = r1 * (1.f - wa1);
            float sg = warp_sum(r0 * wa0 + r1 * wa1);
            // stage blend coeffs, read_val via broadcast LDS.128
            S.attn[g][lane]      = c0;
            S.attn[g][lane + 32] = c1;
            __syncwarp();
            const int bp = (k == 0) ? 0 : ((k - 1) & 1);
            const float* tpb = &S.tape[bp][g][0];
            float rv0 = 0.f, rv1 = 0.f, rv2 = 0.f, rv3 = 0.f;
#pragma unroll
            for (int kk = 0; kk < 16; kk++) {
                float4 a4 = *(const float4*)&S.attn[g][kk * 4];
                rv0 += a4.x * tpb[(4 * kk + 0) * 33 + lane];
                rv1 += a4.y * tpb[(4 * kk + 1) * 33 + lane];
                rv2 += a4.z * tpb[(4 * kk + 2) * 33 + lane];
                rv3 += a4.w * tpb[(4 * kk + 3) * 33 + lane];
            }
            float rv = (rv0 + rv1) + (rv2 + rv3) + sg * S.wv[g][lane];
            float pre = xp + S.acc[g][lane] + rv + S.bh[lane];
            float ex2 = __expf(2.f * pre);
            float hn  = 1.f - 2.f / (ex2 + 1.f);
            float hnhi = __shfl_down_sync(0xffffffffu, hn, 1);
            if ((lane & 1) == 0) {
                uint32_t doff = off_hn[g] + (uint32_t)(d0 + lane) * 4;
#pragma unroll
                for (int r = 0; r < CPB; r++)
                    push_async64(pb[r] + doff, hn, hnhi, pb[r] + offm_hn[g]);
            }
            float gi = zt * S.gz[lane] + rv * S.gr[lane] + hn * S.gh[lane] + S.bg[lane];
            gi = fminf(fmaxf(gi, -20.f), 20.f);
            float sig = 1.f / (1.f + __expf(-gi));
            out[(size_t)(bg * TT + k) * DD + d0 + lane] = hn * gi * sig;
            int sn = (k + 1 < TT) ? k + 1 : k;
            size_t nrow = (size_t)(bg * TT + sn) * EE;
            xp = __ldcs(&g_xz[nrow + d0 + lane]);
            zt = __ldcs(&g_xz[nrow + 512 + d0 + lane]);
        }

        // ---- D (non-ctrl warps, k>0): materialize tape from CF's WS ----
        if (dg >= 0 && k > 0) {
            mbar_wait_cta(mbcf[dg], par);
            float b0 = S.wsf[dg][lane] * scale;
            float b1 = S.wsf[dg][lane + 32] * scale;
            float f0 = __expf(b0), f1 = __expf(b1);
            float fs = warp_sum(f0 + f1);
            float finv = 1.f / fs;
            f0 *= finv; f1 *= finv;
            const float wvl = S.wv[dg][lane];
            const float* tsrc = &S.tape[(k - 1) & 1][dg][0];
            float* tdst = &S.tape[k & 1][dg][0];
            for (int n = dr0; n < dr1; n++) {
                float vsel = (n < 32) ? f0 : f1;
                float a = __shfl_sync(0xffffffffu, vsel, n & 31);
                float told = tsrc[n * 33 + lane];
                tdst[n * 33 + lane] = told - told * a + wvl * a;
            }
        }

        // ---- C: join, matvec, combined partial pushes ----
        mbar_wait_cta(mbhn[0], par);
        mbar_wait_cta(mbhn[1], par);
        __syncthreads();   // Sa: D tape writes + B/D reads settled
        if (t == 0) {
            mbar_expect_tx(mbhn[0], HN_BYTES);
            mbar_expect_tx(mbhn[1], HN_BYTES);
        }
#pragma unroll
        for (int g = 0; g < 2; g++) {
            unsigned long long v[8];
#pragma unroll
            for (int ch = 0; ch < 4; ch++) {
                ulonglong2 tv = *(const ulonglong2*)(&S.hnew[g][ch * 128 + lane * 4]);
                v[ch * 2] = tv.x; v[ch * 2 + 1] = tv.y;
            }
            unsigned long long a2[4] = {0ull, 0ull, 0ull, 0ull};
            unsigned long long b2[4] = {0ull, 0ull, 0ull, 0ull};
#pragma unroll
            for (int i = 0; i < 4; i++)
#pragma unroll
                for (int p = 0; p < 8; p++) {
                    fma2(a2[i], wh[i][p], v[p]);
                    fma2(b2[i], ww[i][p], v[p]);
                }
            float sa[4], sb[4];
#pragma unroll
            for (int i = 0; i < 4; i++) {
                UF2 x; x.u = a2[i];
                UF2 y; y.u = b2[i];
                sa[i] = x.f.x + x.f.y;
                sb[i] = y.f.x + y.f.y;
            }
#pragma unroll
            for (int off = 16; off >= 1; off >>= 1) {
#pragma unroll
                for (int i = 0; i < 4; i++) {
                    sa[i] += __shfl_xor_sync(0xffffffffu, sa[i], off);
                    sb[i] += __shfl_xor_sync(0xffffffffu, sb[i], off);
                }
            }
            if (lane == 0) {
                *(float4*)&S.acc[g][cw * 4] = make_float4(sa[0], sa[1], sa[2], sa[3]);
                *(float4*)&S.wv[g][cw * 4]  = make_float4(sb[0], sb[1], sb[2], sb[3]);
            }
        }
        __syncthreads();   // S3: acc/wv available

        // fused p (h·tape) and ws (wv·tape) partials against buffer k&1
        const int bc2 = k & 1;
#pragma unroll
        for (int g = 0; g < 2; g++) {
            float sp = 0.f, sw = 0.f;
#pragma unroll
            for (int kk = 0; kk < 8; kk++) {
                int dl = q4 * 8 + kk;
                float tp = S.tape[bc2][g][n4 * 33 + dl];
                sp += S.hnew[g][d0 + dl] * tp;
                sw += S.wv[g][dl] * tp;
            }
            sp += __shfl_down_sync(0xffffffffu, sp, 2);
            sp += __shfl_down_sync(0xffffffffu, sp, 1);
            sw += __shfl_down_sync(0xffffffffu, sw, 2);
            sw += __shfl_down_sync(0xffffffffu, sw, 1);
            float sphi = __shfl_down_sync(0xffffffffu, sp, 4);
            float swhi = __shfl_down_sync(0xffffffffu, sw, 4);
            if ((t & 7) == 0) {
                int o  = n4 >> 2;
                int nl = n4 & 3;
                uint32_t dop = off_cin[g] + (uint32_t)(c * 10 + nl) * 4;
                uint32_t dow = off_cin[g] + (uint32_t)(c * 10 + 4 + nl) * 4;
                push_async64(pb[o] + dop, sp, sphi, pb[o] + offm_cin[g]);
                push_async64(pb[o] + dow, sw, swhi, pb[o] + offm_cin[g]);
            }
        }
        // q = h·wv partial (warp0 -> g0, warp5 -> g1), pushed to rank0
        if (isctrl) {
            const int g = gme;
            float qp = warp_sum(S.hnew[g][d0 + lane] * S.wv[g][lane]);
            if (lane == 0) {
                uint32_t doff = off_cin[g] + (uint32_t)(c * 10 + 8) * 4;
                push_async32(pb[0] + doff, qp, pb[0] + offm_cin[g]);
            }
        }
    }

    // ---- post-loop: owners process final inbox (completion TT, parity 0) ----
    if (isowner) {
        const int g = og;
        mbar_wait_cta(mbcin[g], 0u);
        const float* cin = &S.cin[g][0];
        const int ctaL = lane >> 2, nl = lane & 3;
        float w = cin[ctaL * 10 + 4 + nl] + cin[(ctaL + 8) * 10 + 4 + nl];
        w += __shfl_xor_sync(0xffffffffu, w, 4);
        w += __shfl_xor_sync(0xffffffffu, w, 8);
        w += __shfl_xor_sync(0xffffffffu, w, 16);
        float whi = __shfl_down_sync(0xffffffffu, w, 1);
        if (lane == 0 || lane == 2) {
            uint32_t dow = off_wsf[g] + (uint32_t)(c * 4 + lane) * 4;
            uint32_t dop = off_rsf[g] + (uint32_t)(c * 4 + lane) * 4;
#pragma unroll
            for (int r = 0; r < CPB; r++) {
                push_async64(pb[r] + dow, w, whi, pb[r] + offm_cf[g]);
                push_async64(pb[r] + dop, 0.f, 0.f, pb[r] + offm_cf[g]);  // byte filler
            }
        }
        if (c == 0 && lane == 0) {
#pragma unroll
            for (int r = 0; r < CPB; r++)
                push_async64(pb[r] + off_qf[g], 0.f, 0.f, pb[r] + offm_cf[g]);
        }
    }

    // ---- epilogue: final write-update blended straight to out (parity 0) ----
    {
        mbar_wait_cta(mbcf[g2], 0u);
        float b0 = S.wsf[g2][lane] * scale;
        float b1 = S.wsf[g2][lane + 32] * scale;
        float f0 = __expf(b0), f1 = __expf(b1);
        float fs = warp_sum(f0 + f1);
        float finv = 1.f / fs;
        f0 *= finv; f1 *= finv;
        const float wvl = S.wv[g2][lane];
        const float* tsrc = &S.tape[(TT - 1) & 1][g2][0];
        const int bg2 = 2 * u + g2;
#pragma unroll
        for (int r = 0; r < 16; r++) {
            int n = rbase + r;
            float vsel = (n < 32) ? f0 : f1;
            float a = __shfl_sync(0xffffffffu, vsel, n & 31);
            float told = tsrc[n * 33 + lane];
            out[(size_t)BB * TT * DD + (size_t)(bg2 * NTAPE + n) * DD + d0 + lane] =
                told - told * a + wvl * a;
        }
    }
    CLUSTER_SYNC_();
}

// ---------------- fallback scan kernel (global-memory barriers) -----------
struct ScanSmem {
    float Wh[RPC * 512];
    float Ww[RPC * 512];
    float tape[NTAPE * 33];
    float hwork[512];
    float hnew[512];
    float acc[RPC];
    float wv[RPC];
    float rv[RPC];
    float attn[NTAPE];
    float score[NTAPE];
    float bh[RPC], gz[RPC], gr[RPC], gh[RPC], bg[RPC];
};

__device__ __forceinline__ void softmax64f(const float* __restrict__ score,
                                           float* __restrict__ attn, int t)
{
    if (t < 32) {
        float a = score[t], b = score[t + 32];
        float m = fmaxf(a, b);
#pragma unroll
        for (int off = 16; off >= 1; off >>= 1)
            m = fmaxf(m, __shfl_xor_sync(0xffffffffu, m, off));
        float e0 = __expf(a - m), e1 = __expf(b - m);
        float ss = e0 + e1;
#pragma unroll
        for (int off = 16; off >= 1; off >>= 1)
            ss += __shfl_xor_sync(0xffffffffu, ss, off);
        float inv = 1.f / ss;
        attn[t] = e0 * inv;
        attn[t + 32] = e1 * inv;
    }
}

__global__ __launch_bounds__(NTHREADS, 1) void scan_kernel(
    const float* __restrict__ tape_init,
    const float* __restrict__ hwork_init,
    const float* __restrict__ W_h,
    const float* __restrict__ b_h,
    const float* __restrict__ W_write,
    const float* __restrict__ gzv,
    const float* __restrict__ grv,
    const float* __restrict__ ghv,
    const float* __restrict__ bgv,
    float* __restrict__ out)
{
    extern __shared__ char raw[];
    ScanSmem& S = *(ScanSmem*)raw;

    const int t  = threadIdx.x;
    const int b  = blockIdx.x / CPB;
    const int c  = blockIdx.x % CPB;
    const int d0 = c * RPC;
    const float scale = 0.044194173824159216f;

    for (int i = t; i < RPC * 512; i += NTHREADS) {
        S.Wh[i] = W_h[(size_t)d0 * 512 + i];
        S.Ww[i] = W_write[(size_t)d0 * 512 + i];
    }
    for (int i = t; i < NTAPE * RPC; i += NTHREADS) {
        int n = i >> 5, dl = i & 31;
        S.tape[n * 33 + dl] = tape_init[(size_t)(b * NTAPE + n) * DD + d0 + dl];
    }
    for (int i = t; i < 512; i += NTHREADS)
        S.hwork[i] = hwork_init[b * 512 + i];
    if (t < RPC) {
        S.bh[t] = b_h[d0 + t];  S.gz[t] = gzv[d0 + t];
        S.gr[t] = grv[d0 + t];  S.gh[t] = ghv[d0 + t];
        S.bg[t] = bgv[d0 + t];
    }
    __syncthreads();

    unsigned bc = 0;
    const int n4 = t >> 2, q4 = t & 3;
    const int dl8 = t >> 3, q8 = t & 7;

    for (int step = 0; step < TT; step++) {
        {
            float s = 0.f;
#pragma unroll
            for (int k = 0; k < 8; k++) {
                int dl = q4 * 8 + k;
                s += S.hwork[d0 + dl] * S.tape[n4 * 33 + dl];
            }
            s += __shfl_down_sync(0xffffffffu, s, 2);
            s += __shfl_down_sync(0xffffffffu, s, 1);
            if (q4 == 0) g_rs[(b * CPB + c) * NTAPE + n4] = s;
        }
        matvec32(S.Wh, S.hwork, S.acc);
        batch_barrier(b, (++bc) * CPB);

        if (t < NTAPE) {
            float s = 0.f;
#pragma unroll
            for (int cc = 0; cc < CPB; cc++)
                s += __ldcg(&g_rs[(b * CPB + cc) * NTAPE + t]);
            S.score[t] = s * scale;
        }
        __syncthreads();
        softmax64f(S.score, S.attn, t);
        __syncthreads();
        {
            float s = 0.f;
#pragma unroll
            for (int k = 0; k < 8; k++) {
                int n = q8 * 8 + k;
                s += S.attn[n] * S.tape[n * 33 + dl8];
            }
            s += __shfl_down_sync(0xffffffffu, s, 4);
            s += __shfl_down_sync(0xffffffffu, s, 2);
            s += __shfl_down_sync(0xffffffffu, s, 1);
            if (q8 == 0) S.rv[dl8] = s;
        }
        __syncthreads();
        if (t < RPC) {
            size_t row = (size_t)(b * TT + step) * EE;
            float xp = g_xz[row + d0 + t];
            float zt = g_xz[row + 512 + d0 + t];
            float hn = tanhf(xp + S.acc[t] + S.rv[t] + S.bh[t]);
            g_hnew[b * 512 + d0 + t] = hn;
            float gi = zt * S.gz[t] + S.rv[t] * S.gr[t] + hn * S.gh[t] + S.bg[t];
            gi = fminf(fmaxf(gi, -20.f), 20.f);
            float sig = 1.f / (1.f + __expf(-gi));
            out[(size_t)(b * TT + step) * DD + d0 + t] = hn * gi * sig;
        }
        batch_barrier(b, (++bc) * CPB);

        S.hnew[t]       = __ldcg(&g_hnew[b * 512 + t]);
        S.hnew[t + 256] = __ldcg(&g_hnew[b * 512 + t + 256]);
        __syncthreads();
        matvec32(S.Ww, S.hnew, S.wv);
        __syncthreads();
        {
            float s = 0.f;
#pragma unroll
            for (int k = 0; k < 8; k++) {
                int dl = q4 * 8 + k;
                s += S.wv[dl] * S.tape[n4 * 33 + dl];
            }
            s += __shfl_down_sync(0xffffffffu, s, 2);
            s += __shfl_down_sync(0xffffffffu, s, 1);
            if (q4 == 0) g_ws[(b * CPB + c) * NTAPE + n4] = s;
        }
        batch_barrier(b, (++bc) * CPB);

        if (t < NTAPE) {
            float s = 0.f;
#pragma unroll
            for (int cc = 0; cc < CPB; cc++)
                s += __ldcg(&g_ws[(b * CPB + cc) * NTAPE + t]);
            S.score[t] = s * scale;
        }
        __syncthreads();
        softmax64f(S.score, S.attn, t);
        __syncthreads();
        for (int e = t; e < NTAPE * RPC; e += NTHREADS) {
            int n = e >> 5, dl = e & 31;
            float a  = S.attn[n];
            float tp = S.tape[n * 33 + dl];
            S.tape[n * 33 + dl] = tp - tp * a + S.wv[dl] * a;
        }
        S.hwork[t]       = S.hnew[t];
        S.hwork[t + 256] = S.hnew[t + 256];
        __syncthreads();
    }

    for (int e = t; e < NTAPE * RPC; e += NTHREADS) {
        int n = e >> 5, dl = e & 31;
        out[(size_t)BB * TT * DD + (size_t)(b * NTAPE + n) * DD + d0 + dl] =
            S.tape[n * 33 + dl];
    }
}

// ---------------- launch ---------------------------------------------------
extern "C" void kernel_launch(void* const* d_in, const int* in_sizes, int n_in,
                              void* d_out, int out_size)
{
    const float* x         = (const float*)d_in[0];
    const float* tape_init = (const float*)d_in[1];
    const float* hwork     = (const float*)d_in[2];
    const float* W_h       = (const float*)d_in[3];
    const float* W_xz      = (const float*)d_in[4];
    const float* b_h       = (const float*)d_in[5];
    const float* W_write   = (const float*)d_in[6];
    const float* g_z       = (const float*)d_in[7];
    const float* g_r       = (const float*)d_in[8];
    const float* g_h       = (const float*)d_in[9];
    const float* b_gate    = (const float*)d_in[10];
    float* out = (float*)d_out;

    gemm_xz_kernel<<<dim3(EE / 64, (BB * TT) / 64), 256>>>(x, W_xz);

    // ---- primary: blended owner-reduce dual-batch cluster scan ----
    cudaFuncSetAttribute(scan8_kernel,
                         cudaFuncAttributeMaxDynamicSharedMemorySize,
                         (int)sizeof(CS));
    cudaError_t aerr = cudaFuncSetAttribute(
        scan8_kernel, cudaFuncAttributeNonPortableClusterSizeAllowed, 1);

    cudaLaunchConfig_t cfg = {};
    cfg.gridDim  = dim3(NCLU * CPB, 1, 1);
    cfg.blockDim = dim3(NTHREADS, 1, 1);
    cfg.dynamicSmemBytes = sizeof(CS);
    cfg.stream = 0;

    int maxClu = 0;
    cudaError_t qerr = cudaOccupancyMaxPotentialClusterSize(
        &maxClu, scan8_kernel, &cfg);

    bool launched = false;
    if (aerr == cudaSuccess && qerr == cudaSuccess && maxClu >= CPB) {
        cudaLaunchAttribute attrs[1];
        attrs[0].id = cudaLaunchAttributeClusterDimension;
        attrs[0].val.clusterDim.x = CPB;
        attrs[0].val.clusterDim.y = 1;
        attrs[0].val.clusterDim.z = 1;
        cfg.attrs = attrs;
        cfg.numAttrs = 1;
        cudaError_t lerr = cudaLaunchKernelEx(&cfg, scan8_kernel,
            tape_init, hwork, W_h, b_h, W_write, g_z, g_r, g_h, b_gate, out);
        launched = (lerr == cudaSuccess);
    }

    // ---- fallback ----
    if (!launched) {
        cudaFuncSetAttribute(scan_kernel,
                             cudaFuncAttributeMaxDynamicSharedMemorySize,
                             (int)sizeof(ScanSmem));
        init_bar_kernel<<<1, 32>>>();
        scan_kernel<<<BB * CPB, NTHREADS, sizeof(ScanSmem)>>>(
            tape_init, hwork, W_h, b_h, W_write, g_z, g_r, g_h, b_gate, out);
    }
}

// round 17
// speedup vs baseline: 1.8253x; 1.0554x over previous
#include <cuda_runtime.h>
#include <cstdint>
#include <cstddef>

// Problem constants
#define BB   8
#define TT   1024
#define DD   512
#define EE   1024
#define NTAPE 64
#define CPB  16        // CTAs per cluster
#define RPC  32        // rows / tape-cols per CTA
#define NTHREADS 256
#define NCLU  4        // clusters (2 batches each)

// ---------------- device scratch ----------
__device__ float    g_xz[(size_t)BB * TT * EE];
__device__ float    g_rs[BB * CPB * NTAPE];         // fallback exchange
__device__ float    g_ws[BB * CPB * NTAPE];
__device__ float    g_hnew[BB * DD];
__device__ unsigned g_bar[BB];

__global__ void init_bar_kernel() {
    if (threadIdx.x < BB) g_bar[threadIdx.x] = 0u;
}

// ---------------- projection GEMM (double-buffered) ----------
__global__ __launch_bounds__(256) void gemm_xz_kernel(
    const float* __restrict__ X, const float* __restrict__ W)
{
    __shared__ float As[2][16][68];
    __shared__ float Bs[2][16][68];
    const int m0 = blockIdx.y * 64;
    const int e0 = blockIdx.x * 64;
    const int tid = threadIdx.x;
    const int tx = tid & 15;
    const int ty = tid >> 4;
    const int lr = tid >> 2;
    const int lc = (tid & 3) * 4;
    float acc[4][4] = {};

    float4 xv = *(const float4*)(X + (size_t)(m0 + lr) * 512 + lc);
    float4 wv = *(const float4*)(W + (size_t)(e0 + lr) * 512 + lc);
    As[0][lc + 0][lr] = xv.x; As[0][lc + 1][lr] = xv.y;
    As[0][lc + 2][lr] = xv.z; As[0][lc + 3][lr] = xv.w;
    Bs[0][lc + 0][lr] = wv.x; Bs[0][lc + 1][lr] = wv.y;
    Bs[0][lc + 2][lr] = wv.z; Bs[0][lc + 3][lr] = wv.w;
    __syncthreads();

    for (int kt = 0; kt < 32; kt++) {
        const int cur = kt & 1;
        if (kt + 1 < 32) {
            xv = *(const float4*)(X + (size_t)(m0 + lr) * 512 + (kt + 1) * 16 + lc);
            wv = *(const float4*)(W + (size_t)(e0 + lr) * 512 + (kt + 1) * 16 + lc);
        }
#pragma unroll
        for (int kk = 0; kk < 16; kk++) {
            float4 a  = *(const float4*)&As[cur][kk][ty * 4];
            float4 bv = *(const float4*)&Bs[cur][kk][tx * 4];
            float av[4] = {a.x, a.y, a.z, a.w};
            float bw[4] = {bv.x, bv.y, bv.z, bv.w};
#pragma unroll
            for (int i = 0; i < 4; i++)
#pragma unroll
                for (int j = 0; j < 4; j++)
                    acc[i][j] += av[i] * bw[j];
        }
        if (kt + 1 < 32) {
            const int nxt = cur ^ 1;
            As[nxt][lc + 0][lr] = xv.x; As[nxt][lc + 1][lr] = xv.y;
            As[nxt][lc + 2][lr] = xv.z; As[nxt][lc + 3][lr] = xv.w;
            Bs[nxt][lc + 0][lr] = wv.x; Bs[nxt][lc + 1][lr] = wv.y;
            Bs[nxt][lc + 2][lr] = wv.z; Bs[nxt][lc + 3][lr] = wv.w;
            __syncthreads();
        }
    }
#pragma unroll
    for (int i = 0; i < 4; i++) {
        float4 o = make_float4(acc[i][0], acc[i][1], acc[i][2], acc[i][3]);
        *(float4*)(&g_xz[(size_t)(m0 + ty * 4 + i) * EE + e0 + tx * 4]) = o;
    }
}

// ---------------- helpers ------------------------------------------
__device__ __forceinline__ uint32_t smem_u32(const void* p) {
    return (uint32_t)__cvta_generic_to_shared(p);
}
__device__ __forceinline__ uint32_t mapa_u32(uint32_t local_addr, uint32_t rank) {
    uint32_t r;
    asm volatile("mapa.shared::cluster.u32 %0, %1, %2;"
                 : "=r"(r) : "r"(local_addr), "r"(rank));
    return r;
}
#define CLUSTER_SYNC_() do {                                              \
    asm volatile("barrier.cluster.arrive.aligned;" ::: "memory");         \
    asm volatile("barrier.cluster.wait.aligned;"   ::: "memory");         \
} while (0)

__device__ __forceinline__ void push_async32(uint32_t raddr, float v, uint32_t rmbar) {
    asm volatile(
        "st.async.shared::cluster.mbarrier::complete_tx::bytes.b32 [%0], %1, [%2];"
        :: "r"(raddr), "r"(__float_as_uint(v)), "r"(rmbar) : "memory");
}
__device__ __forceinline__ void push_async64(uint32_t raddr, float lo, float hi,
                                             uint32_t rmbar) {
    unsigned long long v =
        (unsigned long long)__float_as_uint(lo) |
        ((unsigned long long)__float_as_uint(hi) << 32);
    asm volatile(
        "st.async.shared::cluster.mbarrier::complete_tx::bytes.b64 [%0], %1, [%2];"
        :: "r"(raddr), "l"(v), "r"(rmbar) : "memory");
}
__device__ __forceinline__ void mbar_init(uint32_t mbar, uint32_t cnt) {
    asm volatile("mbarrier.init.shared.b64 [%0], %1;" :: "r"(mbar), "r"(cnt) : "memory");
}
__device__ __forceinline__ void mbar_expect_tx(uint32_t mbar, uint32_t bytes) {
    asm volatile("mbarrier.arrive.expect_tx.shared.b64 _, [%0], %1;"
                 :: "r"(mbar), "r"(bytes) : "memory");
}
__device__ __forceinline__ void mbar_wait_cta(uint32_t mbar, uint32_t parity) {
    asm volatile(
        "{\n\t"
        ".reg .pred P1;\n\t"
        "WAIT_LOOP_%=:\n\t"
        "mbarrier.try_wait.parity.acquire.cta.shared::cta.b64 P1, [%0], %1, 0x989680;\n\t"
        "@P1 bra.uni WAIT_DONE_%=;\n\t"
        "bra.uni WAIT_LOOP_%=;\n\t"
        "WAIT_DONE_%=:\n\t"
        "}"
        :: "r"(mbar), "r"(parity) : "memory");
}

__device__ __forceinline__ void fma2(unsigned long long& d,
                                     unsigned long long a,
                                     unsigned long long b) {
    asm("fma.rn.f32x2 %0, %1, %2, %0;" : "+l"(d) : "l"(a), "l"(b));
}
union UF2 { unsigned long long u; float2 f; };

__device__ __forceinline__ unsigned ld_acq_u32(const unsigned* p) {
    unsigned v;
    asm volatile("ld.global.acquire.gpu.u32 %0, [%1];" : "=r"(v) : "l"(p));
    return v;
}
__device__ __forceinline__ void batch_barrier(int b, unsigned target) {
    __syncthreads();
    if (threadIdx.x == 0) {
        __threadfence();
        atomicAdd(&g_bar[b], 1u);
        while (ld_acq_u32(&g_bar[b]) < target) { }
    }
    __syncthreads();
}

// (fallback-only) conflict-free smem matvec
__device__ __forceinline__ void matvec32(const float* __restrict__ sW,
                                         const float* __restrict__ vec,
                                         float* __restrict__ dest)
{
    const int lane = threadIdx.x & 31;
    const int warp = threadIdx.x >> 5;
    float4 v0 = *(const float4*)(vec + 0   + lane * 4);
    float4 v1 = *(const float4*)(vec + 128 + lane * 4);
    float4 v2 = *(const float4*)(vec + 256 + lane * 4);
    float4 v3 = *(const float4*)(vec + 384 + lane * 4);
#pragma unroll
    for (int rr = 0; rr < 4; rr++) {
        int r = warp * 4 + rr;
        const float* w = sW + r * 512;
        float4 w0 = *(const float4*)(w + 0   + lane * 4);
        float4 w1 = *(const float4*)(w + 128 + lane * 4);
        float4 w2 = *(const float4*)(w + 256 + lane * 4);
        float4 w3 = *(const float4*)(w + 384 + lane * 4);
        float s = w0.x * v0.x + w0.y * v0.y + w0.z * v0.z + w0.w * v0.w
                + w1.x * v1.x + w1.y * v1.y + w1.z * v1.z + w1.w * v1.w
                + w2.x * v2.x + w2.y * v2.y + w2.z * v2.z + w2.w * v2.w
                + w3.x * v3.x + w3.y * v3.y + w3.z * v3.z + w3.w * v3.w;
#pragma unroll
        for (int off = 16; off >= 1; off >>= 1)
            s += __shfl_down_sync(0xffffffffu, s, off);
        if (lane == 0) dest[r] = s;
    }
}

// warp-wide sum via 5-stage butterfly (all lanes get result)
__device__ __forceinline__ float warp_sum(float v) {
#pragma unroll
    for (int off = 16; off >= 1; off >>= 1)
        v += __shfl_xor_sync(0xffffffffu, v, off);
    return v;
}

// ---------------- blended owner-reduce dual-batch cluster scan --------------
// inbox layout per batch: cin[cta][0..3]=p, [4..7]=ws, [8]=q, [9]=pad (stride 10)
struct __align__(16) CS {
    float tape[2][2][NTAPE * 33];   // [buffer][batch]
    float hnew[2][512];
    float cin[2][CPB * 10];         // combined inbox
    float rsf[2][64];               // finished P
    float wsf[2][64];               // finished WS
    float qf[2][2];                 // finished Q (+pad)
    float attn[2][64];              // B staging (blend coeffs)
    float acc[2][RPC];
    float wv[2][RPC];
    float bh[RPC], gz[RPC], gr[RPC], gh[RPC], bg[RPC];
    unsigned long long mb_cin[2], mb_cf[2], mb_hn[2];
};

#define CF_BYTES  (15 * 32 + 40)       // 520: 16 owners' P+WS pairs, rank0 adds Q
#define HN_BYTES  (CPB * RPC * 4)      // 2048

__global__ __launch_bounds__(NTHREADS, 1) void scan9_kernel(
    const float* __restrict__ tape_init,
    const float* __restrict__ hwork_init,
    const float* __restrict__ W_h,
    const float* __restrict__ b_h,
    const float* __restrict__ W_write,
    const float* __restrict__ gzv,
    const float* __restrict__ grv,
    const float* __restrict__ ghv,
    const float* __restrict__ bgv,
    float* __restrict__ out)
{
    extern __shared__ char raw[];
    CS& S = *(CS*)raw;

    const int t    = threadIdx.x;
    const int lane = t & 31;
    const int cw   = t >> 5;
    const int u    = blockIdx.x >> 4;
    const int c    = blockIdx.x & 15;
    const int d0   = c * RPC;
    const float scale = 0.044194173824159216f;  // 1/sqrt(512)

    const bool isctrl = (cw == 0) || (cw == 5);
    const int  gme    = (cw == 5) ? 1 : 0;
    const bool isowner = (cw == 1) || (cw == 6);
    const int  og      = (cw == 6) ? 1 : 0;
    // D-warp assignment (non-ctrl): materialize tape into double buffer
    int dg = -1, dr0 = 0, dr1 = 0;
    if      (cw == 1) { dg = 0; dr0 = 0;  dr1 = 22; }
    else if (cw == 2) { dg = 0; dr0 = 22; dr1 = 43; }
    else if (cw == 3) { dg = 0; dr0 = 43; dr1 = 64; }
    else if (cw == 4) { dg = 1; dr0 = 0;  dr1 = 22; }
    else if (cw == 6) { dg = 1; dr0 = 22; dr1 = 43; }
    else if (cw == 7) { dg = 1; dr0 = 43; dr1 = 64; }
    // epilogue row ownership
    const int g2    = cw >> 2;
    const int rbase = (cw & 3) * 16;
    const uint32_t CIN_BYTES = (c == 0) ? (CPB * 32 + CPB * 4) : (CPB * 32);

    // ---- weights into registers ----
    unsigned long long wh[4][8], ww[4][8];
#pragma unroll
    for (int i = 0; i < 4; i++) {
        const size_t rowoff = (size_t)(d0 + cw * 4 + i) * 512;
#pragma unroll
        for (int ch = 0; ch < 4; ch++) {
            ulonglong2 a = *(const ulonglong2*)(W_h     + rowoff + ch * 128 + lane * 4);
            ulonglong2 b = *(const ulonglong2*)(W_write + rowoff + ch * 128 + lane * 4);
            wh[i][ch * 2] = a.x; wh[i][ch * 2 + 1] = a.y;
            ww[i][ch * 2] = b.x; ww[i][ch * 2 + 1] = b.y;
        }
    }

    // ---- one-time smem loads ----
#pragma unroll
    for (int g = 0; g < 2; g++) {
        int bg = 2 * u + g;
        for (int i = t; i < NTAPE * RPC; i += NTHREADS) {
            int n = i >> 5, dl = i & 31;
            S.tape[0][g][n * 33 + dl] =
                tape_init[(size_t)(bg * NTAPE + n) * DD + d0 + dl];
        }
        for (int i = t; i < 512; i += NTHREADS)
            S.hnew[g][i] = hwork_init[bg * 512 + i];
    }
    if (t < RPC) {
        S.bh[t] = b_h[d0 + t];  S.gz[t] = gzv[d0 + t];
        S.gr[t] = grv[d0 + t];  S.gh[t] = ghv[d0 + t];
        S.bg[t] = bgv[d0 + t];
        S.wv[0][t] = 0.f;  S.wv[1][t] = 0.f;
    }

    const uint32_t sbase = smem_u32(&S);
    uint32_t pb[CPB];
#pragma unroll
    for (int r = 0; r < CPB; r++) pb[r] = mapa_u32(sbase, r);

    uint32_t mbcin[2], mbcf[2], mbhn[2];
    uint32_t off_cin[2], off_rsf[2], off_wsf[2], off_qf[2], off_hn[2];
    uint32_t offm_cin[2], offm_cf[2], offm_hn[2];
#pragma unroll
    for (int g = 0; g < 2; g++) {
        mbcin[g] = smem_u32(&S.mb_cin[g]);
        mbcf[g]  = smem_u32(&S.mb_cf[g]);
        mbhn[g]  = smem_u32(&S.mb_hn[g]);
        off_cin[g] = smem_u32(&S.cin[g][0]) - sbase;
        off_rsf[g] = smem_u32(&S.rsf[g][0]) - sbase;
        off_wsf[g] = smem_u32(&S.wsf[g][0]) - sbase;
        off_qf[g]  = smem_u32(&S.qf[g][0])  - sbase;
        off_hn[g]  = smem_u32(&S.hnew[g][0]) - sbase;
        offm_cin[g] = mbcin[g] - sbase;
        offm_cf[g]  = mbcf[g]  - sbase;
        offm_hn[g]  = mbhn[g]  - sbase;
    }
    if (t == 0) {
#pragma unroll
        for (int g = 0; g < 2; g++) {
            mbar_init(mbcin[g], 1); mbar_init(mbcf[g], 1); mbar_init(mbhn[g], 1);
            mbar_expect_tx(mbcin[g], CIN_BYTES);
            mbar_expect_tx(mbcf[g],  CF_BYTES);
            mbar_expect_tx(mbhn[g],  HN_BYTES);
        }
    }
    __syncthreads();

    // ---- pre-loop: acc[g] = Wh @ h_init ----
#pragma unroll
    for (int g = 0; g < 2; g++) {
        unsigned long long v[8];
#pragma unroll
        for (int ch = 0; ch < 4; ch++) {
            ulonglong2 tv = *(const ulonglong2*)(&S.hnew[g][ch * 128 + lane * 4]);
            v[ch * 2] = tv.x; v[ch * 2 + 1] = tv.y;
        }
        unsigned long long a2[4] = {0ull, 0ull, 0ull, 0ull};
#pragma unroll
        for (int i = 0; i < 4; i++)
#pragma unroll
            for (int p = 0; p < 8; p++) fma2(a2[i], wh[i][p], v[p]);
        float sa[4];
#pragma unroll
        for (int i = 0; i < 4; i++) {
            UF2 x; x.u = a2[i];
            sa[i] = warp_sum(x.f.x + x.f.y);
        }
        if (lane == 0)
            *(float4*)&S.acc[g][cw * 4] = make_float4(sa[0], sa[1], sa[2], sa[3]);
    }
    __syncthreads();
    CLUSTER_SYNC_();

    const int n4 = t >> 2, q4 = t & 3;

    // ---- bootstrap: push p0 = h_init·tape_0, ws=0, q=0 (inbox completion 0) ----
#pragma unroll
    for (int g = 0; g < 2; g++) {
        float sp = 0.f;
#pragma unroll
        for (int kk = 0; kk < 8; kk++) {
            int dl = q4 * 8 + kk;
            sp += S.hnew[g][d0 + dl] * S.tape[0][g][n4 * 33 + dl];
        }
        sp += __shfl_down_sync(0xffffffffu, sp, 2);
        sp += __shfl_down_sync(0xffffffffu, sp, 1);
        float sphi = __shfl_down_sync(0xffffffffu, sp, 4);
        if ((t & 7) == 0) {
            int o  = n4 >> 2;
            int nl = n4 & 3;
            uint32_t dop = off_cin[g] + (uint32_t)(c * 10 + nl) * 4;
            uint32_t dow = off_cin[g] + (uint32_t)(c * 10 + 4 + nl) * 4;
            push_async64(pb[o] + dop, sp, sphi, pb[o] + offm_cin[g]);
            push_async64(pb[o] + dow, 0.f, 0.f, pb[o] + offm_cin[g]);
        }
    }
    if (isctrl && lane == 0) {
        uint32_t doff = off_cin[gme] + (uint32_t)(c * 10 + 8) * 4;
        push_async32(pb[0] + doff, 0.f, pb[0] + offm_cin[gme]);
    }

    // ---- xz prefetch (ctrl warps, step 0) ----
    float xp = 0.f, zt = 0.f;
    if (isctrl) {
        size_t row = (size_t)((2 * u + gme) * TT) * EE;
        xp = __ldcs(&g_xz[row + d0 + lane]);
        zt = __ldcs(&g_xz[row + 512 + d0 + lane]);
    }

    for (int k = 0; k < TT; k++) {
        const uint32_t par = (uint32_t)(k & 1);

        // ---- OWNER (warps 1,6): reduce combined inbox, distributed broadcast ----
        if (isowner) {
            const int g = og;
            mbar_wait_cta(mbcin[g], par);
            if (lane == 0) mbar_expect_tx(mbcin[g], CIN_BYTES);
            const float* cin = &S.cin[g][0];
            const int ctaL = lane >> 2, nl = lane & 3;
            float p = cin[ctaL * 10 + nl]      + cin[(ctaL + 8) * 10 + nl];
            float w = cin[ctaL * 10 + 4 + nl]  + cin[(ctaL + 8) * 10 + 4 + nl];
            p += __shfl_xor_sync(0xffffffffu, p, 4);
            p += __shfl_xor_sync(0xffffffffu, p, 8);
            p += __shfl_xor_sync(0xffffffffu, p, 16);
            w += __shfl_xor_sync(0xffffffffu, w, 4);
            w += __shfl_xor_sync(0xffffffffu, w, 8);
            w += __shfl_xor_sync(0xffffffffu, w, 16);
            float phi = __shfl_down_sync(0xffffffffu, p, 1);
            float whi = __shfl_down_sync(0xffffffffu, w, 1);
            float qv = warp_sum((lane < CPB) ? cin[lane * 10 + 8] : 0.f);
            // distributed broadcast: 16 even lanes, 4 ranks each.
            // sub=lane&7 selects kind (0:P-nl0, 2:P-nl2, 4:W-nl0, 6:W-nl2);
            // grp=lane>>3 selects the 4-rank chunk; value valid on every lane
            // because the xor-reduce left identical sums on all lanes of equal nl.
            const int sub = lane & 7, grp = lane >> 3;
            const bool isP = (sub < 4);
            float lo = isP ? p : w;
            float hi = isP ? phi : whi;
            uint32_t dst = (isP ? off_rsf[g] : off_wsf[g])
                         + (uint32_t)(c * 4 + nl) * 4;
            if ((lane & 1) == 0) {
#pragma unroll
                for (int i = 0; i < 4; i++) {
                    int r = grp * 4 + i;
                    push_async64(pb[r] + dst, lo, hi, pb[r] + offm_cf[g]);
                }
            }
            if (c == 0 && lane < CPB)
                push_async64(pb[lane] + off_qf[g], qv, 0.f, pb[lane] + offm_cf[g]);
        }

        // ---- B (ctrl warps): one CF wait -> blend -> h_k (max-free softmax) ----
        if (isctrl) {
            const int g = gme;
            const int bg = 2 * u + g;
            mbar_wait_cta(mbcf[g], par);
            if (lane == 0) mbar_expect_tx(mbcf[g], CF_BYTES);
            float wa0 = 0.f, wa1 = 0.f;
            if (k > 0) {
                float b0 = S.wsf[g][lane] * scale;
                float b1 = S.wsf[g][lane + 32] * scale;
                float f0 = __expf(b0), f1 = __expf(b1);
                float fs = warp_sum(f0 + f1);
                float finv = 1.f / fs;
                wa0 = f0 * finv; wa1 = f1 * finv;
            }
            float Q  = S.qf[g][0];
            float p0 = S.rsf[g][lane];
            float p1 = S.rsf[g][lane + 32];
            float s0 = (p0 + (Q - p0) * wa0) * scale;
            float s1 = (p1 + (Q - p1) * wa1) * scale;
            float e0 = __expf(s0), e1 = __expf(s1);
            // two independent butterflies, interleaved for ILP
            float ssv = e0 + e1;
            float sgv = e0 * wa0 + e1 * wa1;
#pragma unroll
            for (int off = 16; off >= 1; off >>= 1) {
                ssv += __shfl_xor_sync(0xffffffffu, ssv, off);
                sgv += __shfl_xor_sync(0xffffffffu, sgv, off);
            }
            float inv = 1.f / ssv;
            float r0 = e0 * inv, r1 = e1 * inv;
            float c0 = r0 * (1.f - wa0), c1 = r1 * (1.f - wa1);
            float sg = sgv * inv;
            // stage blend coeffs, read_val via broadcast LDS.128
            S.attn[g][lane]      = c0;
            S.attn[g][lane + 32] = c1;
            __syncwarp();
            const int bp = (k == 0) ? 0 : ((k - 1) & 1);
            const float* tpb = &S.tape[bp][g][0];
            float rv0 = 0.f, rv1 = 0.f, rv2 = 0.f, rv3 = 0.f;
#pragma unroll
            for (int kk = 0; kk < 16; kk++) {
                float4 a4 = *(const float4*)&S.attn[g][kk * 4];
                rv0 += a4.x * tpb[(4 * kk + 0) * 33 + lane];
                rv1 += a4.y * tpb[(4 * kk + 1) * 33 + lane];
                rv2 += a4.z * tpb[(4 * kk + 2) * 33 + lane];
                rv3 += a4.w * tpb[(4 * kk + 3) * 33 + lane];
            }
            float rv = (rv0 + rv1) + (rv2 + rv3) + sg * S.wv[g][lane];
            float pre = xp + S.acc[g][lane] + rv + S.bh[lane];
            float ex2 = __expf(2.f * pre);
            float hn  = 1.f - 2.f / (ex2 + 1.f);
            float hnhi = __shfl_down_sync(0xffffffffu, hn, 1);
            if ((lane & 1) == 0) {
                uint32_t doff = off_hn[g] + (uint32_t)(d0 + lane) * 4;
#pragma unroll
                for (int r = 0; r < CPB; r++)
                    push_async64(pb[r] + doff, hn, hnhi, pb[r] + offm_hn[g]);
            }
            float gi = zt * S.gz[lane] + rv * S.gr[lane] + hn * S.gh[lane] + S.bg[lane];
            gi = fminf(fmaxf(gi, -20.f), 20.f);
            float sig = 1.f / (1.f + __expf(-gi));
            out[(size_t)(bg * TT + k) * DD + d0 + lane] = hn * gi * sig;
            int sn = (k + 1 < TT) ? k + 1 : k;
            size_t nrow = (size_t)(bg * TT + sn) * EE;
            xp = __ldcs(&g_xz[nrow + d0 + lane]);
            zt = __ldcs(&g_xz[nrow + 512 + d0 + lane]);
        }

        // ---- D (non-ctrl warps, k>0): materialize tape from CF's WS ----
        if (dg >= 0 && k > 0) {
            mbar_wait_cta(mbcf[dg], par);
            float b0 = S.wsf[dg][lane] * scale;
            float b1 = S.wsf[dg][lane + 32] * scale;
            float f0 = __expf(b0), f1 = __expf(b1);
            float fs = warp_sum(f0 + f1);
            float finv = 1.f / fs;
            f0 *= finv; f1 *= finv;
            const float wvl = S.wv[dg][lane];
            const float* tsrc = &S.tape[(k - 1) & 1][dg][0];
            float* tdst = &S.tape[k & 1][dg][0];
            for (int n = dr0; n < dr1; n++) {
                float vsel = (n < 32) ? f0 : f1;
                float a = __shfl_sync(0xffffffffu, vsel, n & 31);
                float told = tsrc[n * 33 + lane];
                tdst[n * 33 + lane] = told - told * a + wvl * a;
            }
        }

        // ---- C: join, matvec, combined partial pushes ----
        mbar_wait_cta(mbhn[0], par);
        mbar_wait_cta(mbhn[1], par);
        __syncthreads();   // Sa: D tape writes + B/D reads settled
        if (t == 0) {
            mbar_expect_tx(mbhn[0], HN_BYTES);
            mbar_expect_tx(mbhn[1], HN_BYTES);
        }
#pragma unroll
        for (int g = 0; g < 2; g++) {
            unsigned long long v[8];
#pragma unroll
            for (int ch = 0; ch < 4; ch++) {
                ulonglong2 tv = *(const ulonglong2*)(&S.hnew[g][ch * 128 + lane * 4]);
                v[ch * 2] = tv.x; v[ch * 2 + 1] = tv.y;
            }
            unsigned long long a2[4] = {0ull, 0ull, 0ull, 0ull};
            unsigned long long b2[4] = {0ull, 0ull, 0ull, 0ull};
#pragma unroll
            for (int i = 0; i < 4; i++)
#pragma unroll
                for (int p = 0; p < 8; p++) {
                    fma2(a2[i], wh[i][p], v[p]);
                    fma2(b2[i], ww[i][p], v[p]);
                }
            float sa[4], sb[4];
#pragma unroll
            for (int i = 0; i < 4; i++) {
                UF2 x; x.u = a2[i];
                UF2 y; y.u = b2[i];
                sa[i] = x.f.x + x.f.y;
                sb[i] = y.f.x + y.f.y;
            }
#pragma unroll
            for (int off = 16; off >= 1; off >>= 1) {
#pragma unroll
                for (int i = 0; i < 4; i++) {
                    sa[i] += __shfl_xor_sync(0xffffffffu, sa[i], off);
                    sb[i] += __shfl_xor_sync(0xffffffffu, sb[i], off);
                }
            }
            if (lane == 0) {
                *(float4*)&S.acc[g][cw * 4] = make_float4(sa[0], sa[1], sa[2], sa[3]);
                *(float4*)&S.wv[g][cw * 4]  = make_float4(sb[0], sb[1], sb[2], sb[3]);
            }
        }
        __syncthreads();   // S3: acc/wv available

        // fused p (h·tape) and ws (wv·tape) partials against buffer k&1
        const int bc2 = k & 1;
#pragma unroll
        for (int g = 0; g < 2; g++) {
            float sp = 0.f, sw = 0.f;
#pragma unroll
            for (int kk = 0; kk < 8; kk++) {
                int dl = q4 * 8 + kk;
                float tp = S.tape[bc2][g][n4 * 33 + dl];
                sp += S.hnew[g][d0 + dl] * tp;
                sw += S.wv[g][dl] * tp;
            }
            sp += __shfl_down_sync(0xffffffffu, sp, 2);
            sp += __shfl_down_sync(0xffffffffu, sp, 1);
            sw += __shfl_down_sync(0xffffffffu, sw, 2);
            sw += __shfl_down_sync(0xffffffffu, sw, 1);
            float sphi = __shfl_down_sync(0xffffffffu, sp, 4);
            float swhi = __shfl_down_sync(0xffffffffu, sw, 4);
            if ((t & 7) == 0) {
                int o  = n4 >> 2;
                int nl = n4 & 3;
                uint32_t dop = off_cin[g] + (uint32_t)(c * 10 + nl) * 4;
                uint32_t dow = off_cin[g] + (uint32_t)(c * 10 + 4 + nl) * 4;
                push_async64(pb[o] + dop, sp, sphi, pb[o] + offm_cin[g]);
                push_async64(pb[o] + dow, sw, swhi, pb[o] + offm_cin[g]);
            }
        }
        // q = h·wv partial (warp0 -> g0, warp5 -> g1), pushed to rank0
        if (isctrl) {
            const int g = gme;
            float qp = warp_sum(S.hnew[g][d0 + lane] * S.wv[g][lane]);
            if (lane == 0) {
                uint32_t doff = off_cin[g] + (uint32_t)(c * 10 + 8) * 4;
                push_async32(pb[0] + doff, qp, pb[0] + offm_cin[g]);
            }
        }
    }

    // ---- post-loop: owners process final inbox (completion TT, parity 0) ----
    if (isowner) {
        const int g = og;
        mbar_wait_cta(mbcin[g], 0u);
        const float* cin = &S.cin[g][0];
        const int ctaL = lane >> 2, nl = lane & 3;
        float w = cin[ctaL * 10 + 4 + nl] + cin[(ctaL + 8) * 10 + 4 + nl];
        w += __shfl_xor_sync(0xffffffffu, w, 4);
        w += __shfl_xor_sync(0xffffffffu, w, 8);
        w += __shfl_xor_sync(0xffffffffu, w, 16);
        float whi = __shfl_down_sync(0xffffffffu, w, 1);
        const int sub = lane & 7, grp = lane >> 3;
        const bool isP = (sub < 4);
        float lo = isP ? 0.f : w;      // P slots are byte filler post-loop
        float hi = isP ? 0.f : whi;
        uint32_t dst = (isP ? off_rsf[g] : off_wsf[g])
                     + (uint32_t)(c * 4 + nl) * 4;
        if ((lane & 1) == 0) {
#pragma unroll
            for (int i = 0; i < 4; i++) {
                int r = grp * 4 + i;
                push_async64(pb[r] + dst, lo, hi, pb[r] + offm_cf[g]);
            }
        }
        if (c == 0 && lane < CPB)
            push_async64(pb[lane] + off_qf[g], 0.f, 0.f, pb[lane] + offm_cf[g]);
    }

    // ---- epilogue: final write-update blended straight to out (parity 0) ----
    {
        mbar_wait_cta(mbcf[g2], 0u);
        float b0 = S.wsf[g2][lane] * scale;
        float b1 = S.wsf[g2][lane + 32] * scale;
        float f0 = __expf(b0), f1 = __expf(b1);
        float fs = warp_sum(f0 + f1);
        float finv = 1.f / fs;
        f0 *= finv; f1 *= finv;
        const float wvl = S.wv[g2][lane];
        const float* tsrc = &S.tape[(TT - 1) & 1][g2][0];
        const int bg2 = 2 * u + g2;
#pragma unroll
        for (int r = 0; r < 16; r++) {
            int n = rbase + r;
            float vsel = (n < 32) ? f0 : f1;
            float a = __shfl_sync(0xffffffffu, vsel, n & 31);
            float told = tsrc[n * 33 + lane];
            out[(size_t)BB * TT * DD + (size_t)(bg2 * NTAPE + n) * DD + d0 + lane] =
                told - told * a + wvl * a;
        }
    }
    CLUSTER_SYNC_();
}

// ---------------- fallback scan kernel (global-memory barriers) -----------
struct ScanSmem {
    float Wh[RPC * 512];
    float Ww[RPC * 512];
    float tape[NTAPE * 33];
    float hwork[512];
    float hnew[512];
    float acc[RPC];
    float wv[RPC];
    float rv[RPC];
    float attn[NTAPE];
    float score[NTAPE];
    float bh[RPC], gz[RPC], gr[RPC], gh[RPC], bg[RPC];
};

__device__ __forceinline__ void softmax64f(const float* __restrict__ score,
                                           float* __restrict__ attn, int t)
{
    if (t < 32) {
        float a = score[t], b = score[t + 32];
        float m = fmaxf(a, b);
#pragma unroll
        for (int off = 16; off >= 1; off >>= 1)
            m = fmaxf(m, __shfl_xor_sync(0xffffffffu, m, off));
        float e0 = __expf(a - m), e1 = __expf(b - m);
        float ss = e0 + e1;
#pragma unroll
        for (int off = 16; off >= 1; off >>= 1)
            ss += __shfl_xor_sync(0xffffffffu, ss, off);
        float inv = 1.f / ss;
        attn[t] = e0 * inv;
        attn[t + 32] = e1 * inv;
    }
}

__global__ __launch_bounds__(NTHREADS, 1) void scan_kernel(
    const float* __restrict__ tape_init,
    const float* __restrict__ hwork_init,
    const float* __restrict__ W_h,
    const float* __restrict__ b_h,
    const float* __restrict__ W_write,
    const float* __restrict__ gzv,
    const float* __restrict__ grv,
    const float* __restrict__ ghv,
    const float* __restrict__ bgv,
    float* __restrict__ out)
{
    extern __shared__ char raw[];
    ScanSmem& S = *(ScanSmem*)raw;

    const int t  = threadIdx.x;
    const int b  = blockIdx.x / CPB;
    const int c  = blockIdx.x % CPB;
    const int d0 = c * RPC;
    const float scale = 0.044194173824159216f;

    for (int i = t; i < RPC * 512; i += NTHREADS) {
        S.Wh[i] = W_h[(size_t)d0 * 512 + i];
        S.Ww[i] = W_write[(size_t)d0 * 512 + i];
    }
    for (int i = t; i < NTAPE * RPC; i += NTHREADS) {
        int n = i >> 5, dl = i & 31;
        S.tape[n * 33 + dl] = tape_init[(size_t)(b * NTAPE + n) * DD + d0 + dl];
    }
    for (int i = t; i < 512; i += NTHREADS)
        S.hwork[i] = hwork_init[b * 512 + i];
    if (t < RPC) {
        S.bh[t] = b_h[d0 + t];  S.gz[t] = gzv[d0 + t];
        S.gr[t] = grv[d0 + t];  S.gh[t] = ghv[d0 + t];
        S.bg[t] = bgv[d0 + t];
    }
    __syncthreads();

    unsigned bc = 0;
    const int n4 = t >> 2, q4 = t & 3;
    const int dl8 = t >> 3, q8 = t & 7;

    for (int step = 0; step < TT; step++) {
        {
            float s = 0.f;
#pragma unroll
            for (int k = 0; k < 8; k++) {
                int dl = q4 * 8 + k;
                s += S.hwork[d0 + dl] * S.tape[n4 * 33 + dl];
            }
            s += __shfl_down_sync(0xffffffffu, s, 2);
            s += __shfl_down_sync(0xffffffffu, s, 1);
            if (q4 == 0) g_rs[(b * CPB + c) * NTAPE + n4] = s;
        }
        matvec32(S.Wh, S.hwork, S.acc);
        batch_barrier(b, (++bc) * CPB);

        if (t < NTAPE) {
            float s = 0.f;
#pragma unroll
            for (int cc = 0; cc < CPB; cc++)
                s += __ldcg(&g_rs[(b * CPB + cc) * NTAPE + t]);
            S.score[t] = s * scale;
        }
        __syncthreads();
        softmax64f(S.score, S.attn, t);
        __syncthreads();
        {
            float s = 0.f;
#pragma unroll
            for (int k = 0; k < 8; k++) {
                int n = q8 * 8 + k;
                s += S.attn[n] * S.tape[n * 33 + dl8];
            }
            s += __shfl_down_sync(0xffffffffu, s, 4);
            s += __shfl_down_sync(0xffffffffu, s, 2);
            s += __shfl_down_sync(0xffffffffu, s, 1);
            if (q8 == 0) S.rv[dl8] = s;
        }
        __syncthreads();
        if (t < RPC) {
            size_t row = (size_t)(b * TT + step) * EE;
            float xp = g_xz[row + d0 + t];
            float zt = g_xz[row + 512 + d0 + t];
            float hn = tanhf(xp + S.acc[t] + S.rv[t] + S.bh[t]);
            g_hnew[b * 512 + d0 + t] = hn;
            float gi = zt * S.gz[t] + S.rv[t] * S.gr[t] + hn * S.gh[t] + S.bg[t];
            gi = fminf(fmaxf(gi, -20.f), 20.f);
            float sig = 1.f / (1.f + __expf(-gi));
            out[(size_t)(b * TT + step) * DD + d0 + t] = hn * gi * sig;
        }
        batch_barrier(b, (++bc) * CPB);

        S.hnew[t]       = __ldcg(&g_hnew[b * 512 + t]);
        S.hnew[t + 256] = __ldcg(&g_hnew[b * 512 + t + 256]);
        __syncthreads();
        matvec32(S.Ww, S.hnew, S.wv);
        __syncthreads();
        {
            float s = 0.f;
#pragma unroll
            for (int k = 0; k < 8; k++) {
                int dl = q4 * 8 + k;
                s += S.wv[dl] * S.tape[n4 * 33 + dl];
            }
            s += __shfl_down_sync(0xffffffffu, s, 2);
            s += __shfl_down_sync(0xffffffffu, s, 1);
            if (q4 == 0) g_ws[(b * CPB + c) * NTAPE + n4] = s;
        }
        batch_barrier(b, (++bc) * CPB);

        if (t < NTAPE) {
            float s = 0.f;
#pragma unroll
            for (int cc = 0; cc < CPB; cc++)
                s += __ldcg(&g_ws[(b * CPB + cc) * NTAPE + t]);
            S.score[t] = s * scale;
        }
        __syncthreads();
        softmax64f(S.score, S.attn, t);
        __syncthreads();
        for (int e = t; e < NTAPE * RPC; e += NTHREADS) {
            int n = e >> 5, dl = e & 31;
            float a  = S.attn[n];
            float tp = S.tape[n * 33 + dl];
            S.tape[n * 33 + dl] = tp - tp * a + S.wv[dl] * a;
        }
        S.hwork[t]       = S.hnew[t];
        S.hwork[t + 256] = S.hnew[t + 256];
        __syncthreads();
    }

    for (int e = t; e < NTAPE * RPC; e += NTHREADS) {
        int n = e >> 5, dl = e & 31;
        out[(size_t)BB * TT * DD + (size_t)(b * NTAPE + n) * DD + d0 + dl] =
            S.tape[n * 33 + dl];
    }
}

// ---------------- launch ---------------------------------------------------
extern "C" void kernel_launch(void* const* d_in, const int* in_sizes, int n_in,
                              void* d_out, int out_size)
{
    const float* x         = (const float*)d_in[0];
    const float* tape_init = (const float*)d_in[1];
    const float* hwork     = (const float*)d_in[2];
    const float* W_h       = (const float*)d_in[3];
    const float* W_xz      = (const float*)d_in[4];
    const float* b_h       = (const float*)d_in[5];
    const float* W_write   = (const float*)d_in[6];
    const float* g_z       = (const float*)d_in[7];
    const float* g_r       = (const float*)d_in[8];
    const float* g_h       = (const float*)d_in[9];
    const float* b_gate    = (const float*)d_in[10];
    float* out = (float*)d_out;

    gemm_xz_kernel<<<dim3(EE / 64, (BB * TT) / 64), 256>>>(x, W_xz);

    // ---- primary: blended owner-reduce dual-batch cluster scan ----
    cudaFuncSetAttribute(scan9_kernel,
                         cudaFuncAttributeMaxDynamicSharedMemorySize,
                         (int)sizeof(CS));
    cudaError_t aerr = cudaFuncSetAttribute(
        scan9_kernel, cudaFuncAttributeNonPortableClusterSizeAllowed, 1);

    cudaLaunchConfig_t cfg = {};
    cfg.gridDim  = dim3(NCLU * CPB, 1, 1);
    cfg.blockDim = dim3(NTHREADS, 1, 1);
    cfg.dynamicSmemBytes = sizeof(CS);
    cfg.stream = 0;

    int maxClu = 0;
    cudaError_t qerr = cudaOccupancyMaxPotentialClusterSize(
        &maxClu, scan9_kernel, &cfg);

    bool launched = false;
    if (aerr == cudaSuccess && qerr == cudaSuccess && maxClu >= CPB) {
        cudaLaunchAttribute attrs[1];
        attrs[0].id = cudaLaunchAttributeClusterDimension;
        attrs[0].val.clusterDim.x = CPB;
        attrs[0].val.clusterDim.y = 1;
        attrs[0].val.clusterDim.z = 1;
        cfg.attrs = attrs;
        cfg.numAttrs = 1;
        cudaError_t lerr = cudaLaunchKernelEx(&cfg, scan9_kernel,
            tape_init, hwork, W_h, b_h, W_write, g_z, g_r, g_h, b_gate, out);
        launched = (lerr == cudaSuccess);
    }

    // ---- fallback ----
    if (!launched) {
        cudaFuncSetAttribute(scan_kernel,
                             cudaFuncAttributeMaxDynamicSharedMemorySize,
                             (int)sizeof(ScanSmem));
        init_bar_kernel<<<1, 32>>>();
        scan_kernel<<<BB * CPB, NTHREADS, sizeof(ScanSmem)>>>(
            tape_init, hwork, W_h, b_h, W_write, g_z, g_r, g_h, b_gate, out);
    }
}